// round 1
// baseline (speedup 1.0000x reference)
#include <cuda_runtime.h>
#include <math.h>

#define HD   768
#define NHD  12
#define DHD  64
#define BB   4
#define SSQ  1024
#define EPSF 1e-6f

// Scratch (allocation-free rule: __device__ globals)
__device__ float g_q [BB*NHD*SSQ*DHD];
__device__ float g_k [BB*NHD*SSQ*DHD];
__device__ float g_v [BB*NHD*SSQ*DHD];
__device__ float g_t [BB*NHD*SSQ*DHD];
__device__ float g_sp[BB*NHD*SSQ*DHD];
__device__ float g_itn[BB*NHD*SSQ];   // 1/(||T_row||+eps)
__device__ float g_isn[BB*NHD*SSQ];   // 1/(||S_row||+eps)

// ---------------------------------------------------------------------------
// Projection GEMM: out[n,o] = sum_i X[n,i]*W[o,i] + b[o]
// Tiles: BM=BN=64, BK=16, 256 threads, 4x4 micro-tile (strided).
// grid = (12 heads, 64 row-tiles, 5 matrices). BlockIdx.x == head (DH==BN==64),
// so T/S row norms are computed in the epilogue via 16-lane shuffle reduce.
// ---------------------------------------------------------------------------
__global__ __launch_bounds__(256) void proj_kernel(
    const float* __restrict__ hs, const float* __restrict__ te, const float* __restrict__ se,
    const float* __restrict__ Wq, const float* __restrict__ bq,
    const float* __restrict__ Wk, const float* __restrict__ bk,
    const float* __restrict__ Wv, const float* __restrict__ bv,
    const float* __restrict__ Wt, const float* __restrict__ bt,
    const float* __restrict__ Ws, const float* __restrict__ bs)
{
    __shared__ float Xs [64][17];
    __shared__ float Wsm[64][17];

    const int z = blockIdx.z;
    const float* X; const float* W; const float* bias; float* out; float* invn;
    if      (z == 0) { X = hs; W = Wq; bias = bq; out = g_q;  invn = 0;     }
    else if (z == 1) { X = hs; W = Wk; bias = bk; out = g_k;  invn = 0;     }
    else if (z == 2) { X = hs; W = Wv; bias = bv; out = g_v;  invn = 0;     }
    else if (z == 3) { X = te; W = Wt; bias = bt; out = g_t;  invn = g_itn; }
    else             { X = se; W = Ws; bias = bs; out = g_sp; invn = g_isn; }

    const int tx = threadIdx.x & 15;
    const int ty = threadIdx.x >> 4;
    const int nb = blockIdx.y * 64;   // row base (token index)
    const int ob = blockIdx.x * 64;   // col base (= head*64)
    const int lr = threadIdx.x >> 2;        // load row 0..63
    const int lc = (threadIdx.x & 3) * 4;   // load col {0,4,8,12}

    float acc[4][4];
#pragma unroll
    for (int i = 0; i < 4; i++)
#pragma unroll
        for (int j = 0; j < 4; j++) acc[i][j] = 0.f;

    for (int kb = 0; kb < HD; kb += 16) {
        float4 xv = *(const float4*)(X + (size_t)(nb + lr) * HD + kb + lc);
        float4 wv = *(const float4*)(W + (size_t)(ob + lr) * HD + kb + lc);
        Xs [lr][lc+0] = xv.x; Xs [lr][lc+1] = xv.y; Xs [lr][lc+2] = xv.z; Xs [lr][lc+3] = xv.w;
        Wsm[lr][lc+0] = wv.x; Wsm[lr][lc+1] = wv.y; Wsm[lr][lc+2] = wv.z; Wsm[lr][lc+3] = wv.w;
        __syncthreads();
#pragma unroll
        for (int kk = 0; kk < 16; kk++) {
            float a[4], bw[4];
#pragma unroll
            for (int i = 0; i < 4; i++) a[i]  = Xs [ty + i*16][kk];
#pragma unroll
            for (int j = 0; j < 4; j++) bw[j] = Wsm[tx + j*16][kk];
#pragma unroll
            for (int i = 0; i < 4; i++)
#pragma unroll
                for (int j = 0; j < 4; j++) acc[i][j] = fmaf(a[i], bw[j], acc[i][j]);
        }
        __syncthreads();
    }

    const int h = blockIdx.x;
#pragma unroll
    for (int i = 0; i < 4; i++) {
        const int n  = nb + ty + i*16;
        const int b_ = n / SSQ;
        const int s_ = n - b_*SSQ;
        const size_t base = (((size_t)b_*NHD + h)*SSQ + s_) * DHD;
        float ss2 = 0.f;
#pragma unroll
        for (int j = 0; j < 4; j++) {
            const int d = tx + j*16;
            const float val = acc[i][j] + bias[ob + d];
            out[base + d] = val;
            ss2 = fmaf(val, val, ss2);
        }
        if (invn) {
#pragma unroll
            for (int o = 1; o < 16; o <<= 1)
                ss2 += __shfl_xor_sync(0xffffffffu, ss2, o);
            if (tx == 0)
                invn[((size_t)b_*NHD + h)*SSQ + s_] = 1.0f / (sqrtf(ss2) + EPSF);
        }
    }
}

// ---------------------------------------------------------------------------
// Flash-style attention. One block = 64 queries of one (b,h). 16 key chunks.
// Scores: (q.k)*(T.T)*(S.S) * invTn_q * invSn_q / 8 + mask[k], online softmax.
// ---------------------------------------------------------------------------
#define ST 65
#define ATTN_SMEM (8 * 64 * ST * 4)

__global__ __launch_bounds__(256) void attn_kernel(const float* __restrict__ mask,
                                                   float* __restrict__ out)
{
    extern __shared__ float sm[];
    float* Qq = sm;
    float* Qt = Qq + 64*ST;
    float* Qs = Qt + 64*ST;
    float* Kb = Qs + 64*ST;
    float* Kt = Kb + 64*ST;
    float* Ks = Kt + 64*ST;
    float* Vv = Ks + 64*ST;
    float* Pp = Vv + 64*ST;

    const int tx = threadIdx.x & 15;
    const int ty = threadIdx.x >> 4;
    const int bh = blockIdx.y;        // b*NH + h
    const int b_ = bh / NHD;
    const int h  = bh - b_*NHD;
    const int qb = blockIdx.x * 64;

    const float* qp = g_q  + (size_t)bh*SSQ*DHD;
    const float* kp = g_k  + (size_t)bh*SSQ*DHD;
    const float* vp = g_v  + (size_t)bh*SSQ*DHD;
    const float* tp = g_t  + (size_t)bh*SSQ*DHD;
    const float* sp = g_sp + (size_t)bh*SSQ*DHD;

    // Load query tiles (q, T, S): 64x64 each
    for (int e = threadIdx.x; e < 64*64; e += 256) {
        const int r = e >> 6, d = e & 63;
        const size_t gi = (size_t)(qb + r)*DHD + d;
        Qq[r*ST + d] = qp[gi];
        Qt[r*ST + d] = tp[gi];
        Qs[r*ST + d] = sp[gi];
    }

    float rowscale[4];
#pragma unroll
    for (int i = 0; i < 4; i++) {
        const int q = qb + ty + i*16;
        rowscale[i] = g_itn[(size_t)bh*SSQ + q] * g_isn[(size_t)bh*SSQ + q] * 0.125f;
    }

    float m_i[4], l_i[4], O[4][4];
#pragma unroll
    for (int i = 0; i < 4; i++) {
        m_i[i] = -1e30f; l_i[i] = 0.f;
#pragma unroll
        for (int j = 0; j < 4; j++) O[i][j] = 0.f;
    }
    __syncthreads();

    for (int kb0 = 0; kb0 < SSQ; kb0 += 64) {
        // Load key-side tiles (k, T, S, V)
        for (int e = threadIdx.x; e < 64*64; e += 256) {
            const int r = e >> 6, d = e & 63;
            const size_t gi = (size_t)(kb0 + r)*DHD + d;
            Kb[r*ST + d] = kp[gi];
            Kt[r*ST + d] = tp[gi];
            Ks[r*ST + d] = sp[gi];
            Vv[r*ST + d] = vp[gi];
        }
        __syncthreads();

        // Three 64x64 score accumulations
        float ab[4][4], at[4][4], as2[4][4];
#pragma unroll
        for (int i = 0; i < 4; i++)
#pragma unroll
            for (int j = 0; j < 4; j++) { ab[i][j] = 0.f; at[i][j] = 0.f; as2[i][j] = 0.f; }

#pragma unroll 8
        for (int kk = 0; kk < 64; kk++) {
            float qa[4], ta[4], sa[4], kbv[4], ktv[4], ksv[4];
#pragma unroll
            for (int i = 0; i < 4; i++) {
                qa[i] = Qq[(ty + i*16)*ST + kk];
                ta[i] = Qt[(ty + i*16)*ST + kk];
                sa[i] = Qs[(ty + i*16)*ST + kk];
            }
#pragma unroll
            for (int j = 0; j < 4; j++) {
                kbv[j] = Kb[(tx + j*16)*ST + kk];
                ktv[j] = Kt[(tx + j*16)*ST + kk];
                ksv[j] = Ks[(tx + j*16)*ST + kk];
            }
#pragma unroll
            for (int i = 0; i < 4; i++)
#pragma unroll
                for (int j = 0; j < 4; j++) {
                    ab [i][j] = fmaf(qa[i], kbv[j], ab [i][j]);
                    at [i][j] = fmaf(ta[i], ktv[j], at [i][j]);
                    as2[i][j] = fmaf(sa[i], ksv[j], as2[i][j]);
                }
        }

        float mk[4];
#pragma unroll
        for (int j = 0; j < 4; j++) mk[j] = mask[(size_t)b_*SSQ + kb0 + tx + j*16];

        // Combine + online softmax (per query row: reduce across 16 tx lanes)
#pragma unroll
        for (int i = 0; i < 4; i++) {
            float c[4];
            float mc = -1e30f;
#pragma unroll
            for (int j = 0; j < 4; j++) {
                c[j] = ab[i][j] * at[i][j] * as2[i][j] * rowscale[i] + mk[j];
                mc = fmaxf(mc, c[j]);
            }
#pragma unroll
            for (int o = 1; o < 16; o <<= 1)
                mc = fmaxf(mc, __shfl_xor_sync(0xffffffffu, mc, o));
            const float mnew = fmaxf(m_i[i], mc);
            const float f = __expf(m_i[i] - mnew);
            m_i[i] = mnew;
            float rs = 0.f;
#pragma unroll
            for (int j = 0; j < 4; j++) {
                const float p = __expf(c[j] - mnew);
                Pp[(ty + i*16)*ST + tx + j*16] = p;
                rs += p;
            }
#pragma unroll
            for (int o = 1; o < 16; o <<= 1)
                rs += __shfl_xor_sync(0xffffffffu, rs, o);
            l_i[i] = l_i[i] * f + rs;
#pragma unroll
            for (int j = 0; j < 4; j++) O[i][j] *= f;
        }
        __syncthreads();

        // O += P @ V
#pragma unroll 8
        for (int kk = 0; kk < 64; kk++) {
            float pv[4], vv[4];
#pragma unroll
            for (int i = 0; i < 4; i++) pv[i] = Pp[(ty + i*16)*ST + kk];
#pragma unroll
            for (int j = 0; j < 4; j++) vv[j] = Vv[kk*ST + tx + j*16];
#pragma unroll
            for (int i = 0; i < 4; i++)
#pragma unroll
                for (int j = 0; j < 4; j++) O[i][j] = fmaf(pv[i], vv[j], O[i][j]);
        }
        __syncthreads();
    }

    // Write out: [B,S,H] with head h at cols h*64..h*64+63
#pragma unroll
    for (int i = 0; i < 4; i++) {
        const int q = qb + ty + i*16;
        const float inv_l = 1.0f / l_i[i];
#pragma unroll
        for (int j = 0; j < 4; j++) {
            const int d = tx + j*16;
            out[((size_t)b_*SSQ + q)*HD + h*DHD + d] = O[i][j] * inv_l;
        }
    }
}

// ---------------------------------------------------------------------------
extern "C" void kernel_launch(void* const* d_in, const int* in_sizes, int n_in,
                              void* d_out, int out_size)
{
    const float* hs   = (const float*)d_in[0];
    const float* te   = (const float*)d_in[1];
    const float* se   = (const float*)d_in[2];
    const float* mask = (const float*)d_in[3];
    const float* Wq = (const float*)d_in[4];  const float* bq = (const float*)d_in[5];
    const float* Wk = (const float*)d_in[6];  const float* bk = (const float*)d_in[7];
    const float* Wv = (const float*)d_in[8];  const float* bv = (const float*)d_in[9];
    const float* Wt = (const float*)d_in[10]; const float* bt = (const float*)d_in[11];
    const float* Ws = (const float*)d_in[12]; const float* bs = (const float*)d_in[13];
    float* out = (float*)d_out;

    dim3 gp(NHD, (BB*SSQ)/64, 5);   // (12, 64, 5)
    proj_kernel<<<gp, 256>>>(hs, te, se, Wq, bq, Wk, bk, Wv, bv, Wt, bt, Ws, bs);

    cudaFuncSetAttribute(attn_kernel, cudaFuncAttributeMaxDynamicSharedMemorySize, ATTN_SMEM);
    dim3 ga(SSQ/64, BB*NHD);        // (16, 48)
    attn_kernel<<<ga, 256, ATTN_SMEM>>>(mask, out);
}

// round 2
// speedup vs baseline: 1.0021x; 1.0021x over previous
#include <cuda_runtime.h>
#include <math.h>

#define HD   768
#define NHD  12
#define DHD  64
#define BB   4
#define SSQ  1024
#define EPSF 1e-6f

// Scratch (allocation-free rule: __device__ globals)
__device__ float g_q [BB*NHD*SSQ*DHD];
__device__ float g_k [BB*NHD*SSQ*DHD];
__device__ float g_v [BB*NHD*SSQ*DHD];
__device__ float g_t [BB*NHD*SSQ*DHD];
__device__ float g_sp[BB*NHD*SSQ*DHD];
__device__ float g_itn[BB*NHD*SSQ];   // 1/(||T_row||+eps)
__device__ float g_isn[BB*NHD*SSQ];   // 1/(||S_row||+eps)

// ---------------------------------------------------------------------------
// Projection GEMM: out[n,o] = sum_i X[n,i]*W[o,i] + b[o]
// Tiles: BM=BN=64, BK=16, 256 threads, 4x4 micro-tile (strided).
// grid = (12 heads, 64 row-tiles, 5 matrices). BlockIdx.x == head (DH==BN==64),
// so T/S row norms are computed in the epilogue via 16-lane shuffle reduce.
// ---------------------------------------------------------------------------
__global__ __launch_bounds__(256) void proj_kernel(
    const float* __restrict__ hs, const float* __restrict__ te, const float* __restrict__ se,
    const float* __restrict__ Wq, const float* __restrict__ bq,
    const float* __restrict__ Wk, const float* __restrict__ bk,
    const float* __restrict__ Wv, const float* __restrict__ bv,
    const float* __restrict__ Wt, const float* __restrict__ bt,
    const float* __restrict__ Ws, const float* __restrict__ bs)
{
    __shared__ float Xs [64][17];
    __shared__ float Wsm[64][17];

    const int z = blockIdx.z;
    const float* X; const float* W; const float* bias; float* out; float* invn;
    if      (z == 0) { X = hs; W = Wq; bias = bq; out = g_q;  invn = 0;     }
    else if (z == 1) { X = hs; W = Wk; bias = bk; out = g_k;  invn = 0;     }
    else if (z == 2) { X = hs; W = Wv; bias = bv; out = g_v;  invn = 0;     }
    else if (z == 3) { X = te; W = Wt; bias = bt; out = g_t;  invn = g_itn; }
    else             { X = se; W = Ws; bias = bs; out = g_sp; invn = g_isn; }

    const int tx = threadIdx.x & 15;
    const int ty = threadIdx.x >> 4;
    const int nb = blockIdx.y * 64;   // row base (token index)
    const int ob = blockIdx.x * 64;   // col base (= head*64)
    const int lr = threadIdx.x >> 2;        // load row 0..63
    const int lc = (threadIdx.x & 3) * 4;   // load col {0,4,8,12}

    float acc[4][4];
#pragma unroll
    for (int i = 0; i < 4; i++)
#pragma unroll
        for (int j = 0; j < 4; j++) acc[i][j] = 0.f;

    for (int kb = 0; kb < HD; kb += 16) {
        float4 xv = *(const float4*)(X + (size_t)(nb + lr) * HD + kb + lc);
        float4 wv = *(const float4*)(W + (size_t)(ob + lr) * HD + kb + lc);
        Xs [lr][lc+0] = xv.x; Xs [lr][lc+1] = xv.y; Xs [lr][lc+2] = xv.z; Xs [lr][lc+3] = xv.w;
        Wsm[lr][lc+0] = wv.x; Wsm[lr][lc+1] = wv.y; Wsm[lr][lc+2] = wv.z; Wsm[lr][lc+3] = wv.w;
        __syncthreads();
#pragma unroll
        for (int kk = 0; kk < 16; kk++) {
            float a[4], bw[4];
#pragma unroll
            for (int i = 0; i < 4; i++) a[i]  = Xs [ty + i*16][kk];
#pragma unroll
            for (int j = 0; j < 4; j++) bw[j] = Wsm[tx + j*16][kk];
#pragma unroll
            for (int i = 0; i < 4; i++)
#pragma unroll
                for (int j = 0; j < 4; j++) acc[i][j] = fmaf(a[i], bw[j], acc[i][j]);
        }
        __syncthreads();
    }

    const int h = blockIdx.x;
#pragma unroll
    for (int i = 0; i < 4; i++) {
        const int n  = nb + ty + i*16;
        const int b_ = n / SSQ;
        const int s_ = n - b_*SSQ;
        const size_t base = (((size_t)b_*NHD + h)*SSQ + s_) * DHD;
        float ss2 = 0.f;
#pragma unroll
        for (int j = 0; j < 4; j++) {
            const int d = tx + j*16;
            const float val = acc[i][j] + bias[ob + d];
            out[base + d] = val;
            ss2 = fmaf(val, val, ss2);
        }
        if (invn) {
#pragma unroll
            for (int o = 1; o < 16; o <<= 1)
                ss2 += __shfl_xor_sync(0xffffffffu, ss2, o);
            if (tx == 0)
                invn[((size_t)b_*NHD + h)*SSQ + s_] = 1.0f / (sqrtf(ss2) + EPSF);
        }
    }
}

// ---------------------------------------------------------------------------
// Flash-style attention. One block = 64 queries of one (b,h). 16 key chunks.
// Scores: (q.k)*(T.T)*(S.S) * invTn_q * invSn_q / 8 + mask[k], online softmax.
// ---------------------------------------------------------------------------
#define ST 65
#define ATTN_SMEM (8 * 64 * ST * 4)

__global__ __launch_bounds__(256) void attn_kernel(const float* __restrict__ mask,
                                                   float* __restrict__ out)
{
    extern __shared__ float sm[];
    float* Qq = sm;
    float* Qt = Qq + 64*ST;
    float* Qs = Qt + 64*ST;
    float* Kb = Qs + 64*ST;
    float* Kt = Kb + 64*ST;
    float* Ks = Kt + 64*ST;
    float* Vv = Ks + 64*ST;
    float* Pp = Vv + 64*ST;

    const int tx = threadIdx.x & 15;
    const int ty = threadIdx.x >> 4;
    const int bh = blockIdx.y;        // b*NH + h
    const int b_ = bh / NHD;
    const int h  = bh - b_*NHD;
    const int qb = blockIdx.x * 64;

    const float* qp = g_q  + (size_t)bh*SSQ*DHD;
    const float* kp = g_k  + (size_t)bh*SSQ*DHD;
    const float* vp = g_v  + (size_t)bh*SSQ*DHD;
    const float* tp = g_t  + (size_t)bh*SSQ*DHD;
    const float* sp = g_sp + (size_t)bh*SSQ*DHD;

    // Load query tiles (q, T, S): 64x64 each
    for (int e = threadIdx.x; e < 64*64; e += 256) {
        const int r = e >> 6, d = e & 63;
        const size_t gi = (size_t)(qb + r)*DHD + d;
        Qq[r*ST + d] = qp[gi];
        Qt[r*ST + d] = tp[gi];
        Qs[r*ST + d] = sp[gi];
    }

    float rowscale[4];
#pragma unroll
    for (int i = 0; i < 4; i++) {
        const int q = qb + ty + i*16;
        rowscale[i] = g_itn[(size_t)bh*SSQ + q] * g_isn[(size_t)bh*SSQ + q] * 0.125f;
    }

    float m_i[4], l_i[4], O[4][4];
#pragma unroll
    for (int i = 0; i < 4; i++) {
        m_i[i] = -1e30f; l_i[i] = 0.f;
#pragma unroll
        for (int j = 0; j < 4; j++) O[i][j] = 0.f;
    }
    __syncthreads();

    for (int kb0 = 0; kb0 < SSQ; kb0 += 64) {
        // Load key-side tiles (k, T, S, V)
        for (int e = threadIdx.x; e < 64*64; e += 256) {
            const int r = e >> 6, d = e & 63;
            const size_t gi = (size_t)(kb0 + r)*DHD + d;
            Kb[r*ST + d] = kp[gi];
            Kt[r*ST + d] = tp[gi];
            Ks[r*ST + d] = sp[gi];
            Vv[r*ST + d] = vp[gi];
        }
        __syncthreads();

        // Three 64x64 score accumulations
        float ab[4][4], at[4][4], as2[4][4];
#pragma unroll
        for (int i = 0; i < 4; i++)
#pragma unroll
            for (int j = 0; j < 4; j++) { ab[i][j] = 0.f; at[i][j] = 0.f; as2[i][j] = 0.f; }

#pragma unroll 8
        for (int kk = 0; kk < 64; kk++) {
            float qa[4], ta[4], sa[4], kbv[4], ktv[4], ksv[4];
#pragma unroll
            for (int i = 0; i < 4; i++) {
                qa[i] = Qq[(ty + i*16)*ST + kk];
                ta[i] = Qt[(ty + i*16)*ST + kk];
                sa[i] = Qs[(ty + i*16)*ST + kk];
            }
#pragma unroll
            for (int j = 0; j < 4; j++) {
                kbv[j] = Kb[(tx + j*16)*ST + kk];
                ktv[j] = Kt[(tx + j*16)*ST + kk];
                ksv[j] = Ks[(tx + j*16)*ST + kk];
            }
#pragma unroll
            for (int i = 0; i < 4; i++)
#pragma unroll
                for (int j = 0; j < 4; j++) {
                    ab [i][j] = fmaf(qa[i], kbv[j], ab [i][j]);
                    at [i][j] = fmaf(ta[i], ktv[j], at [i][j]);
                    as2[i][j] = fmaf(sa[i], ksv[j], as2[i][j]);
                }
        }

        float mk[4];
#pragma unroll
        for (int j = 0; j < 4; j++) mk[j] = mask[(size_t)b_*SSQ + kb0 + tx + j*16];

        // Combine + online softmax (per query row: reduce across 16 tx lanes)
#pragma unroll
        for (int i = 0; i < 4; i++) {
            float c[4];
            float mc = -1e30f;
#pragma unroll
            for (int j = 0; j < 4; j++) {
                c[j] = ab[i][j] * at[i][j] * as2[i][j] * rowscale[i] + mk[j];
                mc = fmaxf(mc, c[j]);
            }
#pragma unroll
            for (int o = 1; o < 16; o <<= 1)
                mc = fmaxf(mc, __shfl_xor_sync(0xffffffffu, mc, o));
            const float mnew = fmaxf(m_i[i], mc);
            const float f = __expf(m_i[i] - mnew);
            m_i[i] = mnew;
            float rs = 0.f;
#pragma unroll
            for (int j = 0; j < 4; j++) {
                const float p = __expf(c[j] - mnew);
                Pp[(ty + i*16)*ST + tx + j*16] = p;
                rs += p;
            }
#pragma unroll
            for (int o = 1; o < 16; o <<= 1)
                rs += __shfl_xor_sync(0xffffffffu, rs, o);
            l_i[i] = l_i[i] * f + rs;
#pragma unroll
            for (int j = 0; j < 4; j++) O[i][j] *= f;
        }
        __syncthreads();

        // O += P @ V
#pragma unroll 8
        for (int kk = 0; kk < 64; kk++) {
            float pv[4], vv[4];
#pragma unroll
            for (int i = 0; i < 4; i++) pv[i] = Pp[(ty + i*16)*ST + kk];
#pragma unroll
            for (int j = 0; j < 4; j++) vv[j] = Vv[kk*ST + tx + j*16];
#pragma unroll
            for (int i = 0; i < 4; i++)
#pragma unroll
                for (int j = 0; j < 4; j++) O[i][j] = fmaf(pv[i], vv[j], O[i][j]);
        }
        __syncthreads();
    }

    // Write out: [B,S,H] with head h at cols h*64..h*64+63
#pragma unroll
    for (int i = 0; i < 4; i++) {
        const int q = qb + ty + i*16;
        const float inv_l = 1.0f / l_i[i];
#pragma unroll
        for (int j = 0; j < 4; j++) {
            const int d = tx + j*16;
            out[((size_t)b_*SSQ + q)*HD + h*DHD + d] = O[i][j] * inv_l;
        }
    }
}

// ---------------------------------------------------------------------------
extern "C" void kernel_launch(void* const* d_in, const int* in_sizes, int n_in,
                              void* d_out, int out_size)
{
    const float* hs   = (const float*)d_in[0];
    const float* te   = (const float*)d_in[1];
    const float* se   = (const float*)d_in[2];
    const float* mask = (const float*)d_in[3];
    const float* Wq = (const float*)d_in[4];  const float* bq = (const float*)d_in[5];
    const float* Wk = (const float*)d_in[6];  const float* bk = (const float*)d_in[7];
    const float* Wv = (const float*)d_in[8];  const float* bv = (const float*)d_in[9];
    const float* Wt = (const float*)d_in[10]; const float* bt = (const float*)d_in[11];
    const float* Ws = (const float*)d_in[12]; const float* bs = (const float*)d_in[13];
    float* out = (float*)d_out;

    dim3 gp(NHD, (BB*SSQ)/64, 5);   // (12, 64, 5)
    proj_kernel<<<gp, 256>>>(hs, te, se, Wq, bq, Wk, bk, Wv, bv, Wt, bt, Ws, bs);

    cudaFuncSetAttribute(attn_kernel, cudaFuncAttributeMaxDynamicSharedMemorySize, ATTN_SMEM);
    dim3 ga(SSQ/64, BB*NHD);        // (16, 48)
    attn_kernel<<<ga, 256, ATTN_SMEM>>>(mask, out);
}

// round 3
// speedup vs baseline: 1.0033x; 1.0012x over previous
#include <cuda_runtime.h>
#include <math.h>

#define HD   768
#define NHD  12
#define DHD  64
#define BB   4
#define SSQ  1024
#define EPSF 1e-6f

// Scratch (allocation-free rule: __device__ globals)
__device__ float g_q [BB*NHD*SSQ*DHD];
__device__ float g_k [BB*NHD*SSQ*DHD];
__device__ float g_v [BB*NHD*SSQ*DHD];
__device__ float g_t [BB*NHD*SSQ*DHD];
__device__ float g_sp[BB*NHD*SSQ*DHD];
__device__ float g_itn[BB*NHD*SSQ];   // 1/(||T_row||+eps)
__device__ float g_isn[BB*NHD*SSQ];   // 1/(||S_row||+eps)

// ---------------------------------------------------------------------------
// Projection GEMM: out[n,o] = sum_i X[n,i]*W[o,i] + b[o]
// Tiles: BM=BN=64, BK=16, 256 threads, 4x4 micro-tile (strided).
// grid = (12 heads, 64 row-tiles, 5 matrices). BlockIdx.x == head (DH==BN==64),
// so T/S row norms are computed in the epilogue via 16-lane shuffle reduce.
// ---------------------------------------------------------------------------
__global__ __launch_bounds__(256) void proj_kernel(
    const float* __restrict__ hs, const float* __restrict__ te, const float* __restrict__ se,
    const float* __restrict__ Wq, const float* __restrict__ bq,
    const float* __restrict__ Wk, const float* __restrict__ bk,
    const float* __restrict__ Wv, const float* __restrict__ bv,
    const float* __restrict__ Wt, const float* __restrict__ bt,
    const float* __restrict__ Ws, const float* __restrict__ bs)
{
    __shared__ float Xs [64][17];
    __shared__ float Wsm[64][17];

    const int z = blockIdx.z;
    const float* X; const float* W; const float* bias; float* out; float* invn;
    if      (z == 0) { X = hs; W = Wq; bias = bq; out = g_q;  invn = 0;     }
    else if (z == 1) { X = hs; W = Wk; bias = bk; out = g_k;  invn = 0;     }
    else if (z == 2) { X = hs; W = Wv; bias = bv; out = g_v;  invn = 0;     }
    else if (z == 3) { X = te; W = Wt; bias = bt; out = g_t;  invn = g_itn; }
    else             { X = se; W = Ws; bias = bs; out = g_sp; invn = g_isn; }

    const int tx = threadIdx.x & 15;
    const int ty = threadIdx.x >> 4;
    const int nb = blockIdx.y * 64;   // row base (token index)
    const int ob = blockIdx.x * 64;   // col base (= head*64)
    const int lr = threadIdx.x >> 2;        // load row 0..63
    const int lc = (threadIdx.x & 3) * 4;   // load col {0,4,8,12}

    float acc[4][4];
#pragma unroll
    for (int i = 0; i < 4; i++)
#pragma unroll
        for (int j = 0; j < 4; j++) acc[i][j] = 0.f;

    for (int kb = 0; kb < HD; kb += 16) {
        float4 xv = *(const float4*)(X + (size_t)(nb + lr) * HD + kb + lc);
        float4 wv = *(const float4*)(W + (size_t)(ob + lr) * HD + kb + lc);
        Xs [lr][lc+0] = xv.x; Xs [lr][lc+1] = xv.y; Xs [lr][lc+2] = xv.z; Xs [lr][lc+3] = xv.w;
        Wsm[lr][lc+0] = wv.x; Wsm[lr][lc+1] = wv.y; Wsm[lr][lc+2] = wv.z; Wsm[lr][lc+3] = wv.w;
        __syncthreads();
#pragma unroll
        for (int kk = 0; kk < 16; kk++) {
            float a[4], bw[4];
#pragma unroll
            for (int i = 0; i < 4; i++) a[i]  = Xs [ty + i*16][kk];
#pragma unroll
            for (int j = 0; j < 4; j++) bw[j] = Wsm[tx + j*16][kk];
#pragma unroll
            for (int i = 0; i < 4; i++)
#pragma unroll
                for (int j = 0; j < 4; j++) acc[i][j] = fmaf(a[i], bw[j], acc[i][j]);
        }
        __syncthreads();
    }

    const int h = blockIdx.x;
#pragma unroll
    for (int i = 0; i < 4; i++) {
        const int n  = nb + ty + i*16;
        const int b_ = n / SSQ;
        const int s_ = n - b_*SSQ;
        const size_t base = (((size_t)b_*NHD + h)*SSQ + s_) * DHD;
        float ss2 = 0.f;
#pragma unroll
        for (int j = 0; j < 4; j++) {
            const int d = tx + j*16;
            const float val = acc[i][j] + bias[ob + d];
            out[base + d] = val;
            ss2 = fmaf(val, val, ss2);
        }
        if (invn) {
#pragma unroll
            for (int o = 1; o < 16; o <<= 1)
                ss2 += __shfl_xor_sync(0xffffffffu, ss2, o);
            if (tx == 0)
                invn[((size_t)b_*NHD + h)*SSQ + s_] = 1.0f / (sqrtf(ss2) + EPSF);
        }
    }
}

// ---------------------------------------------------------------------------
// Flash-style attention. One block = 64 queries of one (b,h). 16 key chunks.
// Scores: (q.k)*(T.T)*(S.S) * invTn_q * invSn_q / 8 + mask[k], online softmax.
// ---------------------------------------------------------------------------
#define ST 65
#define ATTN_SMEM (8 * 64 * ST * 4)

__global__ __launch_bounds__(256) void attn_kernel(const float* __restrict__ mask,
                                                   float* __restrict__ out)
{
    extern __shared__ float sm[];
    float* Qq = sm;
    float* Qt = Qq + 64*ST;
    float* Qs = Qt + 64*ST;
    float* Kb = Qs + 64*ST;
    float* Kt = Kb + 64*ST;
    float* Ks = Kt + 64*ST;
    float* Vv = Ks + 64*ST;
    float* Pp = Vv + 64*ST;

    const int tx = threadIdx.x & 15;
    const int ty = threadIdx.x >> 4;
    const int bh = blockIdx.y;        // b*NH + h
    const int b_ = bh / NHD;
    const int h  = bh - b_*NHD;
    const int qb = blockIdx.x * 64;

    const float* qp = g_q  + (size_t)bh*SSQ*DHD;
    const float* kp = g_k  + (size_t)bh*SSQ*DHD;
    const float* vp = g_v  + (size_t)bh*SSQ*DHD;
    const float* tp = g_t  + (size_t)bh*SSQ*DHD;
    const float* sp = g_sp + (size_t)bh*SSQ*DHD;

    // Load query tiles (q, T, S): 64x64 each
    for (int e = threadIdx.x; e < 64*64; e += 256) {
        const int r = e >> 6, d = e & 63;
        const size_t gi = (size_t)(qb + r)*DHD + d;
        Qq[r*ST + d] = qp[gi];
        Qt[r*ST + d] = tp[gi];
        Qs[r*ST + d] = sp[gi];
    }

    float rowscale[4];
#pragma unroll
    for (int i = 0; i < 4; i++) {
        const int q = qb + ty + i*16;
        rowscale[i] = g_itn[(size_t)bh*SSQ + q] * g_isn[(size_t)bh*SSQ + q] * 0.125f;
    }

    float m_i[4], l_i[4], O[4][4];
#pragma unroll
    for (int i = 0; i < 4; i++) {
        m_i[i] = -1e30f; l_i[i] = 0.f;
#pragma unroll
        for (int j = 0; j < 4; j++) O[i][j] = 0.f;
    }
    __syncthreads();

    for (int kb0 = 0; kb0 < SSQ; kb0 += 64) {
        // Load key-side tiles (k, T, S, V)
        for (int e = threadIdx.x; e < 64*64; e += 256) {
            const int r = e >> 6, d = e & 63;
            const size_t gi = (size_t)(kb0 + r)*DHD + d;
            Kb[r*ST + d] = kp[gi];
            Kt[r*ST + d] = tp[gi];
            Ks[r*ST + d] = sp[gi];
            Vv[r*ST + d] = vp[gi];
        }
        __syncthreads();

        // Three 64x64 score accumulations
        float ab[4][4], at[4][4], as2[4][4];
#pragma unroll
        for (int i = 0; i < 4; i++)
#pragma unroll
            for (int j = 0; j < 4; j++) { ab[i][j] = 0.f; at[i][j] = 0.f; as2[i][j] = 0.f; }

#pragma unroll 8
        for (int kk = 0; kk < 64; kk++) {
            float qa[4], ta[4], sa[4], kbv[4], ktv[4], ksv[4];
#pragma unroll
            for (int i = 0; i < 4; i++) {
                qa[i] = Qq[(ty + i*16)*ST + kk];
                ta[i] = Qt[(ty + i*16)*ST + kk];
                sa[i] = Qs[(ty + i*16)*ST + kk];
            }
#pragma unroll
            for (int j = 0; j < 4; j++) {
                kbv[j] = Kb[(tx + j*16)*ST + kk];
                ktv[j] = Kt[(tx + j*16)*ST + kk];
                ksv[j] = Ks[(tx + j*16)*ST + kk];
            }
#pragma unroll
            for (int i = 0; i < 4; i++)
#pragma unroll
                for (int j = 0; j < 4; j++) {
                    ab [i][j] = fmaf(qa[i], kbv[j], ab [i][j]);
                    at [i][j] = fmaf(ta[i], ktv[j], at [i][j]);
                    as2[i][j] = fmaf(sa[i], ksv[j], as2[i][j]);
                }
        }

        float mk[4];
#pragma unroll
        for (int j = 0; j < 4; j++) mk[j] = mask[(size_t)b_*SSQ + kb0 + tx + j*16];

        // Combine + online softmax (per query row: reduce across 16 tx lanes)
#pragma unroll
        for (int i = 0; i < 4; i++) {
            float c[4];
            float mc = -1e30f;
#pragma unroll
            for (int j = 0; j < 4; j++) {
                c[j] = ab[i][j] * at[i][j] * as2[i][j] * rowscale[i] + mk[j];
                mc = fmaxf(mc, c[j]);
            }
#pragma unroll
            for (int o = 1; o < 16; o <<= 1)
                mc = fmaxf(mc, __shfl_xor_sync(0xffffffffu, mc, o));
            const float mnew = fmaxf(m_i[i], mc);
            const float f = __expf(m_i[i] - mnew);
            m_i[i] = mnew;
            float rs = 0.f;
#pragma unroll
            for (int j = 0; j < 4; j++) {
                const float p = __expf(c[j] - mnew);
                Pp[(ty + i*16)*ST + tx + j*16] = p;
                rs += p;
            }
#pragma unroll
            for (int o = 1; o < 16; o <<= 1)
                rs += __shfl_xor_sync(0xffffffffu, rs, o);
            l_i[i] = l_i[i] * f + rs;
#pragma unroll
            for (int j = 0; j < 4; j++) O[i][j] *= f;
        }
        __syncthreads();

        // O += P @ V
#pragma unroll 8
        for (int kk = 0; kk < 64; kk++) {
            float pv[4], vv[4];
#pragma unroll
            for (int i = 0; i < 4; i++) pv[i] = Pp[(ty + i*16)*ST + kk];
#pragma unroll
            for (int j = 0; j < 4; j++) vv[j] = Vv[kk*ST + tx + j*16];
#pragma unroll
            for (int i = 0; i < 4; i++)
#pragma unroll
                for (int j = 0; j < 4; j++) O[i][j] = fmaf(pv[i], vv[j], O[i][j]);
        }
        __syncthreads();
    }

    // Write out: [B,S,H] with head h at cols h*64..h*64+63
#pragma unroll
    for (int i = 0; i < 4; i++) {
        const int q = qb + ty + i*16;
        const float inv_l = 1.0f / l_i[i];
#pragma unroll
        for (int j = 0; j < 4; j++) {
            const int d = tx + j*16;
            out[((size_t)b_*SSQ + q)*HD + h*DHD + d] = O[i][j] * inv_l;
        }
    }
}

// ---------------------------------------------------------------------------
extern "C" void kernel_launch(void* const* d_in, const int* in_sizes, int n_in,
                              void* d_out, int out_size)
{
    const float* hs   = (const float*)d_in[0];
    const float* te   = (const float*)d_in[1];
    const float* se   = (const float*)d_in[2];
    const float* mask = (const float*)d_in[3];
    const float* Wq = (const float*)d_in[4];  const float* bq = (const float*)d_in[5];
    const float* Wk = (const float*)d_in[6];  const float* bk = (const float*)d_in[7];
    const float* Wv = (const float*)d_in[8];  const float* bv = (const float*)d_in[9];
    const float* Wt = (const float*)d_in[10]; const float* bt = (const float*)d_in[11];
    const float* Ws = (const float*)d_in[12]; const float* bs = (const float*)d_in[13];
    float* out = (float*)d_out;

    dim3 gp(NHD, (BB*SSQ)/64, 5);   // (12, 64, 5)
    proj_kernel<<<gp, 256>>>(hs, te, se, Wq, bq, Wk, bk, Wv, bv, Wt, bt, Ws, bs);

    cudaFuncSetAttribute(attn_kernel, cudaFuncAttributeMaxDynamicSharedMemorySize, ATTN_SMEM);
    dim3 ga(SSQ/64, BB*NHD);        // (16, 48)
    attn_kernel<<<ga, 256, ATTN_SMEM>>>(mask, out);
}

// round 4
// speedup vs baseline: 1.0042x; 1.0009x over previous
#include <cuda_runtime.h>
#include <math.h>

#define HD   768
#define NHD  12
#define DHD  64
#define BB   4
#define SSQ  1024
#define EPSF 1e-6f

// Scratch (allocation-free rule: __device__ globals)
__device__ float g_q [BB*NHD*SSQ*DHD];
__device__ float g_k [BB*NHD*SSQ*DHD];
__device__ float g_v [BB*NHD*SSQ*DHD];
__device__ float g_t [BB*NHD*SSQ*DHD];
__device__ float g_sp[BB*NHD*SSQ*DHD];
__device__ float g_itn[BB*NHD*SSQ];   // 1/(||T_row||+eps)
__device__ float g_isn[BB*NHD*SSQ];   // 1/(||S_row||+eps)

// ---------------------------------------------------------------------------
// Projection GEMM: out[n,o] = sum_i X[n,i]*W[o,i] + b[o]
// Tiles: BM=BN=64, BK=16, 256 threads, 4x4 micro-tile (strided).
// grid = (12 heads, 64 row-tiles, 5 matrices). BlockIdx.x == head (DH==BN==64),
// so T/S row norms are computed in the epilogue via 16-lane shuffle reduce.
// ---------------------------------------------------------------------------
__global__ __launch_bounds__(256) void proj_kernel(
    const float* __restrict__ hs, const float* __restrict__ te, const float* __restrict__ se,
    const float* __restrict__ Wq, const float* __restrict__ bq,
    const float* __restrict__ Wk, const float* __restrict__ bk,
    const float* __restrict__ Wv, const float* __restrict__ bv,
    const float* __restrict__ Wt, const float* __restrict__ bt,
    const float* __restrict__ Ws, const float* __restrict__ bs)
{
    __shared__ float Xs [64][17];
    __shared__ float Wsm[64][17];

    const int z = blockIdx.z;
    const float* X; const float* W; const float* bias; float* out; float* invn;
    if      (z == 0) { X = hs; W = Wq; bias = bq; out = g_q;  invn = 0;     }
    else if (z == 1) { X = hs; W = Wk; bias = bk; out = g_k;  invn = 0;     }
    else if (z == 2) { X = hs; W = Wv; bias = bv; out = g_v;  invn = 0;     }
    else if (z == 3) { X = te; W = Wt; bias = bt; out = g_t;  invn = g_itn; }
    else             { X = se; W = Ws; bias = bs; out = g_sp; invn = g_isn; }

    const int tx = threadIdx.x & 15;
    const int ty = threadIdx.x >> 4;
    const int nb = blockIdx.y * 64;   // row base (token index)
    const int ob = blockIdx.x * 64;   // col base (= head*64)
    const int lr = threadIdx.x >> 2;        // load row 0..63
    const int lc = (threadIdx.x & 3) * 4;   // load col {0,4,8,12}

    float acc[4][4];
#pragma unroll
    for (int i = 0; i < 4; i++)
#pragma unroll
        for (int j = 0; j < 4; j++) acc[i][j] = 0.f;

    for (int kb = 0; kb < HD; kb += 16) {
        float4 xv = *(const float4*)(X + (size_t)(nb + lr) * HD + kb + lc);
        float4 wv = *(const float4*)(W + (size_t)(ob + lr) * HD + kb + lc);
        Xs [lr][lc+0] = xv.x; Xs [lr][lc+1] = xv.y; Xs [lr][lc+2] = xv.z; Xs [lr][lc+3] = xv.w;
        Wsm[lr][lc+0] = wv.x; Wsm[lr][lc+1] = wv.y; Wsm[lr][lc+2] = wv.z; Wsm[lr][lc+3] = wv.w;
        __syncthreads();
#pragma unroll
        for (int kk = 0; kk < 16; kk++) {
            float a[4], bw[4];
#pragma unroll
            for (int i = 0; i < 4; i++) a[i]  = Xs [ty + i*16][kk];
#pragma unroll
            for (int j = 0; j < 4; j++) bw[j] = Wsm[tx + j*16][kk];
#pragma unroll
            for (int i = 0; i < 4; i++)
#pragma unroll
                for (int j = 0; j < 4; j++) acc[i][j] = fmaf(a[i], bw[j], acc[i][j]);
        }
        __syncthreads();
    }

    const int h = blockIdx.x;
#pragma unroll
    for (int i = 0; i < 4; i++) {
        const int n  = nb + ty + i*16;
        const int b_ = n / SSQ;
        const int s_ = n - b_*SSQ;
        const size_t base = (((size_t)b_*NHD + h)*SSQ + s_) * DHD;
        float ss2 = 0.f;
#pragma unroll
        for (int j = 0; j < 4; j++) {
            const int d = tx + j*16;
            const float val = acc[i][j] + bias[ob + d];
            out[base + d] = val;
            ss2 = fmaf(val, val, ss2);
        }
        if (invn) {
#pragma unroll
            for (int o = 1; o < 16; o <<= 1)
                ss2 += __shfl_xor_sync(0xffffffffu, ss2, o);
            if (tx == 0)
                invn[((size_t)b_*NHD + h)*SSQ + s_] = 1.0f / (sqrtf(ss2) + EPSF);
        }
    }
}

// ---------------------------------------------------------------------------
// Flash-style attention. One block = 64 queries of one (b,h). 16 key chunks.
// Scores: (q.k)*(T.T)*(S.S) * invTn_q * invSn_q / 8 + mask[k], online softmax.
// ---------------------------------------------------------------------------
#define ST 65
#define ATTN_SMEM (8 * 64 * ST * 4)

__global__ __launch_bounds__(256) void attn_kernel(const float* __restrict__ mask,
                                                   float* __restrict__ out)
{
    extern __shared__ float sm[];
    float* Qq = sm;
    float* Qt = Qq + 64*ST;
    float* Qs = Qt + 64*ST;
    float* Kb = Qs + 64*ST;
    float* Kt = Kb + 64*ST;
    float* Ks = Kt + 64*ST;
    float* Vv = Ks + 64*ST;
    float* Pp = Vv + 64*ST;

    const int tx = threadIdx.x & 15;
    const int ty = threadIdx.x >> 4;
    const int bh = blockIdx.y;        // b*NH + h
    const int b_ = bh / NHD;
    const int h  = bh - b_*NHD;
    const int qb = blockIdx.x * 64;

    const float* qp = g_q  + (size_t)bh*SSQ*DHD;
    const float* kp = g_k  + (size_t)bh*SSQ*DHD;
    const float* vp = g_v  + (size_t)bh*SSQ*DHD;
    const float* tp = g_t  + (size_t)bh*SSQ*DHD;
    const float* sp = g_sp + (size_t)bh*SSQ*DHD;

    // Load query tiles (q, T, S): 64x64 each
    for (int e = threadIdx.x; e < 64*64; e += 256) {
        const int r = e >> 6, d = e & 63;
        const size_t gi = (size_t)(qb + r)*DHD + d;
        Qq[r*ST + d] = qp[gi];
        Qt[r*ST + d] = tp[gi];
        Qs[r*ST + d] = sp[gi];
    }

    float rowscale[4];
#pragma unroll
    for (int i = 0; i < 4; i++) {
        const int q = qb + ty + i*16;
        rowscale[i] = g_itn[(size_t)bh*SSQ + q] * g_isn[(size_t)bh*SSQ + q] * 0.125f;
    }

    float m_i[4], l_i[4], O[4][4];
#pragma unroll
    for (int i = 0; i < 4; i++) {
        m_i[i] = -1e30f; l_i[i] = 0.f;
#pragma unroll
        for (int j = 0; j < 4; j++) O[i][j] = 0.f;
    }
    __syncthreads();

    for (int kb0 = 0; kb0 < SSQ; kb0 += 64) {
        // Load key-side tiles (k, T, S, V)
        for (int e = threadIdx.x; e < 64*64; e += 256) {
            const int r = e >> 6, d = e & 63;
            const size_t gi = (size_t)(kb0 + r)*DHD + d;
            Kb[r*ST + d] = kp[gi];
            Kt[r*ST + d] = tp[gi];
            Ks[r*ST + d] = sp[gi];
            Vv[r*ST + d] = vp[gi];
        }
        __syncthreads();

        // Three 64x64 score accumulations
        float ab[4][4], at[4][4], as2[4][4];
#pragma unroll
        for (int i = 0; i < 4; i++)
#pragma unroll
            for (int j = 0; j < 4; j++) { ab[i][j] = 0.f; at[i][j] = 0.f; as2[i][j] = 0.f; }

#pragma unroll 8
        for (int kk = 0; kk < 64; kk++) {
            float qa[4], ta[4], sa[4], kbv[4], ktv[4], ksv[4];
#pragma unroll
            for (int i = 0; i < 4; i++) {
                qa[i] = Qq[(ty + i*16)*ST + kk];
                ta[i] = Qt[(ty + i*16)*ST + kk];
                sa[i] = Qs[(ty + i*16)*ST + kk];
            }
#pragma unroll
            for (int j = 0; j < 4; j++) {
                kbv[j] = Kb[(tx + j*16)*ST + kk];
                ktv[j] = Kt[(tx + j*16)*ST + kk];
                ksv[j] = Ks[(tx + j*16)*ST + kk];
            }
#pragma unroll
            for (int i = 0; i < 4; i++)
#pragma unroll
                for (int j = 0; j < 4; j++) {
                    ab [i][j] = fmaf(qa[i], kbv[j], ab [i][j]);
                    at [i][j] = fmaf(ta[i], ktv[j], at [i][j]);
                    as2[i][j] = fmaf(sa[i], ksv[j], as2[i][j]);
                }
        }

        float mk[4];
#pragma unroll
        for (int j = 0; j < 4; j++) mk[j] = mask[(size_t)b_*SSQ + kb0 + tx + j*16];

        // Combine + online softmax (per query row: reduce across 16 tx lanes)
#pragma unroll
        for (int i = 0; i < 4; i++) {
            float c[4];
            float mc = -1e30f;
#pragma unroll
            for (int j = 0; j < 4; j++) {
                c[j] = ab[i][j] * at[i][j] * as2[i][j] * rowscale[i] + mk[j];
                mc = fmaxf(mc, c[j]);
            }
#pragma unroll
            for (int o = 1; o < 16; o <<= 1)
                mc = fmaxf(mc, __shfl_xor_sync(0xffffffffu, mc, o));
            const float mnew = fmaxf(m_i[i], mc);
            const float f = __expf(m_i[i] - mnew);
            m_i[i] = mnew;
            float rs = 0.f;
#pragma unroll
            for (int j = 0; j < 4; j++) {
                const float p = __expf(c[j] - mnew);
                Pp[(ty + i*16)*ST + tx + j*16] = p;
                rs += p;
            }
#pragma unroll
            for (int o = 1; o < 16; o <<= 1)
                rs += __shfl_xor_sync(0xffffffffu, rs, o);
            l_i[i] = l_i[i] * f + rs;
#pragma unroll
            for (int j = 0; j < 4; j++) O[i][j] *= f;
        }
        __syncthreads();

        // O += P @ V
#pragma unroll 8
        for (int kk = 0; kk < 64; kk++) {
            float pv[4], vv[4];
#pragma unroll
            for (int i = 0; i < 4; i++) pv[i] = Pp[(ty + i*16)*ST + kk];
#pragma unroll
            for (int j = 0; j < 4; j++) vv[j] = Vv[kk*ST + tx + j*16];
#pragma unroll
            for (int i = 0; i < 4; i++)
#pragma unroll
                for (int j = 0; j < 4; j++) O[i][j] = fmaf(pv[i], vv[j], O[i][j]);
        }
        __syncthreads();
    }

    // Write out: [B,S,H] with head h at cols h*64..h*64+63
#pragma unroll
    for (int i = 0; i < 4; i++) {
        const int q = qb + ty + i*16;
        const float inv_l = 1.0f / l_i[i];
#pragma unroll
        for (int j = 0; j < 4; j++) {
            const int d = tx + j*16;
            out[((size_t)b_*SSQ + q)*HD + h*DHD + d] = O[i][j] * inv_l;
        }
    }
}

// ---------------------------------------------------------------------------
extern "C" void kernel_launch(void* const* d_in, const int* in_sizes, int n_in,
                              void* d_out, int out_size)
{
    const float* hs   = (const float*)d_in[0];
    const float* te   = (const float*)d_in[1];
    const float* se   = (const float*)d_in[2];
    const float* mask = (const float*)d_in[3];
    const float* Wq = (const float*)d_in[4];  const float* bq = (const float*)d_in[5];
    const float* Wk = (const float*)d_in[6];  const float* bk = (const float*)d_in[7];
    const float* Wv = (const float*)d_in[8];  const float* bv = (const float*)d_in[9];
    const float* Wt = (const float*)d_in[10]; const float* bt = (const float*)d_in[11];
    const float* Ws = (const float*)d_in[12]; const float* bs = (const float*)d_in[13];
    float* out = (float*)d_out;

    dim3 gp(NHD, (BB*SSQ)/64, 5);   // (12, 64, 5)
    proj_kernel<<<gp, 256>>>(hs, te, se, Wq, bq, Wk, bk, Wv, bv, Wt, bt, Ws, bs);

    cudaFuncSetAttribute(attn_kernel, cudaFuncAttributeMaxDynamicSharedMemorySize, ATTN_SMEM);
    dim3 ga(SSQ/64, BB*NHD);        // (16, 48)
    attn_kernel<<<ga, 256, ATTN_SMEM>>>(mask, out);
}

// round 5
// speedup vs baseline: 1.2469x; 1.2416x over previous
#include <cuda_runtime.h>
#include <math.h>

#define HD   768
#define NHD  12
#define DHD  64
#define BB   4
#define SSQ  1024
#define EPSF 1e-6f

// Scratch (allocation-free rule: __device__ globals)
__device__ float g_q [BB*NHD*SSQ*DHD];
__device__ float g_k [BB*NHD*SSQ*DHD];
__device__ float g_v [BB*NHD*SSQ*DHD];
__device__ float g_t [BB*NHD*SSQ*DHD];
__device__ float g_sp[BB*NHD*SSQ*DHD];
__device__ float g_itn[BB*NHD*SSQ];   // 1/(||T_row||+eps)
__device__ float g_isn[BB*NHD*SSQ];   // 1/(||S_row||+eps)

// ---------------------------------------------------------------------------
// Projection GEMM: out[n,o] = sum_i X[n,i]*W[o,i] + b[o]
// Tiles: BM=128, BN=64, BK=32, 256 threads, 8x4 micro-tile (strided).
// grid = (12 heads, 32 row-tiles, 5 matrices). BlockIdx.x == head (DH==BN==64),
// so T/S row norms are computed in the epilogue via 16-lane shuffle reduce.
// ---------------------------------------------------------------------------
__global__ __launch_bounds__(256) void proj_kernel(
    const float* __restrict__ hs, const float* __restrict__ te, const float* __restrict__ se,
    const float* __restrict__ Wq, const float* __restrict__ bq,
    const float* __restrict__ Wk, const float* __restrict__ bk,
    const float* __restrict__ Wv, const float* __restrict__ bv,
    const float* __restrict__ Wt, const float* __restrict__ bt,
    const float* __restrict__ Ws, const float* __restrict__ bs)
{
    __shared__ float Xs [128][33];
    __shared__ float Wsm[ 64][33];

    const int z = blockIdx.z;
    const float* X; const float* W; const float* bias; float* out; float* invn;
    if      (z == 0) { X = hs; W = Wq; bias = bq; out = g_q;  invn = 0;     }
    else if (z == 1) { X = hs; W = Wk; bias = bk; out = g_k;  invn = 0;     }
    else if (z == 2) { X = hs; W = Wv; bias = bv; out = g_v;  invn = 0;     }
    else if (z == 3) { X = te; W = Wt; bias = bt; out = g_t;  invn = g_itn; }
    else             { X = se; W = Ws; bias = bs; out = g_sp; invn = g_isn; }

    const int tid = threadIdx.x;
    const int tx = tid & 15;          // 0..15 -> output cols d = tx + j*16
    const int ty = tid >> 4;          // 0..15 -> output rows n = ty + i*16
    const int nb = blockIdx.y * 128;  // row base (token index)
    const int ob = blockIdx.x * 64;   // col base (= head*64)

    float acc[8][4];
#pragma unroll
    for (int i = 0; i < 8; i++)
#pragma unroll
        for (int j = 0; j < 4; j++) acc[i][j] = 0.f;

    for (int kb = 0; kb < HD; kb += 32) {
        // Load X tile: 128x32 floats = 1024 float4, 4 per thread
#pragma unroll
        for (int l = 0; l < 4; l++) {
            const int flat = tid + l*256;
            const int r  = flat >> 3;          // 0..127
            const int c4 = (flat & 7) * 4;     // 0,4,...,28
            float4 v = *(const float4*)(X + (size_t)(nb + r)*HD + kb + c4);
            Xs[r][c4+0] = v.x; Xs[r][c4+1] = v.y; Xs[r][c4+2] = v.z; Xs[r][c4+3] = v.w;
        }
        // Load W tile: 64x32 floats = 512 float4, 2 per thread
#pragma unroll
        for (int l = 0; l < 2; l++) {
            const int flat = tid + l*256;
            const int r  = flat >> 3;          // 0..63
            const int c4 = (flat & 7) * 4;
            float4 v = *(const float4*)(W + (size_t)(ob + r)*HD + kb + c4);
            Wsm[r][c4+0] = v.x; Wsm[r][c4+1] = v.y; Wsm[r][c4+2] = v.z; Wsm[r][c4+3] = v.w;
        }
        __syncthreads();
#pragma unroll 8
        for (int kk = 0; kk < 32; kk++) {
            float a[8], bw[4];
#pragma unroll
            for (int i = 0; i < 8; i++) a[i]  = Xs [ty + i*16][kk];
#pragma unroll
            for (int j = 0; j < 4; j++) bw[j] = Wsm[tx + j*16][kk];
#pragma unroll
            for (int i = 0; i < 8; i++)
#pragma unroll
                for (int j = 0; j < 4; j++) acc[i][j] = fmaf(a[i], bw[j], acc[i][j]);
        }
        __syncthreads();
    }

    const int h = blockIdx.x;
#pragma unroll
    for (int i = 0; i < 8; i++) {
        const int n  = nb + ty + i*16;
        const int b_ = n / SSQ;
        const int s_ = n - b_*SSQ;
        const size_t base = (((size_t)b_*NHD + h)*SSQ + s_) * DHD;
        float ss2 = 0.f;
#pragma unroll
        for (int j = 0; j < 4; j++) {
            const int d = tx + j*16;
            const float val = acc[i][j] + bias[ob + d];
            out[base + d] = val;
            ss2 = fmaf(val, val, ss2);
        }
        if (invn) {
#pragma unroll
            for (int o = 1; o < 16; o <<= 1)
                ss2 += __shfl_xor_sync(0xffffffffu, ss2, o);
            if (tx == 0)
                invn[((size_t)b_*NHD + h)*SSQ + s_] = 1.0f / (sqrtf(ss2) + EPSF);
        }
    }
}

// ---------------------------------------------------------------------------
// Flash-style attention. One block = 64 queries of one (b,h). 16 key chunks.
// Scores: (q.k)*(T.T)*(S.S) * invTn_q * invSn_q / 8 + mask[k], online softmax.
// Smem reduced to 6 buffers (99.8 KB): P overlays Kb, V overlays Kt, both dead
// after the score pass. -> 2 blocks/SM (occ 25%).
// ---------------------------------------------------------------------------
#define ST 65
#define ATTN_SMEM (6 * 64 * ST * 4)

__global__ __launch_bounds__(256, 2) void attn_kernel(const float* __restrict__ mask,
                                                      float* __restrict__ out)
{
    extern __shared__ float sm[];
    float* Qq = sm;
    float* Qt = Qq + 64*ST;
    float* Qs = Qt + 64*ST;
    float* Kb = Qs + 64*ST;
    float* Kt = Kb + 64*ST;
    float* Ks = Kt + 64*ST;
    float* Pp = Kb;   // overlay: P written after score pass (Kb dead)
    float* Vv = Kt;   // overlay: V loaded after score pass (Kt dead)

    const int tx = threadIdx.x & 15;
    const int ty = threadIdx.x >> 4;
    const int bh = blockIdx.y;        // b*NH + h
    const int b_ = bh / NHD;
    const int h  = bh - b_*NHD;
    const int qb = blockIdx.x * 64;

    const float* qp = g_q  + (size_t)bh*SSQ*DHD;
    const float* kp = g_k  + (size_t)bh*SSQ*DHD;
    const float* vp = g_v  + (size_t)bh*SSQ*DHD;
    const float* tp = g_t  + (size_t)bh*SSQ*DHD;
    const float* sp = g_sp + (size_t)bh*SSQ*DHD;

    // Load query tiles (q, T, S): 64x64 each
    for (int e = threadIdx.x; e < 64*64; e += 256) {
        const int r = e >> 6, d = e & 63;
        const size_t gi = (size_t)(qb + r)*DHD + d;
        Qq[r*ST + d] = qp[gi];
        Qt[r*ST + d] = tp[gi];
        Qs[r*ST + d] = sp[gi];
    }

    float rowscale[4];
#pragma unroll
    for (int i = 0; i < 4; i++) {
        const int q = qb + ty + i*16;
        rowscale[i] = g_itn[(size_t)bh*SSQ + q] * g_isn[(size_t)bh*SSQ + q] * 0.125f;
    }

    float m_i[4], l_i[4], O[4][4];
#pragma unroll
    for (int i = 0; i < 4; i++) {
        m_i[i] = -1e30f; l_i[i] = 0.f;
#pragma unroll
        for (int j = 0; j < 4; j++) O[i][j] = 0.f;
    }
    __syncthreads();

    for (int kb0 = 0; kb0 < SSQ; kb0 += 64) {
        // Load key-side tiles (k, T, S) — NOT V (its buffer aliases Kt)
        for (int e = threadIdx.x; e < 64*64; e += 256) {
            const int r = e >> 6, d = e & 63;
            const size_t gi = (size_t)(kb0 + r)*DHD + d;
            Kb[r*ST + d] = kp[gi];
            Kt[r*ST + d] = tp[gi];
            Ks[r*ST + d] = sp[gi];
        }
        __syncthreads();

        // Three 64x64 score accumulations
        float ab[4][4], at[4][4], as2[4][4];
#pragma unroll
        for (int i = 0; i < 4; i++)
#pragma unroll
            for (int j = 0; j < 4; j++) { ab[i][j] = 0.f; at[i][j] = 0.f; as2[i][j] = 0.f; }

#pragma unroll 8
        for (int kk = 0; kk < 64; kk++) {
            float qa[4], ta[4], sa[4], kbv[4], ktv[4], ksv[4];
#pragma unroll
            for (int i = 0; i < 4; i++) {
                qa[i] = Qq[(ty + i*16)*ST + kk];
                ta[i] = Qt[(ty + i*16)*ST + kk];
                sa[i] = Qs[(ty + i*16)*ST + kk];
            }
#pragma unroll
            for (int j = 0; j < 4; j++) {
                kbv[j] = Kb[(tx + j*16)*ST + kk];
                ktv[j] = Kt[(tx + j*16)*ST + kk];
                ksv[j] = Ks[(tx + j*16)*ST + kk];
            }
#pragma unroll
            for (int i = 0; i < 4; i++)
#pragma unroll
                for (int j = 0; j < 4; j++) {
                    ab [i][j] = fmaf(qa[i], kbv[j], ab [i][j]);
                    at [i][j] = fmaf(ta[i], ktv[j], at [i][j]);
                    as2[i][j] = fmaf(sa[i], ksv[j], as2[i][j]);
                }
        }

        float mk[4];
#pragma unroll
        for (int j = 0; j < 4; j++) mk[j] = mask[(size_t)b_*SSQ + kb0 + tx + j*16];

        __syncthreads();   // Kb/Kt reads done before P/V overlay writes

        // Cooperative V load into the dead Kt region — gmem latency overlaps
        // the softmax math below.
        for (int e = threadIdx.x; e < 64*64; e += 256) {
            const int r = e >> 6, d = e & 63;
            Vv[r*ST + d] = vp[(size_t)(kb0 + r)*DHD + d];
        }

        // Combine + online softmax (per query row: reduce across 16 tx lanes)
#pragma unroll
        for (int i = 0; i < 4; i++) {
            float c[4];
            float mc = -1e30f;
#pragma unroll
            for (int j = 0; j < 4; j++) {
                c[j] = ab[i][j] * at[i][j] * as2[i][j] * rowscale[i] + mk[j];
                mc = fmaxf(mc, c[j]);
            }
#pragma unroll
            for (int o = 1; o < 16; o <<= 1)
                mc = fmaxf(mc, __shfl_xor_sync(0xffffffffu, mc, o));
            const float mnew = fmaxf(m_i[i], mc);
            const float f = __expf(m_i[i] - mnew);
            m_i[i] = mnew;
            float rs = 0.f;
#pragma unroll
            for (int j = 0; j < 4; j++) {
                const float p = __expf(c[j] - mnew);
                Pp[(ty + i*16)*ST + tx + j*16] = p;
                rs += p;
            }
#pragma unroll
            for (int o = 1; o < 16; o <<= 1)
                rs += __shfl_xor_sync(0xffffffffu, rs, o);
            l_i[i] = l_i[i] * f + rs;
#pragma unroll
            for (int j = 0; j < 4; j++) O[i][j] *= f;
        }
        __syncthreads();

        // O += P @ V
#pragma unroll 8
        for (int kk = 0; kk < 64; kk++) {
            float pv[4], vv[4];
#pragma unroll
            for (int i = 0; i < 4; i++) pv[i] = Pp[(ty + i*16)*ST + kk];
#pragma unroll
            for (int j = 0; j < 4; j++) vv[j] = Vv[kk*ST + tx + j*16];
#pragma unroll
            for (int i = 0; i < 4; i++)
#pragma unroll
                for (int j = 0; j < 4; j++) O[i][j] = fmaf(pv[i], vv[j], O[i][j]);
        }
        __syncthreads();
    }

    // Write out: [B,S,H] with head h at cols h*64..h*64+63
#pragma unroll
    for (int i = 0; i < 4; i++) {
        const int q = qb + ty + i*16;
        const float inv_l = 1.0f / l_i[i];
#pragma unroll
        for (int j = 0; j < 4; j++) {
            const int d = tx + j*16;
            out[((size_t)b_*SSQ + q)*HD + h*DHD + d] = O[i][j] * inv_l;
        }
    }
}

// ---------------------------------------------------------------------------
extern "C" void kernel_launch(void* const* d_in, const int* in_sizes, int n_in,
                              void* d_out, int out_size)
{
    const float* hs   = (const float*)d_in[0];
    const float* te   = (const float*)d_in[1];
    const float* se   = (const float*)d_in[2];
    const float* mask = (const float*)d_in[3];
    const float* Wq = (const float*)d_in[4];  const float* bq = (const float*)d_in[5];
    const float* Wk = (const float*)d_in[6];  const float* bk = (const float*)d_in[7];
    const float* Wv = (const float*)d_in[8];  const float* bv = (const float*)d_in[9];
    const float* Wt = (const float*)d_in[10]; const float* bt = (const float*)d_in[11];
    const float* Ws = (const float*)d_in[12]; const float* bs = (const float*)d_in[13];
    float* out = (float*)d_out;

    dim3 gp(NHD, (BB*SSQ)/128, 5);  // (12, 32, 5)
    proj_kernel<<<gp, 256>>>(hs, te, se, Wq, bq, Wk, bk, Wv, bv, Wt, bt, Ws, bs);

    cudaFuncSetAttribute(attn_kernel, cudaFuncAttributeMaxDynamicSharedMemorySize, ATTN_SMEM);
    dim3 ga(SSQ/64, BB*NHD);        // (16, 48)
    attn_kernel<<<ga, 256, ATTN_SMEM>>>(mask, out);
}

// round 6
// speedup vs baseline: 1.5076x; 1.2091x over previous
#include <cuda_runtime.h>
#include <math.h>

#define HD   768
#define NHD  12
#define DHD  64
#define BB   4
#define SSQ  1024
#define EPSF 1e-6f

// Scratch: q,k,t,s stored TRANSPOSED per (b,h): [bh][dim 64][token 1024].
// v stored normal: [bh][token 1024][dim 64].
__device__ float g_qT[BB*NHD*DHD*SSQ];
__device__ float g_kT[BB*NHD*DHD*SSQ];
__device__ float g_tT[BB*NHD*DHD*SSQ];
__device__ float g_sT[BB*NHD*DHD*SSQ];
__device__ float g_v [BB*NHD*SSQ*DHD];
__device__ float g_itn[BB*NHD*SSQ];   // 1/(||T_row||+eps)
__device__ float g_isn[BB*NHD*SSQ];   // 1/(||S_row||+eps)

// ---------------------------------------------------------------------------
// Projection GEMM: out[n,o] = sum_i X[n,i]*W[o,i] + b[o]
// BM=128, BN=64, BK=32, 256 thr, 8x4 micro-tile (strided), float4 LDS along kk.
// q/k/t/s written transposed via smem-staged transpose (coalesced STG).
// ---------------------------------------------------------------------------
#define XS 36   // stride for 32-wide k tiles (mult of 4 for LDS.128 alignment)

__global__ __launch_bounds__(256) void proj_kernel(
    const float* __restrict__ hs, const float* __restrict__ te, const float* __restrict__ se,
    const float* __restrict__ Wq, const float* __restrict__ bq,
    const float* __restrict__ Wk, const float* __restrict__ bk,
    const float* __restrict__ Wv, const float* __restrict__ bv,
    const float* __restrict__ Wt, const float* __restrict__ bt,
    const float* __restrict__ Ws, const float* __restrict__ bs)
{
    __shared__ float pool[128*XS + 64*XS];   // Xs | Wsm ; reused as transpose stage
    float* Xs  = pool;            // [128][XS]
    float* Wsm = pool + 128*XS;   // [64][XS]

    const int z = blockIdx.z;
    const float* X; const float* W; const float* bias; float* invn;
    if      (z == 0) { X = hs; W = Wq; bias = bq; invn = 0;     }
    else if (z == 1) { X = hs; W = Wk; bias = bk; invn = 0;     }
    else if (z == 2) { X = hs; W = Wv; bias = bv; invn = 0;     }
    else if (z == 3) { X = te; W = Wt; bias = bt; invn = g_itn; }
    else             { X = se; W = Ws; bias = bs; invn = g_isn; }

    const int tid = threadIdx.x;
    const int tx = tid & 15;
    const int ty = tid >> 4;
    const int nb = blockIdx.y * 128;  // token base
    const int h  = blockIdx.x;        // head
    const int ob = h * 64;            // output col base

    float acc[8][4];
#pragma unroll
    for (int i = 0; i < 8; i++)
#pragma unroll
        for (int j = 0; j < 4; j++) acc[i][j] = 0.f;

    for (int kb = 0; kb < HD; kb += 32) {
        // X tile 128x32 (1024 float4, 4/thread), W tile 64x32 (512, 2/thread)
#pragma unroll
        for (int l = 0; l < 4; l++) {
            const int flat = tid + l*256;
            const int r  = flat >> 3;
            const int c4 = (flat & 7) * 4;
            float4 v = *(const float4*)(X + (size_t)(nb + r)*HD + kb + c4);
            *(float4*)&Xs[r*XS + c4] = v;
        }
#pragma unroll
        for (int l = 0; l < 2; l++) {
            const int flat = tid + l*256;
            const int r  = flat >> 3;
            const int c4 = (flat & 7) * 4;
            float4 v = *(const float4*)(W + (size_t)(ob + r)*HD + kb + c4);
            *(float4*)&Wsm[r*XS + c4] = v;
        }
        __syncthreads();
#pragma unroll
        for (int kk4 = 0; kk4 < 8; kk4++) {
            float4 a4[8], b4[4];
#pragma unroll
            for (int i = 0; i < 8; i++) a4[i] = *(const float4*)&Xs [(ty + i*16)*XS + 4*kk4];
#pragma unroll
            for (int j = 0; j < 4; j++) b4[j] = *(const float4*)&Wsm[(tx + j*16)*XS + 4*kk4];
#pragma unroll
            for (int i = 0; i < 8; i++)
#pragma unroll
                for (int j = 0; j < 4; j++) {
                    acc[i][j] = fmaf(a4[i].x, b4[j].x, acc[i][j]);
                    acc[i][j] = fmaf(a4[i].y, b4[j].y, acc[i][j]);
                    acc[i][j] = fmaf(a4[i].z, b4[j].z, acc[i][j]);
                    acc[i][j] = fmaf(a4[i].w, b4[j].w, acc[i][j]);
                }
        }
        __syncthreads();
    }

    // bias + norms
    float bj[4];
#pragma unroll
    for (int j = 0; j < 4; j++) bj[j] = bias[ob + tx + j*16];

    const int b_ = nb / SSQ;          // block's 128 tokens lie in one batch
    const int sbase = nb - b_*SSQ;
    const size_t bh = (size_t)b_*NHD + h;

#pragma unroll
    for (int i = 0; i < 8; i++) {
#pragma unroll
        for (int j = 0; j < 4; j++) acc[i][j] += bj[j];
        if (invn) {
            float ss2 = 0.f;
#pragma unroll
            for (int j = 0; j < 4; j++) ss2 = fmaf(acc[i][j], acc[i][j], ss2);
#pragma unroll
            for (int o = 1; o < 16; o <<= 1)
                ss2 += __shfl_xor_sync(0xffffffffu, ss2, o);
            if (tx == 0)
                invn[bh*SSQ + sbase + ty + i*16] = 1.0f / (sqrtf(ss2) + EPSF);
        }
    }

    if (z == 2) {
        // V: normal layout [bh][token][dim], coalesced direct store
#pragma unroll
        for (int i = 0; i < 8; i++) {
            const size_t base = (bh*SSQ + sbase + ty + i*16) * DHD;
#pragma unroll
            for (int j = 0; j < 4; j++) g_v[base + tx + j*16] = acc[i][j];
        }
        return;
    }

    float* outT = (z == 0) ? g_qT : (z == 1) ? g_kT : (z == 3) ? g_tT : g_sT;
    float* S = pool;   // stage [64 dim][68 token]

#pragma unroll
    for (int h2 = 0; h2 < 2; h2++) {
        __syncthreads();
#pragma unroll
        for (int i = 0; i < 4; i++) {
            const int i8 = i + 4*h2;        // rows ty + i8*16 in [h2*64, h2*64+64)
            const int tl = ty + i*16;       // token-local within half
#pragma unroll
            for (int j = 0; j < 4; j++)
                S[(tx + j*16)*68 + tl] = acc[i8][j];
        }
        __syncthreads();
#pragma unroll
        for (int l = 0; l < 4; l++) {
            const int e  = tid + l*256;
            const int d  = e >> 4;
            const int t4 = (e & 15) * 4;
            float4 v = *(const float4*)&S[d*68 + t4];
            *(float4*)(outT + ((bh*DHD + d)*SSQ + sbase + h2*64 + t4)) = v;
        }
    }
}

// ---------------------------------------------------------------------------
// Flash attention. Block = 64 queries of one (b,h). All score operands in
// [dim][token] smem tiles -> float4 LDS. P row-major, V [token][dim].
// ---------------------------------------------------------------------------
#define AST 68
#define ATTN_SMEM (6 * 64 * AST * 4)   // 104448 B

__global__ __launch_bounds__(256, 2) void attn_kernel(const float* __restrict__ mask,
                                                      float* __restrict__ out)
{
    extern __shared__ float sm[];
    float* QqT = sm;
    float* QtT = QqT + 64*AST;
    float* QsT = QtT + 64*AST;
    float* KbT = QsT + 64*AST;
    float* KtT = KbT + 64*AST;
    float* KsT = KtT + 64*AST;
    float* Pp  = KbT;   // overlay (dead after score pass)
    float* Vv  = KtT;   // overlay

    const int tid = threadIdx.x;
    const int tx = tid & 15;     // cols 4*tx+j (keys / dims)
    const int ty = tid >> 4;     // rows 4*ty+i (queries)
    const int bh = blockIdx.y;
    const int b_ = bh / NHD;
    const int h  = bh - b_*NHD;
    const int qb = blockIdx.x * 64;

    const float* qT = g_qT + (size_t)bh*DHD*SSQ;
    const float* kT = g_kT + (size_t)bh*DHD*SSQ;
    const float* tT = g_tT + (size_t)bh*DHD*SSQ;
    const float* sT = g_sT + (size_t)bh*DHD*SSQ;
    const float* vp = g_v  + (size_t)bh*SSQ*DHD;

    // Q-side tiles [dim][token]
#pragma unroll
    for (int l = 0; l < 4; l++) {
        const int e  = tid + l*256;
        const int d  = e >> 4;
        const int t4 = (e & 15) * 4;
        *(float4*)&QqT[d*AST + t4] = *(const float4*)(qT + (size_t)d*SSQ + qb + t4);
        *(float4*)&QtT[d*AST + t4] = *(const float4*)(tT + (size_t)d*SSQ + qb + t4);
        *(float4*)&QsT[d*AST + t4] = *(const float4*)(sT + (size_t)d*SSQ + qb + t4);
    }

    float rowscale[4];
#pragma unroll
    for (int i = 0; i < 4; i++) {
        const int q = qb + 4*ty + i;
        rowscale[i] = g_itn[(size_t)bh*SSQ + q] * g_isn[(size_t)bh*SSQ + q] * 0.125f;
    }

    float m_i[4], l_i[4], O[4][4];
#pragma unroll
    for (int i = 0; i < 4; i++) {
        m_i[i] = -1e30f; l_i[i] = 0.f;
#pragma unroll
        for (int j = 0; j < 4; j++) O[i][j] = 0.f;
    }
    __syncthreads();

    for (int kb0 = 0; kb0 < SSQ; kb0 += 64) {
        // K-side tiles [dim][token]
#pragma unroll
        for (int l = 0; l < 4; l++) {
            const int e  = tid + l*256;
            const int d  = e >> 4;
            const int t4 = (e & 15) * 4;
            *(float4*)&KbT[d*AST + t4] = *(const float4*)(kT + (size_t)d*SSQ + kb0 + t4);
            *(float4*)&KtT[d*AST + t4] = *(const float4*)(tT + (size_t)d*SSQ + kb0 + t4);
            *(float4*)&KsT[d*AST + t4] = *(const float4*)(sT + (size_t)d*SSQ + kb0 + t4);
        }
        __syncthreads();

        float ab[4][4], at[4][4], as2[4][4];
#pragma unroll
        for (int i = 0; i < 4; i++)
#pragma unroll
            for (int j = 0; j < 4; j++) { ab[i][j] = 0.f; at[i][j] = 0.f; as2[i][j] = 0.f; }

#pragma unroll 4
        for (int kk = 0; kk < 64; kk++) {
            float4 q4 = *(const float4*)&QqT[kk*AST + 4*ty];
            float4 t4 = *(const float4*)&QtT[kk*AST + 4*ty];
            float4 s4 = *(const float4*)&QsT[kk*AST + 4*ty];
            float4 kb4 = *(const float4*)&KbT[kk*AST + 4*tx];
            float4 kt4 = *(const float4*)&KtT[kk*AST + 4*tx];
            float4 ks4 = *(const float4*)&KsT[kk*AST + 4*tx];
            const float qa[4] = {q4.x, q4.y, q4.z, q4.w};
            const float ta[4] = {t4.x, t4.y, t4.z, t4.w};
            const float sa[4] = {s4.x, s4.y, s4.z, s4.w};
            const float kb_[4] = {kb4.x, kb4.y, kb4.z, kb4.w};
            const float kt_[4] = {kt4.x, kt4.y, kt4.z, kt4.w};
            const float ks_[4] = {ks4.x, ks4.y, ks4.z, ks4.w};
#pragma unroll
            for (int i = 0; i < 4; i++)
#pragma unroll
                for (int j = 0; j < 4; j++) {
                    ab [i][j] = fmaf(qa[i], kb_[j], ab [i][j]);
                    at [i][j] = fmaf(ta[i], kt_[j], at [i][j]);
                    as2[i][j] = fmaf(sa[i], ks_[j], as2[i][j]);
                }
        }

        float4 mk4 = *(const float4*)(mask + (size_t)b_*SSQ + kb0 + 4*tx);
        const float mk[4] = {mk4.x, mk4.y, mk4.z, mk4.w};

        __syncthreads();   // K-tile reads done before P/V overlay writes

        // Prefetch V into registers (latency overlaps softmax below)
        float4 vreg[4];
#pragma unroll
        for (int l = 0; l < 4; l++) {
            const int e  = tid + l*256;
            const int r  = e >> 4;
            const int c4 = (e & 15) * 4;
            vreg[l] = *(const float4*)(vp + (size_t)(kb0 + r)*DHD + c4);
        }

        // Softmax (online), P written as float4 rows
#pragma unroll
        for (int i = 0; i < 4; i++) {
            float c[4];
            float mc = -1e30f;
#pragma unroll
            for (int j = 0; j < 4; j++) {
                c[j] = ab[i][j] * at[i][j] * as2[i][j] * rowscale[i] + mk[j];
                mc = fmaxf(mc, c[j]);
            }
#pragma unroll
            for (int o = 1; o < 16; o <<= 1)
                mc = fmaxf(mc, __shfl_xor_sync(0xffffffffu, mc, o));
            const float mnew = fmaxf(m_i[i], mc);
            const float f = __expf(m_i[i] - mnew);
            m_i[i] = mnew;
            float4 p4;
            p4.x = __expf(c[0] - mnew);
            p4.y = __expf(c[1] - mnew);
            p4.z = __expf(c[2] - mnew);
            p4.w = __expf(c[3] - mnew);
            *(float4*)&Pp[(4*ty + i)*AST + 4*tx] = p4;
            float rs = p4.x + p4.y + p4.z + p4.w;
#pragma unroll
            for (int o = 1; o < 16; o <<= 1)
                rs += __shfl_xor_sync(0xffffffffu, rs, o);
            l_i[i] = l_i[i] * f + rs;
#pragma unroll
            for (int j = 0; j < 4; j++) O[i][j] *= f;
        }

        // Store V tile [token][dim]
#pragma unroll
        for (int l = 0; l < 4; l++) {
            const int e  = tid + l*256;
            const int r  = e >> 4;
            const int c4 = (e & 15) * 4;
            *(float4*)&Vv[r*AST + c4] = vreg[l];
        }
        __syncthreads();

        // O += P @ V
#pragma unroll 2
        for (int kk4 = 0; kk4 < 16; kk4++) {
            float4 vv[4];
#pragma unroll
            for (int t = 0; t < 4; t++)
                vv[t] = *(const float4*)&Vv[(4*kk4 + t)*AST + 4*tx];
#pragma unroll
            for (int i = 0; i < 4; i++) {
                float4 p4 = *(const float4*)&Pp[(4*ty + i)*AST + 4*kk4];
                O[i][0] = fmaf(p4.x, vv[0].x, O[i][0]);
                O[i][1] = fmaf(p4.x, vv[0].y, O[i][1]);
                O[i][2] = fmaf(p4.x, vv[0].z, O[i][2]);
                O[i][3] = fmaf(p4.x, vv[0].w, O[i][3]);
                O[i][0] = fmaf(p4.y, vv[1].x, O[i][0]);
                O[i][1] = fmaf(p4.y, vv[1].y, O[i][1]);
                O[i][2] = fmaf(p4.y, vv[1].z, O[i][2]);
                O[i][3] = fmaf(p4.y, vv[1].w, O[i][3]);
                O[i][0] = fmaf(p4.z, vv[2].x, O[i][0]);
                O[i][1] = fmaf(p4.z, vv[2].y, O[i][1]);
                O[i][2] = fmaf(p4.z, vv[2].z, O[i][2]);
                O[i][3] = fmaf(p4.z, vv[2].w, O[i][3]);
                O[i][0] = fmaf(p4.w, vv[3].x, O[i][0]);
                O[i][1] = fmaf(p4.w, vv[3].y, O[i][1]);
                O[i][2] = fmaf(p4.w, vv[3].z, O[i][2]);
                O[i][3] = fmaf(p4.w, vv[3].w, O[i][3]);
            }
        }
        __syncthreads();
    }

    // Write out [B,S,H], float4 per row
#pragma unroll
    for (int i = 0; i < 4; i++) {
        const int q = qb + 4*ty + i;
        const float inv_l = 1.0f / l_i[i];
        float4 o4;
        o4.x = O[i][0] * inv_l;
        o4.y = O[i][1] * inv_l;
        o4.z = O[i][2] * inv_l;
        o4.w = O[i][3] * inv_l;
        *(float4*)(out + ((size_t)b_*SSQ + q)*HD + h*DHD + 4*tx) = o4;
    }
}

// ---------------------------------------------------------------------------
extern "C" void kernel_launch(void* const* d_in, const int* in_sizes, int n_in,
                              void* d_out, int out_size)
{
    const float* hs   = (const float*)d_in[0];
    const float* te   = (const float*)d_in[1];
    const float* se   = (const float*)d_in[2];
    const float* mask = (const float*)d_in[3];
    const float* Wq = (const float*)d_in[4];  const float* bq = (const float*)d_in[5];
    const float* Wk = (const float*)d_in[6];  const float* bk = (const float*)d_in[7];
    const float* Wv = (const float*)d_in[8];  const float* bv = (const float*)d_in[9];
    const float* Wt = (const float*)d_in[10]; const float* bt = (const float*)d_in[11];
    const float* Ws = (const float*)d_in[12]; const float* bs = (const float*)d_in[13];
    float* out = (float*)d_out;

    dim3 gp(NHD, (BB*SSQ)/128, 5);  // (12, 32, 5)
    proj_kernel<<<gp, 256>>>(hs, te, se, Wq, bq, Wk, bk, Wv, bv, Wt, bt, Ws, bs);

    cudaFuncSetAttribute(attn_kernel, cudaFuncAttributeMaxDynamicSharedMemorySize, ATTN_SMEM);
    dim3 ga(SSQ/64, BB*NHD);        // (16, 48)
    attn_kernel<<<ga, 256, ATTN_SMEM>>>(mask, out);
}

// round 8
// speedup vs baseline: 1.9364x; 1.2844x over previous
#include <cuda_runtime.h>
#include <cuda_bf16.h>
#include <math.h>
#include <stdint.h>

#define HD   768
#define NHD  12
#define DHD  64
#define BB   4
#define SSQ  1024
#define EPSF 1e-6f

#define SWZ128(x) ((x) ^ (((x) >> 3) & 0x70))

__device__ __forceinline__ uint32_t smem_u32(const void* p) {
    uint32_t a;
    asm("{ .reg .u64 t; cvta.to.shared.u64 t, %1; cvt.u32.u64 %0, t; }" : "=r"(a) : "l"(p));
    return a;
}

#define LDSM4(r, addr) \
    asm volatile("ldmatrix.sync.aligned.m8n8.x4.shared.b16 {%0,%1,%2,%3}, [%4];" \
        : "=r"((r)[0]), "=r"((r)[1]), "=r"((r)[2]), "=r"((r)[3]) : "r"(addr))

#define MMA_BF16(d, a, b0, b1) \
    asm volatile("mma.sync.aligned.m16n8k16.row.col.f32.bf16.bf16.f32 " \
        "{%0,%1,%2,%3}, {%4,%5,%6,%7}, {%8,%9}, {%0,%1,%2,%3};" \
        : "+f"((d)[0]), "+f"((d)[1]), "+f"((d)[2]), "+f"((d)[3]) \
        : "r"((a)[0]), "r"((a)[1]), "r"((a)[2]), "r"((a)[3]), "r"(b0), "r"(b1))

// ---------------------------------------------------------------------------
// Scratch (allocation-free rule: __device__ globals)
// ---------------------------------------------------------------------------
__device__ float g_qT[BB*NHD*DHD*SSQ];   // [bh][dim][token]
__device__ float g_kT[BB*NHD*DHD*SSQ];
__device__ float g_tT[BB*NHD*DHD*SSQ];
__device__ float g_sT[BB*NHD*DHD*SSQ];
__device__ float g_v [BB*NHD*SSQ*DHD];   // [bh][token][dim]
__device__ float g_itn[BB*NHD*SSQ];
__device__ float g_isn[BB*NHD*SSQ];

// bf16 split-precision operands
__device__ __nv_bfloat16 g_xh[3*BB*SSQ*HD];
__device__ __nv_bfloat16 g_xl[3*BB*SSQ*HD];
__device__ __nv_bfloat16 g_wh[5*HD*HD];
__device__ __nv_bfloat16 g_wl[5*HD*HD];

// ---------------------------------------------------------------------------
// fp32 -> bf16 hi/lo split kernels
// ---------------------------------------------------------------------------
__global__ __launch_bounds__(256) void split_x_kernel(
    const float* __restrict__ hs, const float* __restrict__ te, const float* __restrict__ se)
{
    const float* src = (blockIdx.y == 0) ? hs : (blockIdx.y == 1) ? te : se;
    const size_t off = (size_t)blockIdx.y * (size_t)(BB*SSQ*HD);
    size_t i = ((size_t)blockIdx.x * blockDim.x + threadIdx.x) * 4;
    if (i >= (size_t)(BB*SSQ*HD)) return;
    float4 x = *(const float4*)(src + i);
    __nv_bfloat16 h0 = __float2bfloat16(x.x), h1 = __float2bfloat16(x.y);
    __nv_bfloat16 h2 = __float2bfloat16(x.z), h3 = __float2bfloat16(x.w);
    __nv_bfloat162 hA; hA.x = h0; hA.y = h1;
    __nv_bfloat162 hB; hB.x = h2; hB.y = h3;
    __nv_bfloat162 lA; lA.x = __float2bfloat16(x.x - __bfloat162float(h0));
                       lA.y = __float2bfloat16(x.y - __bfloat162float(h1));
    __nv_bfloat162 lB; lB.x = __float2bfloat16(x.z - __bfloat162float(h2));
                       lB.y = __float2bfloat16(x.w - __bfloat162float(h3));
    *(__nv_bfloat162*)(g_xh + off + i)     = hA;
    *(__nv_bfloat162*)(g_xh + off + i + 2) = hB;
    *(__nv_bfloat162*)(g_xl + off + i)     = lA;
    *(__nv_bfloat162*)(g_xl + off + i + 2) = lB;
}

__global__ __launch_bounds__(256) void split_w_kernel(
    const float* __restrict__ Wq, const float* __restrict__ Wk, const float* __restrict__ Wv,
    const float* __restrict__ Wt, const float* __restrict__ Ws)
{
    const int z = blockIdx.y;
    const float* src = (z==0)?Wq:(z==1)?Wk:(z==2)?Wv:(z==3)?Wt:Ws;
    const size_t off = (size_t)z * (size_t)(HD*HD);
    size_t i = ((size_t)blockIdx.x * blockDim.x + threadIdx.x) * 4;
    if (i >= (size_t)(HD*HD)) return;
    float4 x = *(const float4*)(src + i);
    __nv_bfloat16 h0 = __float2bfloat16(x.x), h1 = __float2bfloat16(x.y);
    __nv_bfloat16 h2 = __float2bfloat16(x.z), h3 = __float2bfloat16(x.w);
    __nv_bfloat162 hA; hA.x = h0; hA.y = h1;
    __nv_bfloat162 hB; hB.x = h2; hB.y = h3;
    __nv_bfloat162 lA; lA.x = __float2bfloat16(x.x - __bfloat162float(h0));
                       lA.y = __float2bfloat16(x.y - __bfloat162float(h1));
    __nv_bfloat162 lB; lB.x = __float2bfloat16(x.z - __bfloat162float(h2));
                       lB.y = __float2bfloat16(x.w - __bfloat162float(h3));
    *(__nv_bfloat162*)(g_wh + off + i)     = hA;
    *(__nv_bfloat162*)(g_wh + off + i + 2) = hB;
    *(__nv_bfloat162*)(g_wl + off + i)     = lA;
    *(__nv_bfloat162*)(g_wl + off + i + 2) = lB;
}

// ---------------------------------------------------------------------------
// HMMA projection GEMM (mma.sync bf16, split hh+hl+lh, fp32 accum).
// Block 256 thr = 8 warps (4 x 2). Tile M=128 tok, N=128 out, K-chunk 64.
// grid = (6 Ntiles, 32 Mtiles, 5 gemms).
// ---------------------------------------------------------------------------
#define PROJ_SMEM (4*16384)   // Ah|Al|Bh|Bl bf16 tiles, 64 KB

__global__ __launch_bounds__(256) void proj_hmma_kernel(
    const float* __restrict__ bq, const float* __restrict__ bk,
    const float* __restrict__ bv, const float* __restrict__ bt,
    const float* __restrict__ bs)
{
    extern __shared__ char dsm[];
    const uint32_t smb = smem_u32(dsm);
    const uint32_t offAh = 0, offAl = 16384, offBh = 32768, offBl = 49152;

    const int tid  = threadIdx.x;
    const int lane = tid & 31;
    const int wid  = tid >> 5;
    const int wm   = wid & 3;    // 0..3 -> 32 rows each
    const int wn   = wid >> 2;   // 0..1 -> 64 cols each (one head)
    const int nt = blockIdx.x;   // 0..5
    const int mt = blockIdx.y;   // 0..31
    const int z  = blockIdx.z;

    const int xsel = (z <= 2) ? 0 : (z == 3) ? 1 : 2;
    const __nv_bfloat16* Xh = g_xh + (size_t)xsel * (BB*SSQ*HD);
    const __nv_bfloat16* Xl = g_xl + (size_t)xsel * (BB*SSQ*HD);
    const __nv_bfloat16* Wh = g_wh + (size_t)z * (HD*HD);
    const __nv_bfloat16* Wl = g_wl + (size_t)z * (HD*HD);
    const float* bias = (z==0)?bq:(z==1)?bk:(z==2)?bv:(z==3)?bt:bs;

    float D[2][8][4];
#pragma unroll
    for (int mf = 0; mf < 2; mf++)
#pragma unroll
        for (int nf = 0; nf < 8; nf++)
#pragma unroll
            for (int c = 0; c < 4; c++) D[mf][nf][c] = 0.f;

    // ldmatrix lane-address components (constant across chunks)
    const int a_row = wm*32 + (lane & 15);           // + mf*16
    const int a_hi  = (lane >> 4);                   // kseg low bit
    const int b_row = wn*64 + (lane & 7) + (lane >> 4)*8;   // + g*16
    const int b_hi  = (lane >> 3) & 1;

    for (int kb = 0; kb < 12; kb++) {
        // ---- fill 4 smem tiles: each 128 rows x 64 bf16 (128B/row, SW128) ----
        __syncthreads();
#pragma unroll
        for (int l = 0; l < 4; l++) {
            const int flat = tid + l*256;       // 0..1023
            const int r   = flat >> 3;          // 0..127
            const int seg = flat & 7;           // 16B segment
            const uint32_t swo = SWZ128((uint32_t)(r*128 + seg*16));
            const size_t ga = (size_t)(mt*128 + r)*HD + kb*64 + seg*8;
            const size_t gb = (size_t)(nt*128 + r)*HD + kb*64 + seg*8;
            *(uint4*)(dsm + offAh + swo) = *(const uint4*)(Xh + ga);
            *(uint4*)(dsm + offAl + swo) = *(const uint4*)(Xl + ga);
            *(uint4*)(dsm + offBh + swo) = *(const uint4*)(Wh + gb);
            *(uint4*)(dsm + offBl + swo) = *(const uint4*)(Wl + gb);
        }
        __syncthreads();

#pragma unroll
        for (int ks = 0; ks < 4; ks++) {
            uint32_t ah[2][4], al[2][4];
#pragma unroll
            for (int mf = 0; mf < 2; mf++) {
                const uint32_t byo = (uint32_t)((a_row + mf*16)*128 + (ks*2 + a_hi)*16);
                LDSM4(ah[mf], smb + offAh + SWZ128(byo));
                LDSM4(al[mf], smb + offAl + SWZ128(byo));
            }
#pragma unroll
            for (int g = 0; g < 4; g++) {
                uint32_t bh4[4], bl4[4];
                const uint32_t byo = (uint32_t)((b_row + g*16)*128 + (ks*2 + b_hi)*16);
                LDSM4(bh4, smb + offBh + SWZ128(byo));
                LDSM4(bl4, smb + offBl + SWZ128(byo));
#pragma unroll
                for (int sub = 0; sub < 2; sub++) {
                    const int nf = 2*g + sub;
#pragma unroll
                    for (int mf = 0; mf < 2; mf++) {
                        MMA_BF16(D[mf][nf], ah[mf], bh4[2*sub], bh4[2*sub+1]);
                        MMA_BF16(D[mf][nf], ah[mf], bl4[2*sub], bl4[2*sub+1]);
                        MMA_BF16(D[mf][nf], al[mf], bh4[2*sub], bh4[2*sub+1]);
                    }
                }
            }
        }
    }

    // ---- epilogue ----
    const int b_ = (mt*128) >> 10;          // batch (block spans one batch)
    const int h  = nt*2 + wn;               // global head for this warp
    const size_t bh = (size_t)b_*NHD + h;

    // bias (per thread: cols wn*64 + nf*8 + (lane&3)*2 + {0,1})
    float bc[8][2];
#pragma unroll
    for (int nf = 0; nf < 8; nf++) {
        const int col = nt*128 + wn*64 + nf*8 + (lane & 3)*2;
        bc[nf][0] = bias[col];
        bc[nf][1] = bias[col + 1];
    }

    // add bias; compute T/S norms per row (head == warp's 64 cols)
#pragma unroll
    for (int mf = 0; mf < 2; mf++) {
#pragma unroll
        for (int half = 0; half < 2; half++) {
            float ss = 0.f;
#pragma unroll
            for (int nf = 0; nf < 8; nf++) {
                float v0 = D[mf][nf][half*2+0] + bc[nf][0];
                float v1 = D[mf][nf][half*2+1] + bc[nf][1];
                D[mf][nf][half*2+0] = v0;
                D[mf][nf][half*2+1] = v1;
                ss = fmaf(v0, v0, fmaf(v1, v1, ss));
            }
            if (z >= 3) {
                ss += __shfl_xor_sync(0xffffffffu, ss, 1);
                ss += __shfl_xor_sync(0xffffffffu, ss, 2);
                if ((lane & 3) == 0) {
                    const int s_ = (mt*128 + wm*32 + mf*16 + half*8 + (lane >> 2)) & 1023;
                    float* invn = (z == 3) ? g_itn : g_isn;
                    invn[bh*SSQ + s_] = 1.0f / (sqrtf(ss) + EPSF);
                }
            }
        }
    }

    if (z == 2) {
        // V: [bh][token][dim], direct float2 stores
#pragma unroll
        for (int mf = 0; mf < 2; mf++)
#pragma unroll
            for (int half = 0; half < 2; half++) {
                const int s_ = (mt*128 + wm*32 + mf*16 + half*8 + (lane >> 2)) & 1023;
                float* dst = g_v + (bh*SSQ + s_)*DHD + (lane & 3)*2;
#pragma unroll
                for (int nf = 0; nf < 8; nf++) {
                    float2 v = make_float2(D[mf][nf][half*2], D[mf][nf][half*2+1]);
                    *(float2*)(dst + nf*8) = v;
                }
            }
        return;
    }

    // q/k/t/s: transpose-stage through smem -> coalesced [dim][token] stores
    float* outT = (z==0) ? g_qT : (z==1) ? g_kT : (z==3) ? g_tT : g_sT;
    float* S = (float*)dsm;     // [128 cols][66] stage (33.8 KB <= 64 KB)

#pragma unroll
    for (int mf = 0; mf < 2; mf++) {
        __syncthreads();
#pragma unroll
        for (int half = 0; half < 2; half++) {
            const int rl = wm*16 + half*8 + (lane >> 2);   // 0..63
            const int c  = wn*64 + (lane & 3)*2;
#pragma unroll
            for (int nf = 0; nf < 8; nf++) {
                S[(c + nf*8    )*66 + rl] = D[mf][nf][half*2];
                S[(c + nf*8 + 1)*66 + rl] = D[mf][nf][half*2+1];
            }
        }
        __syncthreads();
#pragma unroll
        for (int l = 0; l < 8; l++) {
            const int e  = tid + l*256;      // 0..2047
            const int d  = e >> 4;           // 0..127
            const int r4 = (e & 15) * 4;     // 0..60
            float4 v = make_float4(S[d*66 + r4], S[d*66 + r4 + 1],
                                   S[d*66 + r4 + 2], S[d*66 + r4 + 3]);
            const int tk = mt*128 + mf*16 + (r4 >> 4)*32 + (r4 & 15);
            const int hh = nt*2 + (d >> 6);
            const int dl = d & 63;
            *(float4*)(outT + (((size_t)b_*NHD + hh)*DHD + dl)*SSQ + (tk & 1023)) = v;
        }
    }
}

// ---------------------------------------------------------------------------
// Flash attention (unchanged — at its FFMA roofline; HMMA port next round).
// ---------------------------------------------------------------------------
#define AST 68
#define ATTN_SMEM (6 * 64 * AST * 4)   // 104448 B

__global__ __launch_bounds__(256, 2) void attn_kernel(const float* __restrict__ mask,
                                                      float* __restrict__ out)
{
    extern __shared__ float sm[];
    float* QqT = sm;
    float* QtT = QqT + 64*AST;
    float* QsT = QtT + 64*AST;
    float* KbT = QsT + 64*AST;
    float* KtT = KbT + 64*AST;
    float* KsT = KtT + 64*AST;
    float* Pp  = KbT;
    float* Vv  = KtT;

    const int tid = threadIdx.x;
    const int tx = tid & 15;
    const int ty = tid >> 4;
    const int bh = blockIdx.y;
    const int b_ = bh / NHD;
    const int h  = bh - b_*NHD;
    const int qb = blockIdx.x * 64;

    const float* qT = g_qT + (size_t)bh*DHD*SSQ;
    const float* kT = g_kT + (size_t)bh*DHD*SSQ;
    const float* tT = g_tT + (size_t)bh*DHD*SSQ;
    const float* sT = g_sT + (size_t)bh*DHD*SSQ;
    const float* vp = g_v  + (size_t)bh*SSQ*DHD;

#pragma unroll
    for (int l = 0; l < 4; l++) {
        const int e  = tid + l*256;
        const int d  = e >> 4;
        const int t4 = (e & 15) * 4;
        *(float4*)&QqT[d*AST + t4] = *(const float4*)(qT + (size_t)d*SSQ + qb + t4);
        *(float4*)&QtT[d*AST + t4] = *(const float4*)(tT + (size_t)d*SSQ + qb + t4);
        *(float4*)&QsT[d*AST + t4] = *(const float4*)(sT + (size_t)d*SSQ + qb + t4);
    }

    float rowscale[4];
#pragma unroll
    for (int i = 0; i < 4; i++) {
        const int q = qb + 4*ty + i;
        rowscale[i] = g_itn[(size_t)bh*SSQ + q] * g_isn[(size_t)bh*SSQ + q] * 0.125f;
    }

    float m_i[4], l_i[4], O[4][4];
#pragma unroll
    for (int i = 0; i < 4; i++) {
        m_i[i] = -1e30f; l_i[i] = 0.f;
#pragma unroll
        for (int j = 0; j < 4; j++) O[i][j] = 0.f;
    }
    __syncthreads();

    for (int kb0 = 0; kb0 < SSQ; kb0 += 64) {
#pragma unroll
        for (int l = 0; l < 4; l++) {
            const int e  = tid + l*256;
            const int d  = e >> 4;
            const int t4 = (e & 15) * 4;
            *(float4*)&KbT[d*AST + t4] = *(const float4*)(kT + (size_t)d*SSQ + kb0 + t4);
            *(float4*)&KtT[d*AST + t4] = *(const float4*)(tT + (size_t)d*SSQ + kb0 + t4);
            *(float4*)&KsT[d*AST + t4] = *(const float4*)(sT + (size_t)d*SSQ + kb0 + t4);
        }
        __syncthreads();

        float ab[4][4], at[4][4], as2[4][4];
#pragma unroll
        for (int i = 0; i < 4; i++)
#pragma unroll
            for (int j = 0; j < 4; j++) { ab[i][j] = 0.f; at[i][j] = 0.f; as2[i][j] = 0.f; }

#pragma unroll 4
        for (int kk = 0; kk < 64; kk++) {
            float4 q4 = *(const float4*)&QqT[kk*AST + 4*ty];
            float4 t4 = *(const float4*)&QtT[kk*AST + 4*ty];
            float4 s4 = *(const float4*)&QsT[kk*AST + 4*ty];
            float4 kb4 = *(const float4*)&KbT[kk*AST + 4*tx];
            float4 kt4 = *(const float4*)&KtT[kk*AST + 4*tx];
            float4 ks4 = *(const float4*)&KsT[kk*AST + 4*tx];
            const float qa[4] = {q4.x, q4.y, q4.z, q4.w};
            const float ta[4] = {t4.x, t4.y, t4.z, t4.w};
            const float sa[4] = {s4.x, s4.y, s4.z, s4.w};
            const float kb_[4] = {kb4.x, kb4.y, kb4.z, kb4.w};
            const float kt_[4] = {kt4.x, kt4.y, kt4.z, kt4.w};
            const float ks_[4] = {ks4.x, ks4.y, ks4.z, ks4.w};
#pragma unroll
            for (int i = 0; i < 4; i++)
#pragma unroll
                for (int j = 0; j < 4; j++) {
                    ab [i][j] = fmaf(qa[i], kb_[j], ab [i][j]);
                    at [i][j] = fmaf(ta[i], kt_[j], at [i][j]);
                    as2[i][j] = fmaf(sa[i], ks_[j], as2[i][j]);
                }
        }

        float4 mk4 = *(const float4*)(mask + (size_t)b_*SSQ + kb0 + 4*tx);
        const float mk[4] = {mk4.x, mk4.y, mk4.z, mk4.w};

        __syncthreads();

        float4 vreg[4];
#pragma unroll
        for (int l = 0; l < 4; l++) {
            const int e  = tid + l*256;
            const int r  = e >> 4;
            const int c4 = (e & 15) * 4;
            vreg[l] = *(const float4*)(vp + (size_t)(kb0 + r)*DHD + c4);
        }

#pragma unroll
        for (int i = 0; i < 4; i++) {
            float c[4];
            float mc = -1e30f;
#pragma unroll
            for (int j = 0; j < 4; j++) {
                c[j] = ab[i][j] * at[i][j] * as2[i][j] * rowscale[i] + mk[j];
                mc = fmaxf(mc, c[j]);
            }
#pragma unroll
            for (int o = 1; o < 16; o <<= 1)
                mc = fmaxf(mc, __shfl_xor_sync(0xffffffffu, mc, o));
            const float mnew = fmaxf(m_i[i], mc);
            const float f = __expf(m_i[i] - mnew);
            m_i[i] = mnew;
            float4 p4;
            p4.x = __expf(c[0] - mnew);
            p4.y = __expf(c[1] - mnew);
            p4.z = __expf(c[2] - mnew);
            p4.w = __expf(c[3] - mnew);
            *(float4*)&Pp[(4*ty + i)*AST + 4*tx] = p4;
            float rs = p4.x + p4.y + p4.z + p4.w;
#pragma unroll
            for (int o = 1; o < 16; o <<= 1)
                rs += __shfl_xor_sync(0xffffffffu, rs, o);
            l_i[i] = l_i[i] * f + rs;
#pragma unroll
            for (int j = 0; j < 4; j++) O[i][j] *= f;
        }

#pragma unroll
        for (int l = 0; l < 4; l++) {
            const int e  = tid + l*256;
            const int r  = e >> 4;
            const int c4 = (e & 15) * 4;
            *(float4*)&Vv[r*AST + c4] = vreg[l];
        }
        __syncthreads();

#pragma unroll 2
        for (int kk4 = 0; kk4 < 16; kk4++) {
            float4 vv[4];
#pragma unroll
            for (int t = 0; t < 4; t++)
                vv[t] = *(const float4*)&Vv[(4*kk4 + t)*AST + 4*tx];
#pragma unroll
            for (int i = 0; i < 4; i++) {
                float4 p4 = *(const float4*)&Pp[(4*ty + i)*AST + 4*kk4];
                O[i][0] = fmaf(p4.x, vv[0].x, O[i][0]);
                O[i][1] = fmaf(p4.x, vv[0].y, O[i][1]);
                O[i][2] = fmaf(p4.x, vv[0].z, O[i][2]);
                O[i][3] = fmaf(p4.x, vv[0].w, O[i][3]);
                O[i][0] = fmaf(p4.y, vv[1].x, O[i][0]);
                O[i][1] = fmaf(p4.y, vv[1].y, O[i][1]);
                O[i][2] = fmaf(p4.y, vv[1].z, O[i][2]);
                O[i][3] = fmaf(p4.y, vv[1].w, O[i][3]);
                O[i][0] = fmaf(p4.z, vv[2].x, O[i][0]);
                O[i][1] = fmaf(p4.z, vv[2].y, O[i][1]);
                O[i][2] = fmaf(p4.z, vv[2].z, O[i][2]);
                O[i][3] = fmaf(p4.z, vv[2].w, O[i][3]);
                O[i][0] = fmaf(p4.w, vv[3].x, O[i][0]);
                O[i][1] = fmaf(p4.w, vv[3].y, O[i][1]);
                O[i][2] = fmaf(p4.w, vv[3].z, O[i][2]);
                O[i][3] = fmaf(p4.w, vv[3].w, O[i][3]);
            }
        }
        __syncthreads();
    }

#pragma unroll
    for (int i = 0; i < 4; i++) {
        const int q = qb + 4*ty + i;
        const float inv_l = 1.0f / l_i[i];
        float4 o4;
        o4.x = O[i][0] * inv_l;
        o4.y = O[i][1] * inv_l;
        o4.z = O[i][2] * inv_l;
        o4.w = O[i][3] * inv_l;
        *(float4*)(out + ((size_t)b_*SSQ + q)*HD + h*DHD + 4*tx) = o4;
    }
}

// ---------------------------------------------------------------------------
extern "C" void kernel_launch(void* const* d_in, const int* in_sizes, int n_in,
                              void* d_out, int out_size)
{
    const float* hs   = (const float*)d_in[0];
    const float* te   = (const float*)d_in[1];
    const float* se   = (const float*)d_in[2];
    const float* mask = (const float*)d_in[3];
    const float* Wq = (const float*)d_in[4];  const float* bq = (const float*)d_in[5];
    const float* Wk = (const float*)d_in[6];  const float* bk = (const float*)d_in[7];
    const float* Wv = (const float*)d_in[8];  const float* bv = (const float*)d_in[9];
    const float* Wt = (const float*)d_in[10]; const float* bt = (const float*)d_in[11];
    const float* Ws = (const float*)d_in[12]; const float* bs = (const float*)d_in[13];
    float* out = (float*)d_out;

    // Split fp32 -> bf16 hi/lo
    dim3 gx((BB*SSQ*HD)/4/256, 3);
    split_x_kernel<<<gx, 256>>>(hs, te, se);
    dim3 gw((HD*HD)/4/256, 5);
    split_w_kernel<<<gw, 256>>>(Wq, Wk, Wv, Wt, Ws);

    // HMMA projections
    cudaFuncSetAttribute(proj_hmma_kernel, cudaFuncAttributeMaxDynamicSharedMemorySize, PROJ_SMEM);
    dim3 gp(HD/128, (BB*SSQ)/128, 5);   // (6, 32, 5)
    proj_hmma_kernel<<<gp, 256, PROJ_SMEM>>>(bq, bk, bv, bt, bs);

    // attention
    cudaFuncSetAttribute(attn_kernel, cudaFuncAttributeMaxDynamicSharedMemorySize, ATTN_SMEM);
    dim3 ga(SSQ/64, BB*NHD);            // (16, 48)
    attn_kernel<<<ga, 256, ATTN_SMEM>>>(mask, out);
}

// round 9
// speedup vs baseline: 4.6096x; 2.3805x over previous
#include <cuda_runtime.h>
#include <cuda_bf16.h>
#include <cuda_fp16.h>
#include <math.h>
#include <stdint.h>

#define HD   768
#define NHD  12
#define DHD  64
#define BB   4
#define SSQ  1024
#define EPSF 1e-6f

#define SWZ128(x) ((x) ^ (((x) >> 3) & 0x70))

__device__ __forceinline__ uint32_t smem_u32(const void* p) {
    uint32_t a;
    asm("{ .reg .u64 t; cvta.to.shared.u64 t, %1; cvt.u32.u64 %0, t; }" : "=r"(a) : "l"(p));
    return a;
}

#define LDSM4(r, addr) \
    asm volatile("ldmatrix.sync.aligned.m8n8.x4.shared.b16 {%0,%1,%2,%3}, [%4];" \
        : "=r"((r)[0]), "=r"((r)[1]), "=r"((r)[2]), "=r"((r)[3]) : "r"(addr))

#define MMA_BF16(d, a, b0, b1) \
    asm volatile("mma.sync.aligned.m16n8k16.row.col.f32.bf16.bf16.f32 " \
        "{%0,%1,%2,%3}, {%4,%5,%6,%7}, {%8,%9}, {%0,%1,%2,%3};" \
        : "+f"((d)[0]), "+f"((d)[1]), "+f"((d)[2]), "+f"((d)[3]) \
        : "r"((a)[0]), "r"((a)[1]), "r"((a)[2]), "r"((a)[3]), "r"(b0), "r"(b1))

#define MMA_F16(d, a, b0, b1) \
    asm volatile("mma.sync.aligned.m16n8k16.row.col.f32.f16.f16.f32 " \
        "{%0,%1,%2,%3}, {%4,%5,%6,%7}, {%8,%9}, {%0,%1,%2,%3};" \
        : "+f"((d)[0]), "+f"((d)[1]), "+f"((d)[2]), "+f"((d)[3]) \
        : "r"((a)[0]), "r"((a)[1]), "r"((a)[2]), "r"((a)[3]), "r"(b0), "r"(b1))

__device__ __forceinline__ void cp16(uint32_t d, const void* s) {
    asm volatile("cp.async.cg.shared.global [%0], [%1], 16;" :: "r"(d), "l"(s) : "memory");
}
#define CP_COMMIT() asm volatile("cp.async.commit_group;" ::: "memory")
#define CP_WAIT(n)  asm volatile("cp.async.wait_group %0;" :: "n"(n) : "memory")

// ---------------------------------------------------------------------------
// Scratch (allocation-free rule: __device__ globals)
// ---------------------------------------------------------------------------
__device__ __nv_bfloat16 g_qh [BB*NHD*SSQ*DHD];   // q hi  [bh][tok][dim]
__device__ __nv_bfloat16 g_ql [BB*NHD*SSQ*DHD];   // q lo
__device__ __nv_bfloat16 g_kh [BB*NHD*SSQ*DHD];
__device__ __nv_bfloat16 g_kl [BB*NHD*SSQ*DHD];
__device__ __half        g_t16[BB*NHD*SSQ*DHD];   // T fp16 [bh][tok][dim]
__device__ __half        g_s16[BB*NHD*SSQ*DHD];
__device__ __nv_bfloat16 g_vTh[BB*NHD*DHD*SSQ];   // V hi  [bh][dim][tok]
__device__ __nv_bfloat16 g_vTl[BB*NHD*DHD*SSQ];
__device__ float g_itn[BB*NHD*SSQ];
__device__ float g_isn[BB*NHD*SSQ];

// bf16 split-precision GEMM inputs
__device__ __nv_bfloat16 g_xh[3*BB*SSQ*HD];
__device__ __nv_bfloat16 g_xl[3*BB*SSQ*HD];
__device__ __nv_bfloat16 g_wh[5*HD*HD];
__device__ __nv_bfloat16 g_wl[5*HD*HD];

// ---------------------------------------------------------------------------
// fp32 -> bf16 hi/lo split kernels
// ---------------------------------------------------------------------------
__global__ __launch_bounds__(256) void split_x_kernel(
    const float* __restrict__ hs, const float* __restrict__ te, const float* __restrict__ se)
{
    const float* src = (blockIdx.y == 0) ? hs : (blockIdx.y == 1) ? te : se;
    const size_t off = (size_t)blockIdx.y * (size_t)(BB*SSQ*HD);
    size_t i = ((size_t)blockIdx.x * blockDim.x + threadIdx.x) * 4;
    if (i >= (size_t)(BB*SSQ*HD)) return;
    float4 x = *(const float4*)(src + i);
    __nv_bfloat16 h0 = __float2bfloat16(x.x), h1 = __float2bfloat16(x.y);
    __nv_bfloat16 h2 = __float2bfloat16(x.z), h3 = __float2bfloat16(x.w);
    __nv_bfloat162 hA; hA.x = h0; hA.y = h1;
    __nv_bfloat162 hB; hB.x = h2; hB.y = h3;
    __nv_bfloat162 lA; lA.x = __float2bfloat16(x.x - __bfloat162float(h0));
                       lA.y = __float2bfloat16(x.y - __bfloat162float(h1));
    __nv_bfloat162 lB; lB.x = __float2bfloat16(x.z - __bfloat162float(h2));
                       lB.y = __float2bfloat16(x.w - __bfloat162float(h3));
    *(__nv_bfloat162*)(g_xh + off + i)     = hA;
    *(__nv_bfloat162*)(g_xh + off + i + 2) = hB;
    *(__nv_bfloat162*)(g_xl + off + i)     = lA;
    *(__nv_bfloat162*)(g_xl + off + i + 2) = lB;
}

__global__ __launch_bounds__(256) void split_w_kernel(
    const float* __restrict__ Wq, const float* __restrict__ Wk, const float* __restrict__ Wv,
    const float* __restrict__ Wt, const float* __restrict__ Ws)
{
    const int z = blockIdx.y;
    const float* src = (z==0)?Wq:(z==1)?Wk:(z==2)?Wv:(z==3)?Wt:Ws;
    const size_t off = (size_t)z * (size_t)(HD*HD);
    size_t i = ((size_t)blockIdx.x * blockDim.x + threadIdx.x) * 4;
    if (i >= (size_t)(HD*HD)) return;
    float4 x = *(const float4*)(src + i);
    __nv_bfloat16 h0 = __float2bfloat16(x.x), h1 = __float2bfloat16(x.y);
    __nv_bfloat16 h2 = __float2bfloat16(x.z), h3 = __float2bfloat16(x.w);
    __nv_bfloat162 hA; hA.x = h0; hA.y = h1;
    __nv_bfloat162 hB; hB.x = h2; hB.y = h3;
    __nv_bfloat162 lA; lA.x = __float2bfloat16(x.x - __bfloat162float(h0));
                       lA.y = __float2bfloat16(x.y - __bfloat162float(h1));
    __nv_bfloat162 lB; lB.x = __float2bfloat16(x.z - __bfloat162float(h2));
                       lB.y = __float2bfloat16(x.w - __bfloat162float(h3));
    *(__nv_bfloat162*)(g_wh + off + i)     = hA;
    *(__nv_bfloat162*)(g_wh + off + i + 2) = hB;
    *(__nv_bfloat162*)(g_wl + off + i)     = lA;
    *(__nv_bfloat162*)(g_wl + off + i + 2) = lB;
}

// ---------------------------------------------------------------------------
// HMMA projection GEMM (split hh+hl+lh). Block 256 thr = 8 warps (4 x 2).
// Tile M=128 tok, N=128 out, K-chunk 64. grid = (6, 32, 5).
// Epilogue emits MMA-ready operands for attention.
// ---------------------------------------------------------------------------
#define PROJ_SMEM (4*16384)

__global__ __launch_bounds__(256) void proj_hmma_kernel(
    const float* __restrict__ bq, const float* __restrict__ bk,
    const float* __restrict__ bv, const float* __restrict__ bt,
    const float* __restrict__ bs)
{
    extern __shared__ char dsm[];
    const uint32_t smb = smem_u32(dsm);
    const uint32_t offAh = 0, offAl = 16384, offBh = 32768, offBl = 49152;

    const int tid  = threadIdx.x;
    const int lane = tid & 31;
    const int wid  = tid >> 5;
    const int wm   = wid & 3;
    const int wn   = wid >> 2;
    const int nt = blockIdx.x;
    const int mt = blockIdx.y;
    const int z  = blockIdx.z;

    const int xsel = (z <= 2) ? 0 : (z == 3) ? 1 : 2;
    const __nv_bfloat16* Xh = g_xh + (size_t)xsel * (BB*SSQ*HD);
    const __nv_bfloat16* Xl = g_xl + (size_t)xsel * (BB*SSQ*HD);
    const __nv_bfloat16* Wh = g_wh + (size_t)z * (HD*HD);
    const __nv_bfloat16* Wl = g_wl + (size_t)z * (HD*HD);
    const float* bias = (z==0)?bq:(z==1)?bk:(z==2)?bv:(z==3)?bt:bs;

    float D[2][8][4];
#pragma unroll
    for (int mf = 0; mf < 2; mf++)
#pragma unroll
        for (int nf = 0; nf < 8; nf++)
#pragma unroll
            for (int c = 0; c < 4; c++) D[mf][nf][c] = 0.f;

    const int a_row = wm*32 + (lane & 15);
    const int a_hi  = (lane >> 4);
    const int b_row = wn*64 + (lane & 7) + (lane >> 4)*8;
    const int b_hi  = (lane >> 3) & 1;

    for (int kb = 0; kb < 12; kb++) {
        __syncthreads();
#pragma unroll
        for (int l = 0; l < 4; l++) {
            const int flat = tid + l*256;
            const int r   = flat >> 3;
            const int seg = flat & 7;
            const uint32_t swo = SWZ128((uint32_t)(r*128 + seg*16));
            const size_t ga = (size_t)(mt*128 + r)*HD + kb*64 + seg*8;
            const size_t gb = (size_t)(nt*128 + r)*HD + kb*64 + seg*8;
            *(uint4*)(dsm + offAh + swo) = *(const uint4*)(Xh + ga);
            *(uint4*)(dsm + offAl + swo) = *(const uint4*)(Xl + ga);
            *(uint4*)(dsm + offBh + swo) = *(const uint4*)(Wh + gb);
            *(uint4*)(dsm + offBl + swo) = *(const uint4*)(Wl + gb);
        }
        __syncthreads();

#pragma unroll
        for (int ks = 0; ks < 4; ks++) {
            uint32_t ah[2][4], al[2][4];
#pragma unroll
            for (int mf = 0; mf < 2; mf++) {
                const uint32_t byo = (uint32_t)((a_row + mf*16)*128 + (ks*2 + a_hi)*16);
                LDSM4(ah[mf], smb + offAh + SWZ128(byo));
                LDSM4(al[mf], smb + offAl + SWZ128(byo));
            }
#pragma unroll
            for (int g = 0; g < 4; g++) {
                uint32_t bh4[4], bl4[4];
                const uint32_t byo = (uint32_t)((b_row + g*16)*128 + (ks*2 + b_hi)*16);
                LDSM4(bh4, smb + offBh + SWZ128(byo));
                LDSM4(bl4, smb + offBl + SWZ128(byo));
#pragma unroll
                for (int sub = 0; sub < 2; sub++) {
                    const int nf = 2*g + sub;
#pragma unroll
                    for (int mf = 0; mf < 2; mf++) {
                        MMA_BF16(D[mf][nf], ah[mf], bh4[2*sub], bh4[2*sub+1]);
                        MMA_BF16(D[mf][nf], ah[mf], bl4[2*sub], bl4[2*sub+1]);
                        MMA_BF16(D[mf][nf], al[mf], bh4[2*sub], bh4[2*sub+1]);
                    }
                }
            }
        }
    }

    // ---- epilogue ----
    const int b_ = (mt*128) >> 10;
    const int h  = nt*2 + wn;
    const size_t bh = (size_t)b_*NHD + h;

    // bias add
#pragma unroll
    for (int nf = 0; nf < 8; nf++) {
        const int col = nt*128 + wn*64 + nf*8 + (lane & 3)*2;
        const float b0 = bias[col], b1 = bias[col + 1];
#pragma unroll
        for (int mf = 0; mf < 2; mf++) {
            D[mf][nf][0] += b0; D[mf][nf][1] += b1;
            D[mf][nf][2] += b0; D[mf][nf][3] += b1;
        }
    }

    if (z <= 1) {
        // q/k: bf16 hi/lo [bh][tok][dim]
        __nv_bfloat16* gh = (z == 0) ? g_qh : g_kh;
        __nv_bfloat16* gl = (z == 0) ? g_ql : g_kl;
#pragma unroll
        for (int mf = 0; mf < 2; mf++)
#pragma unroll
            for (int half = 0; half < 2; half++) {
                const int s_ = (mt*128 + wm*32 + mf*16 + half*8 + (lane >> 2)) & 1023;
                const size_t base = (bh*SSQ + s_)*DHD + (lane & 3)*2;
#pragma unroll
                for (int nf = 0; nf < 8; nf++) {
                    const float v0 = D[mf][nf][half*2], v1 = D[mf][nf][half*2+1];
                    __nv_bfloat16 h0 = __float2bfloat16(v0), h1 = __float2bfloat16(v1);
                    __nv_bfloat162 hv; hv.x = h0; hv.y = h1;
                    __nv_bfloat162 lv;
                    lv.x = __float2bfloat16(v0 - __bfloat162float(h0));
                    lv.y = __float2bfloat16(v1 - __bfloat162float(h1));
                    *(uint32_t*)(gh + base + nf*8) = *(uint32_t*)&hv;
                    *(uint32_t*)(gl + base + nf*8) = *(uint32_t*)&lv;
                }
            }
        return;
    }

    if (z >= 3) {
        // T/S: fp16 [bh][tok][dim] + inverse norms
        __half* gt = (z == 3) ? g_t16 : g_s16;
        float* invn = (z == 3) ? g_itn : g_isn;
#pragma unroll
        for (int mf = 0; mf < 2; mf++)
#pragma unroll
            for (int half = 0; half < 2; half++) {
                const int s_ = (mt*128 + wm*32 + mf*16 + half*8 + (lane >> 2)) & 1023;
                const size_t base = (bh*SSQ + s_)*DHD + (lane & 3)*2;
                float ss = 0.f;
#pragma unroll
                for (int nf = 0; nf < 8; nf++) {
                    const float v0 = D[mf][nf][half*2], v1 = D[mf][nf][half*2+1];
                    ss = fmaf(v0, v0, fmaf(v1, v1, ss));
                    __half2 hv = __floats2half2_rn(v0, v1);
                    *(uint32_t*)(gt + base + nf*8) = *(uint32_t*)&hv;
                }
                ss += __shfl_xor_sync(0xffffffffu, ss, 1);
                ss += __shfl_xor_sync(0xffffffffu, ss, 2);
                if ((lane & 3) == 0)
                    invn[bh*SSQ + s_] = 1.0f / (sqrtf(ss) + EPSF);
            }
        return;
    }

    // z == 2: V -> transposed bf16 hi/lo [bh][dim][tok] via smem stage
    float* S = (float*)dsm;
#pragma unroll
    for (int mf = 0; mf < 2; mf++) {
        __syncthreads();
#pragma unroll
        for (int half = 0; half < 2; half++) {
            const int rl = wm*16 + half*8 + (lane >> 2);
            const int c  = wn*64 + (lane & 3)*2;
#pragma unroll
            for (int nf = 0; nf < 8; nf++) {
                S[(c + nf*8    )*66 + rl] = D[mf][nf][half*2];
                S[(c + nf*8 + 1)*66 + rl] = D[mf][nf][half*2+1];
            }
        }
        __syncthreads();
#pragma unroll
        for (int l = 0; l < 8; l++) {
            const int e  = tid + l*256;
            const int d  = e >> 4;
            const int r4 = (e & 15) * 4;
            float4 v = make_float4(S[d*66 + r4], S[d*66 + r4 + 1],
                                   S[d*66 + r4 + 2], S[d*66 + r4 + 3]);
            const int tk = (mt*128 + mf*16 + (r4 >> 4)*32 + (r4 & 15)) & 1023;
            const int hh = nt*2 + (d >> 6);
            const int dl = d & 63;
            const size_t ob = (((size_t)b_*NHD + hh)*DHD + dl)*SSQ + tk;
            __nv_bfloat16 hx = __float2bfloat16(v.x), hy = __float2bfloat16(v.y);
            __nv_bfloat16 hz = __float2bfloat16(v.z), hw = __float2bfloat16(v.w);
            __nv_bfloat162 hA; hA.x = hx; hA.y = hy;
            __nv_bfloat162 hB; hB.x = hz; hB.y = hw;
            __nv_bfloat162 lA;
            lA.x = __float2bfloat16(v.x - __bfloat162float(hx));
            lA.y = __float2bfloat16(v.y - __bfloat162float(hy));
            __nv_bfloat162 lB;
            lB.x = __float2bfloat16(v.z - __bfloat162float(hz));
            lB.y = __float2bfloat16(v.w - __bfloat162float(hw));
            uint2 hu = make_uint2(*(uint32_t*)&hA, *(uint32_t*)&hB);
            uint2 lu = make_uint2(*(uint32_t*)&lA, *(uint32_t*)&lB);
            *(uint2*)(g_vTh + ob) = hu;
            *(uint2*)(g_vTl + ob) = lu;
        }
    }
}

// ---------------------------------------------------------------------------
// HMMA flash attention. Block = 128 queries of one (b,h); 8 warps x 16 rows.
// 16 key-chunks of 64, cp.async double-buffered. Scores: bf16 split q.k +
// fp16 T.T, S.S. Softmax in fragments. P->A-frag in registers; PV bf16 split.
// ---------------------------------------------------------------------------
#define QTOT      65536                  // 4 Q tiles (qh,ql,t,s) x 16KB
#define STAGE_SZ  50176                  // 6 tiles x 8KB + mask(256B) + pad
#define ATTN_SMEM (QTOT + 2*STAGE_SZ)    // 165888

__global__ __launch_bounds__(256) void attn_hmma_kernel(const float* __restrict__ mask,
                                                        float* __restrict__ out)
{
    extern __shared__ char sbuf[];
    const uint32_t smb = smem_u32(sbuf);
    const int tid = threadIdx.x;
    const int lane = tid & 31;
    const int w = tid >> 5;
    const int bh = blockIdx.y;
    const int b_ = bh / NHD;
    const int h  = bh - b_*NHD;
    const int qb = blockIdx.x * 128;

    const __nv_bfloat16* qhp = g_qh  + (size_t)bh*SSQ*DHD;
    const __nv_bfloat16* qlp = g_ql  + (size_t)bh*SSQ*DHD;
    const __half*        qtp = g_t16 + (size_t)bh*SSQ*DHD;
    const __half*        qsp = g_s16 + (size_t)bh*SSQ*DHD;
    const __nv_bfloat16* khp = g_kh  + (size_t)bh*SSQ*DHD;
    const __nv_bfloat16* klp = g_kl  + (size_t)bh*SSQ*DHD;
    const __half*        ktp = g_t16 + (size_t)bh*SSQ*DHD;
    const __half*        ksp = g_s16 + (size_t)bh*SSQ*DHD;
    const __nv_bfloat16* vhp = g_vTh + (size_t)bh*DHD*SSQ;
    const __nv_bfloat16* vlp = g_vTl + (size_t)bh*DHD*SSQ;
    const float* maskb = mask + (size_t)b_*SSQ;

    // Issue one K/V stage via cp.async
    auto issue = [&](int buf, int kb0) {
        const uint32_t so = smb + QTOT + buf*STAGE_SZ;
#pragma unroll
        for (int l = 0; l < 2; l++) {
            const int flat = tid + l*256;
            const int r = flat >> 3, seg = flat & 7;
            const uint32_t swo = SWZ128((uint32_t)(r*128 + seg*16));
            const size_t srcK = (size_t)(kb0 + r)*DHD + seg*8;
            cp16(so +     0 + swo, khp + srcK);
            cp16(so +  8192 + swo, klp + srcK);
            cp16(so + 16384 + swo, ktp + srcK);
            cp16(so + 24576 + swo, ksp + srcK);
            const size_t srcV = (size_t)r*SSQ + kb0 + seg*8;
            cp16(so + 32768 + swo, vhp + srcV);
            cp16(so + 40960 + swo, vlp + srcV);
        }
        if (tid < 16) cp16(so + 49152 + tid*16, maskb + kb0 + tid*4);
    };

    issue(0, 0);
    CP_COMMIT();

    // Q tiles (qh, ql, t, s): 4 x 128 rows x 128B, SW128
    {
        const char* qsrc[4] = {(const char*)qhp, (const char*)qlp,
                               (const char*)qtp, (const char*)qsp};
#pragma unroll
        for (int l = 0; l < 16; l++) {
            const int flat = tid + l*256;
            const int t = flat >> 10;
            const int idx = flat & 1023;
            const int r = idx >> 3, seg = idx & 7;
            uint4 v = *(const uint4*)(qsrc[t] + ((size_t)(qb + r)*DHD + seg*8)*2);
            *(uint4*)(sbuf + t*16384 + SWZ128((uint32_t)(r*128 + seg*16))) = v;
        }
    }

    // rowscale = itn*isn/8 for this thread's two rows
    const int q0 = qb + w*16 + (lane >> 2);
    float rs[2];
    rs[0] = g_itn[(size_t)bh*SSQ + q0]     * g_isn[(size_t)bh*SSQ + q0]     * 0.125f;
    rs[1] = g_itn[(size_t)bh*SSQ + q0 + 8] * g_isn[(size_t)bh*SSQ + q0 + 8] * 0.125f;

    float O[8][4];
#pragma unroll
    for (int nf = 0; nf < 8; nf++)
#pragma unroll
        for (int c = 0; c < 4; c++) O[nf][c] = 0.f;
    float m0 = -1e30f, m1 = -1e30f, l0 = 0.f, l1 = 0.f;

    const int arow = w*16 + (lane & 15);
    const int asel = lane >> 4;
    const int brow = (lane & 7) + (lane >> 4)*8;
    const int bsel = (lane >> 3) & 1;

    for (int c = 0; c < 16; c++) {
        const int buf = c & 1;
        const uint32_t so = smb + QTOT + buf*STAGE_SZ;
        const char* sp = sbuf + QTOT + buf*STAGE_SZ;

        if (c + 1 < 16) { issue(buf ^ 1, (c + 1)*64); CP_COMMIT(); CP_WAIT(1); }
        else            { CP_WAIT(0); }
        __syncthreads();

        // ---- scores ----
        float sb[8][4], st4[8][4], ss4[8][4];
#pragma unroll
        for (int nf = 0; nf < 8; nf++)
#pragma unroll
            for (int cc = 0; cc < 4; cc++) { sb[nf][cc] = 0.f; st4[nf][cc] = 0.f; ss4[nf][cc] = 0.f; }

#pragma unroll
        for (int ks = 0; ks < 4; ks++) {
            uint32_t ah[4], al[4], at_[4], as_[4];
            const uint32_t aoff = SWZ128((uint32_t)(arow*128 + (ks*2 + asel)*16));
            LDSM4(ah,  smb         + aoff);
            LDSM4(al,  smb + 16384 + aoff);
            LDSM4(at_, smb + 32768 + aoff);
            LDSM4(as_, smb + 49152 + aoff);
#pragma unroll
            for (int g = 0; g < 4; g++) {
                const uint32_t boff = SWZ128((uint32_t)((g*16 + brow)*128 + (ks*2 + bsel)*16));
                uint32_t bh4[4], bl4[4], bt4[4], bs4[4];
                LDSM4(bh4, so +     0 + boff);
                LDSM4(bl4, so +  8192 + boff);
                LDSM4(bt4, so + 16384 + boff);
                LDSM4(bs4, so + 24576 + boff);
#pragma unroll
                for (int sub = 0; sub < 2; sub++) {
                    const int nf = 2*g + sub;
                    MMA_BF16(sb[nf],  ah,  bh4[2*sub], bh4[2*sub+1]);
                    MMA_BF16(sb[nf],  ah,  bl4[2*sub], bl4[2*sub+1]);
                    MMA_BF16(sb[nf],  al,  bh4[2*sub], bh4[2*sub+1]);
                    MMA_F16 (st4[nf], at_, bt4[2*sub], bt4[2*sub+1]);
                    MMA_F16 (ss4[nf], as_, bs4[2*sub], bs4[2*sub+1]);
                }
            }
        }

        // ---- combine + online softmax (fragment layout) ----
        const float* mkp = (const float*)(sp + 49152);
        float mloc0 = -1e30f, mloc1 = -1e30f;
#pragma unroll
        for (int nf = 0; nf < 8; nf++) {
            const float2 mk = *(const float2*)(mkp + nf*8 + (lane & 3)*2);
            float s0 = sb[nf][0]*st4[nf][0]*ss4[nf][0]*rs[0] + mk.x;
            float s1 = sb[nf][1]*st4[nf][1]*ss4[nf][1]*rs[0] + mk.y;
            float s2 = sb[nf][2]*st4[nf][2]*ss4[nf][2]*rs[1] + mk.x;
            float s3 = sb[nf][3]*st4[nf][3]*ss4[nf][3]*rs[1] + mk.y;
            sb[nf][0] = s0; sb[nf][1] = s1; sb[nf][2] = s2; sb[nf][3] = s3;
            mloc0 = fmaxf(mloc0, fmaxf(s0, s1));
            mloc1 = fmaxf(mloc1, fmaxf(s2, s3));
        }
        mloc0 = fmaxf(mloc0, __shfl_xor_sync(0xffffffffu, mloc0, 1));
        mloc0 = fmaxf(mloc0, __shfl_xor_sync(0xffffffffu, mloc0, 2));
        mloc1 = fmaxf(mloc1, __shfl_xor_sync(0xffffffffu, mloc1, 1));
        mloc1 = fmaxf(mloc1, __shfl_xor_sync(0xffffffffu, mloc1, 2));
        const float mn0 = fmaxf(m0, mloc0), mn1 = fmaxf(m1, mloc1);
        const float cr0 = __expf(m0 - mn0), cr1 = __expf(m1 - mn1);
        m0 = mn0; m1 = mn1;

        float rsum0 = 0.f, rsum1 = 0.f;
#pragma unroll
        for (int nf = 0; nf < 8; nf++) {
            float p0 = __expf(sb[nf][0] - mn0);
            float p1 = __expf(sb[nf][1] - mn0);
            float p2 = __expf(sb[nf][2] - mn1);
            float p3 = __expf(sb[nf][3] - mn1);
            sb[nf][0] = p0; sb[nf][1] = p1; sb[nf][2] = p2; sb[nf][3] = p3;
            rsum0 += p0 + p1; rsum1 += p2 + p3;
            O[nf][0] *= cr0; O[nf][1] *= cr0; O[nf][2] *= cr1; O[nf][3] *= cr1;
        }
        rsum0 += __shfl_xor_sync(0xffffffffu, rsum0, 1);
        rsum0 += __shfl_xor_sync(0xffffffffu, rsum0, 2);
        rsum1 += __shfl_xor_sync(0xffffffffu, rsum1, 1);
        rsum1 += __shfl_xor_sync(0xffffffffu, rsum1, 2);
        l0 = l0*cr0 + rsum0;
        l1 = l1*cr1 + rsum1;

        // ---- P @ V : P acc-frags -> A-frags in registers (hi/lo) ----
#pragma unroll
        for (int ks = 0; ks < 4; ks++) {
            uint32_t ph[4], pl[4];
#pragma unroll
            for (int half = 0; half < 2; half++) {        // frag 2ks, 2ks+1
                const int nf = 2*ks + half;
#pragma unroll
                for (int rr = 0; rr < 2; rr++) {          // rows r / r+8
                    const float p0 = sb[nf][rr*2], p1 = sb[nf][rr*2+1];
                    __nv_bfloat16 h0 = __float2bfloat16(p0), h1 = __float2bfloat16(p1);
                    __nv_bfloat162 hv; hv.x = h0; hv.y = h1;
                    __nv_bfloat162 lv;
                    lv.x = __float2bfloat16(p0 - __bfloat162float(h0));
                    lv.y = __float2bfloat16(p1 - __bfloat162float(h1));
                    ph[half*2 + rr] = *(uint32_t*)&hv;
                    pl[half*2 + rr] = *(uint32_t*)&lv;
                }
            }
#pragma unroll
            for (int g = 0; g < 4; g++) {
                const uint32_t boff = SWZ128((uint32_t)((g*16 + brow)*128 + (ks*2 + bsel)*16));
                uint32_t vh4[4], vl4[4];
                LDSM4(vh4, so + 32768 + boff);
                LDSM4(vl4, so + 40960 + boff);
#pragma unroll
                for (int sub = 0; sub < 2; sub++) {
                    const int nf = 2*g + sub;
                    MMA_BF16(O[nf], ph, vh4[2*sub], vh4[2*sub+1]);
                    MMA_BF16(O[nf], ph, vl4[2*sub], vl4[2*sub+1]);
                    MMA_BF16(O[nf], pl, vh4[2*sub], vh4[2*sub+1]);
                }
            }
        }
        __syncthreads();   // all reads of this stage done before refill
    }

    // ---- epilogue ----
    const float il0 = 1.0f / l0, il1 = 1.0f / l1;
    float* o0 = out + ((size_t)b_*SSQ + q0    )*HD + h*DHD + (lane & 3)*2;
    float* o1 = out + ((size_t)b_*SSQ + q0 + 8)*HD + h*DHD + (lane & 3)*2;
#pragma unroll
    for (int nf = 0; nf < 8; nf++) {
        *(float2*)(o0 + nf*8) = make_float2(O[nf][0]*il0, O[nf][1]*il0);
        *(float2*)(o1 + nf*8) = make_float2(O[nf][2]*il1, O[nf][3]*il1);
    }
}

// ---------------------------------------------------------------------------
extern "C" void kernel_launch(void* const* d_in, const int* in_sizes, int n_in,
                              void* d_out, int out_size)
{
    const float* hs   = (const float*)d_in[0];
    const float* te   = (const float*)d_in[1];
    const float* se   = (const float*)d_in[2];
    const float* mask = (const float*)d_in[3];
    const float* Wq = (const float*)d_in[4];  const float* bq = (const float*)d_in[5];
    const float* Wk = (const float*)d_in[6];  const float* bk = (const float*)d_in[7];
    const float* Wv = (const float*)d_in[8];  const float* bv = (const float*)d_in[9];
    const float* Wt = (const float*)d_in[10]; const float* bt = (const float*)d_in[11];
    const float* Ws = (const float*)d_in[12]; const float* bs = (const float*)d_in[13];
    float* out = (float*)d_out;

    dim3 gx((BB*SSQ*HD)/4/256, 3);
    split_x_kernel<<<gx, 256>>>(hs, te, se);
    dim3 gw((HD*HD)/4/256, 5);
    split_w_kernel<<<gw, 256>>>(Wq, Wk, Wv, Wt, Ws);

    cudaFuncSetAttribute(proj_hmma_kernel, cudaFuncAttributeMaxDynamicSharedMemorySize, PROJ_SMEM);
    dim3 gp(HD/128, (BB*SSQ)/128, 5);   // (6, 32, 5)
    proj_hmma_kernel<<<gp, 256, PROJ_SMEM>>>(bq, bk, bv, bt, bs);

    cudaFuncSetAttribute(attn_hmma_kernel, cudaFuncAttributeMaxDynamicSharedMemorySize, ATTN_SMEM);
    dim3 ga(SSQ/128, BB*NHD);           // (8, 48)
    attn_hmma_kernel<<<ga, 256, ATTN_SMEM>>>(mask, out);
}

// round 10
// speedup vs baseline: 5.2436x; 1.1375x over previous
#include <cuda_runtime.h>
#include <cuda_bf16.h>
#include <cuda_fp16.h>
#include <math.h>
#include <stdint.h>

#define HD   768
#define NHD  12
#define DHD  64
#define BB   4
#define SSQ  1024
#define EPSF 1e-6f

#define SWZ128(x) ((x) ^ (((x) >> 3) & 0x70))

__device__ __forceinline__ uint32_t smem_u32(const void* p) {
    uint32_t a;
    asm("{ .reg .u64 t; cvta.to.shared.u64 t, %1; cvt.u32.u64 %0, t; }" : "=r"(a) : "l"(p));
    return a;
}

#define LDSM4(r, addr) \
    asm volatile("ldmatrix.sync.aligned.m8n8.x4.shared.b16 {%0,%1,%2,%3}, [%4];" \
        : "=r"((r)[0]), "=r"((r)[1]), "=r"((r)[2]), "=r"((r)[3]) : "r"(addr))

#define MMA_BF16(d, a, b0, b1) \
    asm volatile("mma.sync.aligned.m16n8k16.row.col.f32.bf16.bf16.f32 " \
        "{%0,%1,%2,%3}, {%4,%5,%6,%7}, {%8,%9}, {%0,%1,%2,%3};" \
        : "+f"((d)[0]), "+f"((d)[1]), "+f"((d)[2]), "+f"((d)[3]) \
        : "r"((a)[0]), "r"((a)[1]), "r"((a)[2]), "r"((a)[3]), "r"(b0), "r"(b1))

#define MMA_F16(d, a, b0, b1) \
    asm volatile("mma.sync.aligned.m16n8k16.row.col.f32.f16.f16.f32 " \
        "{%0,%1,%2,%3}, {%4,%5,%6,%7}, {%8,%9}, {%0,%1,%2,%3};" \
        : "+f"((d)[0]), "+f"((d)[1]), "+f"((d)[2]), "+f"((d)[3]) \
        : "r"((a)[0]), "r"((a)[1]), "r"((a)[2]), "r"((a)[3]), "r"(b0), "r"(b1))

__device__ __forceinline__ void cp16(uint32_t d, const void* s) {
    asm volatile("cp.async.cg.shared.global [%0], [%1], 16;" :: "r"(d), "l"(s) : "memory");
}
#define CP_COMMIT() asm volatile("cp.async.commit_group;" ::: "memory")
#define CP_WAIT(n)  asm volatile("cp.async.wait_group %0;" :: "n"(n) : "memory")

// ---------------------------------------------------------------------------
// Scratch (allocation-free rule: __device__ globals)
// ---------------------------------------------------------------------------
__device__ __nv_bfloat16 g_qh [BB*NHD*SSQ*DHD];   // q hi  [bh][tok][dim]
__device__ __nv_bfloat16 g_ql [BB*NHD*SSQ*DHD];   // q lo
__device__ __nv_bfloat16 g_kh [BB*NHD*SSQ*DHD];
__device__ __nv_bfloat16 g_kl [BB*NHD*SSQ*DHD];
__device__ __half        g_t16[BB*NHD*SSQ*DHD];   // T fp16 [bh][tok][dim]
__device__ __half        g_s16[BB*NHD*SSQ*DHD];
__device__ __nv_bfloat16 g_vTh[BB*NHD*DHD*SSQ];   // V hi  [bh][dim][tok]
__device__ __nv_bfloat16 g_vTl[BB*NHD*DHD*SSQ];
__device__ float g_itn[BB*NHD*SSQ];
__device__ float g_isn[BB*NHD*SSQ];

// bf16 split-precision GEMM inputs
__device__ __nv_bfloat16 g_xh[3*BB*SSQ*HD];
__device__ __nv_bfloat16 g_xl[3*BB*SSQ*HD];
__device__ __nv_bfloat16 g_wh[5*HD*HD];
__device__ __nv_bfloat16 g_wl[5*HD*HD];

// ---------------------------------------------------------------------------
// fp32 -> bf16 hi/lo split kernels
// ---------------------------------------------------------------------------
__global__ __launch_bounds__(256) void split_x_kernel(
    const float* __restrict__ hs, const float* __restrict__ te, const float* __restrict__ se)
{
    const float* src = (blockIdx.y == 0) ? hs : (blockIdx.y == 1) ? te : se;
    const size_t off = (size_t)blockIdx.y * (size_t)(BB*SSQ*HD);
    size_t i = ((size_t)blockIdx.x * blockDim.x + threadIdx.x) * 4;
    if (i >= (size_t)(BB*SSQ*HD)) return;
    float4 x = *(const float4*)(src + i);
    __nv_bfloat16 h0 = __float2bfloat16(x.x), h1 = __float2bfloat16(x.y);
    __nv_bfloat16 h2 = __float2bfloat16(x.z), h3 = __float2bfloat16(x.w);
    __nv_bfloat162 hA; hA.x = h0; hA.y = h1;
    __nv_bfloat162 hB; hB.x = h2; hB.y = h3;
    __nv_bfloat162 lA; lA.x = __float2bfloat16(x.x - __bfloat162float(h0));
                       lA.y = __float2bfloat16(x.y - __bfloat162float(h1));
    __nv_bfloat162 lB; lB.x = __float2bfloat16(x.z - __bfloat162float(h2));
                       lB.y = __float2bfloat16(x.w - __bfloat162float(h3));
    *(__nv_bfloat162*)(g_xh + off + i)     = hA;
    *(__nv_bfloat162*)(g_xh + off + i + 2) = hB;
    *(__nv_bfloat162*)(g_xl + off + i)     = lA;
    *(__nv_bfloat162*)(g_xl + off + i + 2) = lB;
}

__global__ __launch_bounds__(256) void split_w_kernel(
    const float* __restrict__ Wq, const float* __restrict__ Wk, const float* __restrict__ Wv,
    const float* __restrict__ Wt, const float* __restrict__ Ws)
{
    const int z = blockIdx.y;
    const float* src = (z==0)?Wq:(z==1)?Wk:(z==2)?Wv:(z==3)?Wt:Ws;
    const size_t off = (size_t)z * (size_t)(HD*HD);
    size_t i = ((size_t)blockIdx.x * blockDim.x + threadIdx.x) * 4;
    if (i >= (size_t)(HD*HD)) return;
    float4 x = *(const float4*)(src + i);
    __nv_bfloat16 h0 = __float2bfloat16(x.x), h1 = __float2bfloat16(x.y);
    __nv_bfloat16 h2 = __float2bfloat16(x.z), h3 = __float2bfloat16(x.w);
    __nv_bfloat162 hA; hA.x = h0; hA.y = h1;
    __nv_bfloat162 hB; hB.x = h2; hB.y = h3;
    __nv_bfloat162 lA; lA.x = __float2bfloat16(x.x - __bfloat162float(h0));
                       lA.y = __float2bfloat16(x.y - __bfloat162float(h1));
    __nv_bfloat162 lB; lB.x = __float2bfloat16(x.z - __bfloat162float(h2));
                       lB.y = __float2bfloat16(x.w - __bfloat162float(h3));
    *(__nv_bfloat162*)(g_wh + off + i)     = hA;
    *(__nv_bfloat162*)(g_wh + off + i + 2) = hB;
    *(__nv_bfloat162*)(g_wl + off + i)     = lA;
    *(__nv_bfloat162*)(g_wl + off + i + 2) = lB;
}

// ---------------------------------------------------------------------------
// HMMA projection GEMM (split hh+hl+lh), cp.async 2-stage pipeline.
// Block 256 thr = 8 warps (4 x 2). Tile M=128 tok, N=128 out, K-chunk 64.
// grid = (6, 32, 5). Epilogue emits MMA-ready operands for attention.
// ---------------------------------------------------------------------------
#define PSTAGE     65536            // 4 tiles x 16 KB
#define PROJ_SMEM  (2*PSTAGE)       // 131072

__global__ __launch_bounds__(256) void proj_hmma_kernel(
    const float* __restrict__ bq, const float* __restrict__ bk,
    const float* __restrict__ bv, const float* __restrict__ bt,
    const float* __restrict__ bs)
{
    extern __shared__ char dsm[];
    const uint32_t smb = smem_u32(dsm);

    const int tid  = threadIdx.x;
    const int lane = tid & 31;
    const int wid  = tid >> 5;
    const int wm   = wid & 3;
    const int wn   = wid >> 2;
    const int nt = blockIdx.x;
    const int mt = blockIdx.y;
    const int z  = blockIdx.z;

    const int xsel = (z <= 2) ? 0 : (z == 3) ? 1 : 2;
    const __nv_bfloat16* Xh = g_xh + (size_t)xsel * (BB*SSQ*HD);
    const __nv_bfloat16* Xl = g_xl + (size_t)xsel * (BB*SSQ*HD);
    const __nv_bfloat16* Wh = g_wh + (size_t)z * (HD*HD);
    const __nv_bfloat16* Wl = g_wl + (size_t)z * (HD*HD);
    const float* bias = (z==0)?bq:(z==1)?bk:(z==2)?bv:(z==3)?bt:bs;

    float D[2][8][4];
#pragma unroll
    for (int mf = 0; mf < 2; mf++)
#pragma unroll
        for (int nf = 0; nf < 8; nf++)
#pragma unroll
            for (int c = 0; c < 4; c++) D[mf][nf][c] = 0.f;

    const int a_row = wm*32 + (lane & 15);
    const int a_hi  = (lane >> 4);
    const int b_row = wn*64 + (lane & 7) + (lane >> 4)*8;
    const int b_hi  = (lane >> 3) & 1;

    // cp.async stage fill: 4 tiles (Ah|Al|Bh|Bl), each 128 rows x 128 B, SW128
    auto issue = [&](int buf, int kb) {
        const uint32_t so = smb + buf*PSTAGE;
#pragma unroll
        for (int l = 0; l < 4; l++) {
            const int flat = tid + l*256;
            const int r   = flat >> 3;
            const int seg = flat & 7;
            const uint32_t swo = SWZ128((uint32_t)(r*128 + seg*16));
            const size_t ga = (size_t)(mt*128 + r)*HD + kb*64 + seg*8;
            const size_t gb = (size_t)(nt*128 + r)*HD + kb*64 + seg*8;
            cp16(so +     0 + swo, Xh + ga);
            cp16(so + 16384 + swo, Xl + ga);
            cp16(so + 32768 + swo, Wh + gb);
            cp16(so + 49152 + swo, Wl + gb);
        }
    };

    issue(0, 0);
    CP_COMMIT();

    for (int kb = 0; kb < 12; kb++) {
        const int buf = kb & 1;
        const uint32_t so = smb + buf*PSTAGE;

        if (kb + 1 < 12) { issue(buf ^ 1, kb + 1); CP_COMMIT(); CP_WAIT(1); }
        else             { CP_WAIT(0); }
        __syncthreads();

#pragma unroll
        for (int ks = 0; ks < 4; ks++) {
            uint32_t ah[2][4], al[2][4];
#pragma unroll
            for (int mf = 0; mf < 2; mf++) {
                const uint32_t byo = SWZ128((uint32_t)((a_row + mf*16)*128 + (ks*2 + a_hi)*16));
                LDSM4(ah[mf], so +     0 + byo);
                LDSM4(al[mf], so + 16384 + byo);
            }
#pragma unroll
            for (int g = 0; g < 4; g++) {
                uint32_t bh4[4], bl4[4];
                const uint32_t byo = SWZ128((uint32_t)((b_row + g*16)*128 + (ks*2 + b_hi)*16));
                LDSM4(bh4, so + 32768 + byo);
                LDSM4(bl4, so + 49152 + byo);
#pragma unroll
                for (int sub = 0; sub < 2; sub++) {
                    const int nf = 2*g + sub;
#pragma unroll
                    for (int mf = 0; mf < 2; mf++) {
                        MMA_BF16(D[mf][nf], ah[mf], bh4[2*sub], bh4[2*sub+1]);
                        MMA_BF16(D[mf][nf], ah[mf], bl4[2*sub], bl4[2*sub+1]);
                        MMA_BF16(D[mf][nf], al[mf], bh4[2*sub], bh4[2*sub+1]);
                    }
                }
            }
        }
        __syncthreads();   // all reads of this stage done before its refill
    }

    // ---- epilogue ----
    const int b_ = (mt*128) >> 10;
    const int h  = nt*2 + wn;
    const size_t bh = (size_t)b_*NHD + h;

    // bias add
#pragma unroll
    for (int nf = 0; nf < 8; nf++) {
        const int col = nt*128 + wn*64 + nf*8 + (lane & 3)*2;
        const float b0 = bias[col], b1 = bias[col + 1];
#pragma unroll
        for (int mf = 0; mf < 2; mf++) {
            D[mf][nf][0] += b0; D[mf][nf][1] += b1;
            D[mf][nf][2] += b0; D[mf][nf][3] += b1;
        }
    }

    if (z <= 1) {
        // q/k: bf16 hi/lo [bh][tok][dim]
        __nv_bfloat16* gh = (z == 0) ? g_qh : g_kh;
        __nv_bfloat16* gl = (z == 0) ? g_ql : g_kl;
#pragma unroll
        for (int mf = 0; mf < 2; mf++)
#pragma unroll
            for (int half = 0; half < 2; half++) {
                const int s_ = (mt*128 + wm*32 + mf*16 + half*8 + (lane >> 2)) & 1023;
                const size_t base = (bh*SSQ + s_)*DHD + (lane & 3)*2;
#pragma unroll
                for (int nf = 0; nf < 8; nf++) {
                    const float v0 = D[mf][nf][half*2], v1 = D[mf][nf][half*2+1];
                    __nv_bfloat16 h0 = __float2bfloat16(v0), h1 = __float2bfloat16(v1);
                    __nv_bfloat162 hv; hv.x = h0; hv.y = h1;
                    __nv_bfloat162 lv;
                    lv.x = __float2bfloat16(v0 - __bfloat162float(h0));
                    lv.y = __float2bfloat16(v1 - __bfloat162float(h1));
                    *(uint32_t*)(gh + base + nf*8) = *(uint32_t*)&hv;
                    *(uint32_t*)(gl + base + nf*8) = *(uint32_t*)&lv;
                }
            }
        return;
    }

    if (z >= 3) {
        // T/S: fp16 [bh][tok][dim] + inverse norms
        __half* gt = (z == 3) ? g_t16 : g_s16;
        float* invn = (z == 3) ? g_itn : g_isn;
#pragma unroll
        for (int mf = 0; mf < 2; mf++)
#pragma unroll
            for (int half = 0; half < 2; half++) {
                const int s_ = (mt*128 + wm*32 + mf*16 + half*8 + (lane >> 2)) & 1023;
                const size_t base = (bh*SSQ + s_)*DHD + (lane & 3)*2;
                float ss = 0.f;
#pragma unroll
                for (int nf = 0; nf < 8; nf++) {
                    const float v0 = D[mf][nf][half*2], v1 = D[mf][nf][half*2+1];
                    ss = fmaf(v0, v0, fmaf(v1, v1, ss));
                    __half2 hv = __floats2half2_rn(v0, v1);
                    *(uint32_t*)(gt + base + nf*8) = *(uint32_t*)&hv;
                }
                ss += __shfl_xor_sync(0xffffffffu, ss, 1);
                ss += __shfl_xor_sync(0xffffffffu, ss, 2);
                if ((lane & 3) == 0)
                    invn[bh*SSQ + s_] = 1.0f / (sqrtf(ss) + EPSF);
            }
        return;
    }

    // z == 2: V -> transposed bf16 hi/lo [bh][dim][tok] via smem stage
    float* S = (float*)dsm;
#pragma unroll
    for (int mf = 0; mf < 2; mf++) {
        __syncthreads();
#pragma unroll
        for (int half = 0; half < 2; half++) {
            const int rl = wm*16 + half*8 + (lane >> 2);
            const int c  = wn*64 + (lane & 3)*2;
#pragma unroll
            for (int nf = 0; nf < 8; nf++) {
                S[(c + nf*8    )*66 + rl] = D[mf][nf][half*2];
                S[(c + nf*8 + 1)*66 + rl] = D[mf][nf][half*2+1];
            }
        }
        __syncthreads();
#pragma unroll
        for (int l = 0; l < 8; l++) {
            const int e  = tid + l*256;
            const int d  = e >> 4;
            const int r4 = (e & 15) * 4;
            float4 v = make_float4(S[d*66 + r4], S[d*66 + r4 + 1],
                                   S[d*66 + r4 + 2], S[d*66 + r4 + 3]);
            const int tk = (mt*128 + mf*16 + (r4 >> 4)*32 + (r4 & 15)) & 1023;
            const int hh = nt*2 + (d >> 6);
            const int dl = d & 63;
            const size_t ob = (((size_t)b_*NHD + hh)*DHD + dl)*SSQ + tk;
            __nv_bfloat16 hx = __float2bfloat16(v.x), hy = __float2bfloat16(v.y);
            __nv_bfloat16 hz = __float2bfloat16(v.z), hw = __float2bfloat16(v.w);
            __nv_bfloat162 hA; hA.x = hx; hA.y = hy;
            __nv_bfloat162 hB; hB.x = hz; hB.y = hw;
            __nv_bfloat162 lA;
            lA.x = __float2bfloat16(v.x - __bfloat162float(hx));
            lA.y = __float2bfloat16(v.y - __bfloat162float(hy));
            __nv_bfloat162 lB;
            lB.x = __float2bfloat16(v.z - __bfloat162float(hz));
            lB.y = __float2bfloat16(v.w - __bfloat162float(hw));
            uint2 hu = make_uint2(*(uint32_t*)&hA, *(uint32_t*)&hB);
            uint2 lu = make_uint2(*(uint32_t*)&lA, *(uint32_t*)&lB);
            *(uint2*)(g_vTh + ob) = hu;
            *(uint2*)(g_vTl + ob) = lu;
        }
    }
}

// ---------------------------------------------------------------------------
// HMMA flash attention (unchanged from R9). Block = 128 queries of one (b,h);
// 8 warps x 16 rows; 16 key-chunks of 64, cp.async double-buffered.
// ---------------------------------------------------------------------------
#define QTOT      65536
#define STAGE_SZ  50176
#define ATTN_SMEM (QTOT + 2*STAGE_SZ)

__global__ __launch_bounds__(256) void attn_hmma_kernel(const float* __restrict__ mask,
                                                        float* __restrict__ out)
{
    extern __shared__ char sbuf[];
    const uint32_t smb = smem_u32(sbuf);
    const int tid = threadIdx.x;
    const int lane = tid & 31;
    const int w = tid >> 5;
    const int bh = blockIdx.y;
    const int b_ = bh / NHD;
    const int h  = bh - b_*NHD;
    const int qb = blockIdx.x * 128;

    const __nv_bfloat16* qhp = g_qh  + (size_t)bh*SSQ*DHD;
    const __nv_bfloat16* qlp = g_ql  + (size_t)bh*SSQ*DHD;
    const __half*        qtp = g_t16 + (size_t)bh*SSQ*DHD;
    const __half*        qsp = g_s16 + (size_t)bh*SSQ*DHD;
    const __nv_bfloat16* khp = g_kh  + (size_t)bh*SSQ*DHD;
    const __nv_bfloat16* klp = g_kl  + (size_t)bh*SSQ*DHD;
    const __half*        ktp = g_t16 + (size_t)bh*SSQ*DHD;
    const __half*        ksp = g_s16 + (size_t)bh*SSQ*DHD;
    const __nv_bfloat16* vhp = g_vTh + (size_t)bh*DHD*SSQ;
    const __nv_bfloat16* vlp = g_vTl + (size_t)bh*DHD*SSQ;
    const float* maskb = mask + (size_t)b_*SSQ;

    auto issue = [&](int buf, int kb0) {
        const uint32_t so = smb + QTOT + buf*STAGE_SZ;
#pragma unroll
        for (int l = 0; l < 2; l++) {
            const int flat = tid + l*256;
            const int r = flat >> 3, seg = flat & 7;
            const uint32_t swo = SWZ128((uint32_t)(r*128 + seg*16));
            const size_t srcK = (size_t)(kb0 + r)*DHD + seg*8;
            cp16(so +     0 + swo, khp + srcK);
            cp16(so +  8192 + swo, klp + srcK);
            cp16(so + 16384 + swo, ktp + srcK);
            cp16(so + 24576 + swo, ksp + srcK);
            const size_t srcV = (size_t)r*SSQ + kb0 + seg*8;
            cp16(so + 32768 + swo, vhp + srcV);
            cp16(so + 40960 + swo, vlp + srcV);
        }
        if (tid < 16) cp16(so + 49152 + tid*16, maskb + kb0 + tid*4);
    };

    issue(0, 0);
    CP_COMMIT();

    {
        const char* qsrc[4] = {(const char*)qhp, (const char*)qlp,
                               (const char*)qtp, (const char*)qsp};
#pragma unroll
        for (int l = 0; l < 16; l++) {
            const int flat = tid + l*256;
            const int t = flat >> 10;
            const int idx = flat & 1023;
            const int r = idx >> 3, seg = idx & 7;
            uint4 v = *(const uint4*)(qsrc[t] + ((size_t)(qb + r)*DHD + seg*8)*2);
            *(uint4*)(sbuf + t*16384 + SWZ128((uint32_t)(r*128 + seg*16))) = v;
        }
    }

    const int q0 = qb + w*16 + (lane >> 2);
    float rs[2];
    rs[0] = g_itn[(size_t)bh*SSQ + q0]     * g_isn[(size_t)bh*SSQ + q0]     * 0.125f;
    rs[1] = g_itn[(size_t)bh*SSQ + q0 + 8] * g_isn[(size_t)bh*SSQ + q0 + 8] * 0.125f;

    float O[8][4];
#pragma unroll
    for (int nf = 0; nf < 8; nf++)
#pragma unroll
        for (int c = 0; c < 4; c++) O[nf][c] = 0.f;
    float m0 = -1e30f, m1 = -1e30f, l0 = 0.f, l1 = 0.f;

    const int arow = w*16 + (lane & 15);
    const int asel = lane >> 4;
    const int brow = (lane & 7) + (lane >> 4)*8;
    const int bsel = (lane >> 3) & 1;

    for (int c = 0; c < 16; c++) {
        const int buf = c & 1;
        const uint32_t so = smb + QTOT + buf*STAGE_SZ;
        const char* sp = sbuf + QTOT + buf*STAGE_SZ;

        if (c + 1 < 16) { issue(buf ^ 1, (c + 1)*64); CP_COMMIT(); CP_WAIT(1); }
        else            { CP_WAIT(0); }
        __syncthreads();

        float sb[8][4], st4[8][4], ss4[8][4];
#pragma unroll
        for (int nf = 0; nf < 8; nf++)
#pragma unroll
            for (int cc = 0; cc < 4; cc++) { sb[nf][cc] = 0.f; st4[nf][cc] = 0.f; ss4[nf][cc] = 0.f; }

#pragma unroll
        for (int ks = 0; ks < 4; ks++) {
            uint32_t ah[4], al[4], at_[4], as_[4];
            const uint32_t aoff = SWZ128((uint32_t)(arow*128 + (ks*2 + asel)*16));
            LDSM4(ah,  smb         + aoff);
            LDSM4(al,  smb + 16384 + aoff);
            LDSM4(at_, smb + 32768 + aoff);
            LDSM4(as_, smb + 49152 + aoff);
#pragma unroll
            for (int g = 0; g < 4; g++) {
                const uint32_t boff = SWZ128((uint32_t)((g*16 + brow)*128 + (ks*2 + bsel)*16));
                uint32_t bh4[4], bl4[4], bt4[4], bs4[4];
                LDSM4(bh4, so +     0 + boff);
                LDSM4(bl4, so +  8192 + boff);
                LDSM4(bt4, so + 16384 + boff);
                LDSM4(bs4, so + 24576 + boff);
#pragma unroll
                for (int sub = 0; sub < 2; sub++) {
                    const int nf = 2*g + sub;
                    MMA_BF16(sb[nf],  ah,  bh4[2*sub], bh4[2*sub+1]);
                    MMA_BF16(sb[nf],  ah,  bl4[2*sub], bl4[2*sub+1]);
                    MMA_BF16(sb[nf],  al,  bh4[2*sub], bh4[2*sub+1]);
                    MMA_F16 (st4[nf], at_, bt4[2*sub], bt4[2*sub+1]);
                    MMA_F16 (ss4[nf], as_, bs4[2*sub], bs4[2*sub+1]);
                }
            }
        }

        const float* mkp = (const float*)(sp + 49152);
        float mloc0 = -1e30f, mloc1 = -1e30f;
#pragma unroll
        for (int nf = 0; nf < 8; nf++) {
            const float2 mk = *(const float2*)(mkp + nf*8 + (lane & 3)*2);
            float s0 = sb[nf][0]*st4[nf][0]*ss4[nf][0]*rs[0] + mk.x;
            float s1 = sb[nf][1]*st4[nf][1]*ss4[nf][1]*rs[0] + mk.y;
            float s2 = sb[nf][2]*st4[nf][2]*ss4[nf][2]*rs[1] + mk.x;
            float s3 = sb[nf][3]*st4[nf][3]*ss4[nf][3]*rs[1] + mk.y;
            sb[nf][0] = s0; sb[nf][1] = s1; sb[nf][2] = s2; sb[nf][3] = s3;
            mloc0 = fmaxf(mloc0, fmaxf(s0, s1));
            mloc1 = fmaxf(mloc1, fmaxf(s2, s3));
        }
        mloc0 = fmaxf(mloc0, __shfl_xor_sync(0xffffffffu, mloc0, 1));
        mloc0 = fmaxf(mloc0, __shfl_xor_sync(0xffffffffu, mloc0, 2));
        mloc1 = fmaxf(mloc1, __shfl_xor_sync(0xffffffffu, mloc1, 1));
        mloc1 = fmaxf(mloc1, __shfl_xor_sync(0xffffffffu, mloc1, 2));
        const float mn0 = fmaxf(m0, mloc0), mn1 = fmaxf(m1, mloc1);
        const float cr0 = __expf(m0 - mn0), cr1 = __expf(m1 - mn1);
        m0 = mn0; m1 = mn1;

        float rsum0 = 0.f, rsum1 = 0.f;
#pragma unroll
        for (int nf = 0; nf < 8; nf++) {
            float p0 = __expf(sb[nf][0] - mn0);
            float p1 = __expf(sb[nf][1] - mn0);
            float p2 = __expf(sb[nf][2] - mn1);
            float p3 = __expf(sb[nf][3] - mn1);
            sb[nf][0] = p0; sb[nf][1] = p1; sb[nf][2] = p2; sb[nf][3] = p3;
            rsum0 += p0 + p1; rsum1 += p2 + p3;
            O[nf][0] *= cr0; O[nf][1] *= cr0; O[nf][2] *= cr1; O[nf][3] *= cr1;
        }
        rsum0 += __shfl_xor_sync(0xffffffffu, rsum0, 1);
        rsum0 += __shfl_xor_sync(0xffffffffu, rsum0, 2);
        rsum1 += __shfl_xor_sync(0xffffffffu, rsum1, 1);
        rsum1 += __shfl_xor_sync(0xffffffffu, rsum1, 2);
        l0 = l0*cr0 + rsum0;
        l1 = l1*cr1 + rsum1;

#pragma unroll
        for (int ks = 0; ks < 4; ks++) {
            uint32_t ph[4], pl[4];
#pragma unroll
            for (int half = 0; half < 2; half++) {
                const int nf = 2*ks + half;
#pragma unroll
                for (int rr = 0; rr < 2; rr++) {
                    const float p0 = sb[nf][rr*2], p1 = sb[nf][rr*2+1];
                    __nv_bfloat16 h0 = __float2bfloat16(p0), h1 = __float2bfloat16(p1);
                    __nv_bfloat162 hv; hv.x = h0; hv.y = h1;
                    __nv_bfloat162 lv;
                    lv.x = __float2bfloat16(p0 - __bfloat162float(h0));
                    lv.y = __float2bfloat16(p1 - __bfloat162float(h1));
                    ph[half*2 + rr] = *(uint32_t*)&hv;
                    pl[half*2 + rr] = *(uint32_t*)&lv;
                }
            }
#pragma unroll
            for (int g = 0; g < 4; g++) {
                const uint32_t boff = SWZ128((uint32_t)((g*16 + brow)*128 + (ks*2 + bsel)*16));
                uint32_t vh4[4], vl4[4];
                LDSM4(vh4, so + 32768 + boff);
                LDSM4(vl4, so + 40960 + boff);
#pragma unroll
                for (int sub = 0; sub < 2; sub++) {
                    const int nf = 2*g + sub;
                    MMA_BF16(O[nf], ph, vh4[2*sub], vh4[2*sub+1]);
                    MMA_BF16(O[nf], ph, vl4[2*sub], vl4[2*sub+1]);
                    MMA_BF16(O[nf], pl, vh4[2*sub], vh4[2*sub+1]);
                }
            }
        }
        __syncthreads();
    }

    const float il0 = 1.0f / l0, il1 = 1.0f / l1;
    float* o0 = out + ((size_t)b_*SSQ + q0    )*HD + h*DHD + (lane & 3)*2;
    float* o1 = out + ((size_t)b_*SSQ + q0 + 8)*HD + h*DHD + (lane & 3)*2;
#pragma unroll
    for (int nf = 0; nf < 8; nf++) {
        *(float2*)(o0 + nf*8) = make_float2(O[nf][0]*il0, O[nf][1]*il0);
        *(float2*)(o1 + nf*8) = make_float2(O[nf][2]*il1, O[nf][3]*il1);
    }
}

// ---------------------------------------------------------------------------
extern "C" void kernel_launch(void* const* d_in, const int* in_sizes, int n_in,
                              void* d_out, int out_size)
{
    const float* hs   = (const float*)d_in[0];
    const float* te   = (const float*)d_in[1];
    const float* se   = (const float*)d_in[2];
    const float* mask = (const float*)d_in[3];
    const float* Wq = (const float*)d_in[4];  const float* bq = (const float*)d_in[5];
    const float* Wk = (const float*)d_in[6];  const float* bk = (const float*)d_in[7];
    const float* Wv = (const float*)d_in[8];  const float* bv = (const float*)d_in[9];
    const float* Wt = (const float*)d_in[10]; const float* bt = (const float*)d_in[11];
    const float* Ws = (const float*)d_in[12]; const float* bs = (const float*)d_in[13];
    float* out = (float*)d_out;

    dim3 gx((BB*SSQ*HD)/4/256, 3);
    split_x_kernel<<<gx, 256>>>(hs, te, se);
    dim3 gw((HD*HD)/4/256, 5);
    split_w_kernel<<<gw, 256>>>(Wq, Wk, Wv, Wt, Ws);

    cudaFuncSetAttribute(proj_hmma_kernel, cudaFuncAttributeMaxDynamicSharedMemorySize, PROJ_SMEM);
    dim3 gp(HD/128, (BB*SSQ)/128, 5);   // (6, 32, 5)
    proj_hmma_kernel<<<gp, 256, PROJ_SMEM>>>(bq, bk, bv, bt, bs);

    cudaFuncSetAttribute(attn_hmma_kernel, cudaFuncAttributeMaxDynamicSharedMemorySize, ATTN_SMEM);
    dim3 ga(SSQ/128, BB*NHD);           // (8, 48)
    attn_hmma_kernel<<<ga, 256, ATTN_SMEM>>>(mask, out);
}

// round 11
// speedup vs baseline: 5.2626x; 1.0036x over previous
#include <cuda_runtime.h>
#include <cuda_bf16.h>
#include <cuda_fp16.h>
#include <math.h>
#include <stdint.h>

#define HD   768
#define NHD  12
#define DHD  64
#define BB   4
#define SSQ  1024
#define EPSF 1e-6f
#define LOG2E 1.4426950408889634f

#define SWZ128(x) ((x) ^ (((x) >> 3) & 0x70))

__device__ __forceinline__ uint32_t smem_u32(const void* p) {
    uint32_t a;
    asm("{ .reg .u64 t; cvta.to.shared.u64 t, %1; cvt.u32.u64 %0, t; }" : "=r"(a) : "l"(p));
    return a;
}
__device__ __forceinline__ float ex2f(float x) {
    float r; asm("ex2.approx.f32 %0, %1;" : "=f"(r) : "f"(x)); return r;
}

#define LDSM4(r, addr) \
    asm volatile("ldmatrix.sync.aligned.m8n8.x4.shared.b16 {%0,%1,%2,%3}, [%4];" \
        : "=r"((r)[0]), "=r"((r)[1]), "=r"((r)[2]), "=r"((r)[3]) : "r"(addr))

#define MMA_BF16(d, a, b0, b1) \
    asm volatile("mma.sync.aligned.m16n8k16.row.col.f32.bf16.bf16.f32 " \
        "{%0,%1,%2,%3}, {%4,%5,%6,%7}, {%8,%9}, {%0,%1,%2,%3};" \
        : "+f"((d)[0]), "+f"((d)[1]), "+f"((d)[2]), "+f"((d)[3]) \
        : "r"((a)[0]), "r"((a)[1]), "r"((a)[2]), "r"((a)[3]), "r"(b0), "r"(b1))

#define MMA_F16(d, a, b0, b1) \
    asm volatile("mma.sync.aligned.m16n8k16.row.col.f32.f16.f16.f32 " \
        "{%0,%1,%2,%3}, {%4,%5,%6,%7}, {%8,%9}, {%0,%1,%2,%3};" \
        : "+f"((d)[0]), "+f"((d)[1]), "+f"((d)[2]), "+f"((d)[3]) \
        : "r"((a)[0]), "r"((a)[1]), "r"((a)[2]), "r"((a)[3]), "r"(b0), "r"(b1))

__device__ __forceinline__ void cp16(uint32_t d, const void* s) {
    asm volatile("cp.async.cg.shared.global [%0], [%1], 16;" :: "r"(d), "l"(s) : "memory");
}
#define CP_COMMIT() asm volatile("cp.async.commit_group;" ::: "memory")
#define CP_WAIT(n)  asm volatile("cp.async.wait_group %0;" :: "n"(n) : "memory")

// ---------------------------------------------------------------------------
// Scratch (allocation-free rule: __device__ globals)
// ---------------------------------------------------------------------------
__device__ __nv_bfloat16 g_qh [BB*NHD*SSQ*DHD];   // q hi  [bh][tok][dim]
__device__ __nv_bfloat16 g_ql [BB*NHD*SSQ*DHD];   // q lo
__device__ __nv_bfloat16 g_kh [BB*NHD*SSQ*DHD];
__device__ __nv_bfloat16 g_kl [BB*NHD*SSQ*DHD];
__device__ __half        g_t16[BB*NHD*SSQ*DHD];   // T fp16 [bh][tok][dim]
__device__ __half        g_s16[BB*NHD*SSQ*DHD];
__device__ __nv_bfloat16 g_vTh[BB*NHD*DHD*SSQ];   // V hi  [bh][dim][tok]
__device__ __nv_bfloat16 g_vTl[BB*NHD*DHD*SSQ];
__device__ float g_itn[BB*NHD*SSQ];
__device__ float g_isn[BB*NHD*SSQ];

// bf16 split-precision GEMM inputs
__device__ __nv_bfloat16 g_xh[3*BB*SSQ*HD];
__device__ __nv_bfloat16 g_xl[3*BB*SSQ*HD];
__device__ __nv_bfloat16 g_wh[5*HD*HD];
__device__ __nv_bfloat16 g_wl[5*HD*HD];

// ---------------------------------------------------------------------------
// fp32 -> bf16 hi/lo split kernels
// ---------------------------------------------------------------------------
__global__ __launch_bounds__(256) void split_x_kernel(
    const float* __restrict__ hs, const float* __restrict__ te, const float* __restrict__ se)
{
    const float* src = (blockIdx.y == 0) ? hs : (blockIdx.y == 1) ? te : se;
    const size_t off = (size_t)blockIdx.y * (size_t)(BB*SSQ*HD);
    size_t i = ((size_t)blockIdx.x * blockDim.x + threadIdx.x) * 4;
    if (i >= (size_t)(BB*SSQ*HD)) return;
    float4 x = *(const float4*)(src + i);
    __nv_bfloat16 h0 = __float2bfloat16(x.x), h1 = __float2bfloat16(x.y);
    __nv_bfloat16 h2 = __float2bfloat16(x.z), h3 = __float2bfloat16(x.w);
    __nv_bfloat162 hA; hA.x = h0; hA.y = h1;
    __nv_bfloat162 hB; hB.x = h2; hB.y = h3;
    __nv_bfloat162 lA; lA.x = __float2bfloat16(x.x - __bfloat162float(h0));
                       lA.y = __float2bfloat16(x.y - __bfloat162float(h1));
    __nv_bfloat162 lB; lB.x = __float2bfloat16(x.z - __bfloat162float(h2));
                       lB.y = __float2bfloat16(x.w - __bfloat162float(h3));
    *(__nv_bfloat162*)(g_xh + off + i)     = hA;
    *(__nv_bfloat162*)(g_xh + off + i + 2) = hB;
    *(__nv_bfloat162*)(g_xl + off + i)     = lA;
    *(__nv_bfloat162*)(g_xl + off + i + 2) = lB;
}

__global__ __launch_bounds__(256) void split_w_kernel(
    const float* __restrict__ Wq, const float* __restrict__ Wk, const float* __restrict__ Wv,
    const float* __restrict__ Wt, const float* __restrict__ Ws)
{
    const int z = blockIdx.y;
    const float* src = (z==0)?Wq:(z==1)?Wk:(z==2)?Wv:(z==3)?Wt:Ws;
    const size_t off = (size_t)z * (size_t)(HD*HD);
    size_t i = ((size_t)blockIdx.x * blockDim.x + threadIdx.x) * 4;
    if (i >= (size_t)(HD*HD)) return;
    float4 x = *(const float4*)(src + i);
    __nv_bfloat16 h0 = __float2bfloat16(x.x), h1 = __float2bfloat16(x.y);
    __nv_bfloat16 h2 = __float2bfloat16(x.z), h3 = __float2bfloat16(x.w);
    __nv_bfloat162 hA; hA.x = h0; hA.y = h1;
    __nv_bfloat162 hB; hB.x = h2; hB.y = h3;
    __nv_bfloat162 lA; lA.x = __float2bfloat16(x.x - __bfloat162float(h0));
                       lA.y = __float2bfloat16(x.y - __bfloat162float(h1));
    __nv_bfloat162 lB; lB.x = __float2bfloat16(x.z - __bfloat162float(h2));
                       lB.y = __float2bfloat16(x.w - __bfloat162float(h3));
    *(__nv_bfloat162*)(g_wh + off + i)     = hA;
    *(__nv_bfloat162*)(g_wh + off + i + 2) = hB;
    *(__nv_bfloat162*)(g_wl + off + i)     = lA;
    *(__nv_bfloat162*)(g_wl + off + i + 2) = lB;
}

// ---------------------------------------------------------------------------
// HMMA projection GEMM (split hh+hl+lh), cp.async 3-stage pipeline,
// single __syncthreads per K-chunk. Block 256 thr = 8 warps (4 x 2).
// Tile M=128 tok, N=128 out, K-chunk 64. grid = (6, 32, 5).
// ---------------------------------------------------------------------------
#define PSTAGE     65536            // 4 tiles x 16 KB
#define PROJ_SMEM  (3*PSTAGE)       // 196608

__global__ __launch_bounds__(256) void proj_hmma_kernel(
    const float* __restrict__ bq, const float* __restrict__ bk,
    const float* __restrict__ bv, const float* __restrict__ bt,
    const float* __restrict__ bs)
{
    extern __shared__ char dsm[];
    const uint32_t smb = smem_u32(dsm);

    const int tid  = threadIdx.x;
    const int lane = tid & 31;
    const int wid  = tid >> 5;
    const int wm   = wid & 3;
    const int wn   = wid >> 2;
    const int nt = blockIdx.x;
    const int mt = blockIdx.y;
    const int z  = blockIdx.z;

    const int xsel = (z <= 2) ? 0 : (z == 3) ? 1 : 2;
    const __nv_bfloat16* Xh = g_xh + (size_t)xsel * (BB*SSQ*HD);
    const __nv_bfloat16* Xl = g_xl + (size_t)xsel * (BB*SSQ*HD);
    const __nv_bfloat16* Wh = g_wh + (size_t)z * (HD*HD);
    const __nv_bfloat16* Wl = g_wl + (size_t)z * (HD*HD);
    const float* bias = (z==0)?bq:(z==1)?bk:(z==2)?bv:(z==3)?bt:bs;

    float D[2][8][4];
#pragma unroll
    for (int mf = 0; mf < 2; mf++)
#pragma unroll
        for (int nf = 0; nf < 8; nf++)
#pragma unroll
            for (int c = 0; c < 4; c++) D[mf][nf][c] = 0.f;

    const int a_row = wm*32 + (lane & 15);
    const int a_hi  = (lane >> 4);
    const int b_row = wn*64 + (lane & 7) + (lane >> 4)*8;
    const int b_hi  = (lane >> 3) & 1;

    auto issue = [&](int buf, int kb) {
        const uint32_t so = smb + buf*PSTAGE;
#pragma unroll
        for (int l = 0; l < 4; l++) {
            const int flat = tid + l*256;
            const int r   = flat >> 3;
            const int seg = flat & 7;
            const uint32_t swo = SWZ128((uint32_t)(r*128 + seg*16));
            const size_t ga = (size_t)(mt*128 + r)*HD + kb*64 + seg*8;
            const size_t gb = (size_t)(nt*128 + r)*HD + kb*64 + seg*8;
            cp16(so +     0 + swo, Xh + ga);
            cp16(so + 16384 + swo, Xl + ga);
            cp16(so + 32768 + swo, Wh + gb);
            cp16(so + 49152 + swo, Wl + gb);
        }
    };

    issue(0, 0); CP_COMMIT();
    issue(1, 1); CP_COMMIT();

    for (int kb = 0; kb < 12; kb++) {
        if (kb < 11) { CP_WAIT(1); } else { CP_WAIT(0); }
        __syncthreads();
        if (kb + 2 < 12) { issue((kb + 2) % 3, kb + 2); CP_COMMIT(); }
        const uint32_t so = smb + (kb % 3)*PSTAGE;

#pragma unroll
        for (int ks = 0; ks < 4; ks++) {
            uint32_t ah[2][4], al[2][4];
#pragma unroll
            for (int mf = 0; mf < 2; mf++) {
                const uint32_t byo = SWZ128((uint32_t)((a_row + mf*16)*128 + (ks*2 + a_hi)*16));
                LDSM4(ah[mf], so +     0 + byo);
                LDSM4(al[mf], so + 16384 + byo);
            }
#pragma unroll
            for (int g = 0; g < 4; g++) {
                uint32_t bh4[4], bl4[4];
                const uint32_t byo = SWZ128((uint32_t)((b_row + g*16)*128 + (ks*2 + b_hi)*16));
                LDSM4(bh4, so + 32768 + byo);
                LDSM4(bl4, so + 49152 + byo);
#pragma unroll
                for (int sub = 0; sub < 2; sub++) {
                    const int nf = 2*g + sub;
#pragma unroll
                    for (int mf = 0; mf < 2; mf++) {
                        MMA_BF16(D[mf][nf], ah[mf], bh4[2*sub], bh4[2*sub+1]);
                        MMA_BF16(D[mf][nf], ah[mf], bl4[2*sub], bl4[2*sub+1]);
                        MMA_BF16(D[mf][nf], al[mf], bh4[2*sub], bh4[2*sub+1]);
                    }
                }
            }
        }
    }

    // ---- epilogue ----
    const int b_ = (mt*128) >> 10;
    const int h  = nt*2 + wn;
    const size_t bh = (size_t)b_*NHD + h;

#pragma unroll
    for (int nf = 0; nf < 8; nf++) {
        const int col = nt*128 + wn*64 + nf*8 + (lane & 3)*2;
        const float b0 = bias[col], b1 = bias[col + 1];
#pragma unroll
        for (int mf = 0; mf < 2; mf++) {
            D[mf][nf][0] += b0; D[mf][nf][1] += b1;
            D[mf][nf][2] += b0; D[mf][nf][3] += b1;
        }
    }

    if (z <= 1) {
        __nv_bfloat16* gh = (z == 0) ? g_qh : g_kh;
        __nv_bfloat16* gl = (z == 0) ? g_ql : g_kl;
#pragma unroll
        for (int mf = 0; mf < 2; mf++)
#pragma unroll
            for (int half = 0; half < 2; half++) {
                const int s_ = (mt*128 + wm*32 + mf*16 + half*8 + (lane >> 2)) & 1023;
                const size_t base = (bh*SSQ + s_)*DHD + (lane & 3)*2;
#pragma unroll
                for (int nf = 0; nf < 8; nf++) {
                    const float v0 = D[mf][nf][half*2], v1 = D[mf][nf][half*2+1];
                    __nv_bfloat16 h0 = __float2bfloat16(v0), h1 = __float2bfloat16(v1);
                    __nv_bfloat162 hv; hv.x = h0; hv.y = h1;
                    __nv_bfloat162 lv;
                    lv.x = __float2bfloat16(v0 - __bfloat162float(h0));
                    lv.y = __float2bfloat16(v1 - __bfloat162float(h1));
                    *(uint32_t*)(gh + base + nf*8) = *(uint32_t*)&hv;
                    *(uint32_t*)(gl + base + nf*8) = *(uint32_t*)&lv;
                }
            }
        return;
    }

    if (z >= 3) {
        __half* gt = (z == 3) ? g_t16 : g_s16;
        float* invn = (z == 3) ? g_itn : g_isn;
#pragma unroll
        for (int mf = 0; mf < 2; mf++)
#pragma unroll
            for (int half = 0; half < 2; half++) {
                const int s_ = (mt*128 + wm*32 + mf*16 + half*8 + (lane >> 2)) & 1023;
                const size_t base = (bh*SSQ + s_)*DHD + (lane & 3)*2;
                float ss = 0.f;
#pragma unroll
                for (int nf = 0; nf < 8; nf++) {
                    const float v0 = D[mf][nf][half*2], v1 = D[mf][nf][half*2+1];
                    ss = fmaf(v0, v0, fmaf(v1, v1, ss));
                    __half2 hv = __floats2half2_rn(v0, v1);
                    *(uint32_t*)(gt + base + nf*8) = *(uint32_t*)&hv;
                }
                ss += __shfl_xor_sync(0xffffffffu, ss, 1);
                ss += __shfl_xor_sync(0xffffffffu, ss, 2);
                if ((lane & 3) == 0)
                    invn[bh*SSQ + s_] = 1.0f / (sqrtf(ss) + EPSF);
            }
        return;
    }

    // z == 2: V -> transposed bf16 hi/lo [bh][dim][tok] via smem stage
    float* S = (float*)dsm;
#pragma unroll
    for (int mf = 0; mf < 2; mf++) {
        __syncthreads();
#pragma unroll
        for (int half = 0; half < 2; half++) {
            const int rl = wm*16 + half*8 + (lane >> 2);
            const int c  = wn*64 + (lane & 3)*2;
#pragma unroll
            for (int nf = 0; nf < 8; nf++) {
                S[(c + nf*8    )*66 + rl] = D[mf][nf][half*2];
                S[(c + nf*8 + 1)*66 + rl] = D[mf][nf][half*2+1];
            }
        }
        __syncthreads();
#pragma unroll
        for (int l = 0; l < 8; l++) {
            const int e  = tid + l*256;
            const int d  = e >> 4;
            const int r4 = (e & 15) * 4;
            float4 v = make_float4(S[d*66 + r4], S[d*66 + r4 + 1],
                                   S[d*66 + r4 + 2], S[d*66 + r4 + 3]);
            const int tk = (mt*128 + mf*16 + (r4 >> 4)*32 + (r4 & 15)) & 1023;
            const int hh = nt*2 + (d >> 6);
            const int dl = d & 63;
            const size_t ob = (((size_t)b_*NHD + hh)*DHD + dl)*SSQ + tk;
            __nv_bfloat16 hx = __float2bfloat16(v.x), hy = __float2bfloat16(v.y);
            __nv_bfloat16 hz = __float2bfloat16(v.z), hw = __float2bfloat16(v.w);
            __nv_bfloat162 hA; hA.x = hx; hA.y = hy;
            __nv_bfloat162 hB; hB.x = hz; hB.y = hw;
            __nv_bfloat162 lA;
            lA.x = __float2bfloat16(v.x - __bfloat162float(hx));
            lA.y = __float2bfloat16(v.y - __bfloat162float(hy));
            __nv_bfloat162 lB;
            lB.x = __float2bfloat16(v.z - __bfloat162float(hz));
            lB.y = __float2bfloat16(v.w - __bfloat162float(hw));
            uint2 hu = make_uint2(*(uint32_t*)&hA, *(uint32_t*)&hB);
            uint2 lu = make_uint2(*(uint32_t*)&lA, *(uint32_t*)&lB);
            *(uint2*)(g_vTh + ob) = hu;
            *(uint2*)(g_vTl + ob) = lu;
        }
    }
}

// ---------------------------------------------------------------------------
// HMMA flash attention, 3-stage cp.async, single sync per chunk.
// Block = 128 queries of one (b,h); 8 warps x 16 rows; 16 key-chunks of 64.
// exp2-domain softmax; trunc-split P; conditional O-rescale.
// ---------------------------------------------------------------------------
#define QTOT      65536
#define STAGE_SZ  50176
#define ATTN_SMEM (QTOT + 3*STAGE_SZ)   // 216064

__global__ __launch_bounds__(256) void attn_hmma_kernel(const float* __restrict__ mask,
                                                        float* __restrict__ out)
{
    extern __shared__ char sbuf[];
    const uint32_t smb = smem_u32(sbuf);
    const int tid = threadIdx.x;
    const int lane = tid & 31;
    const int w = tid >> 5;
    const int bh = blockIdx.y;
    const int b_ = bh / NHD;
    const int h  = bh - b_*NHD;
    const int qb = blockIdx.x * 128;

    const __nv_bfloat16* qhp = g_qh  + (size_t)bh*SSQ*DHD;
    const __nv_bfloat16* qlp = g_ql  + (size_t)bh*SSQ*DHD;
    const __half*        qtp = g_t16 + (size_t)bh*SSQ*DHD;
    const __half*        qsp = g_s16 + (size_t)bh*SSQ*DHD;
    const __nv_bfloat16* khp = g_kh  + (size_t)bh*SSQ*DHD;
    const __nv_bfloat16* klp = g_kl  + (size_t)bh*SSQ*DHD;
    const __half*        ktp = g_t16 + (size_t)bh*SSQ*DHD;
    const __half*        ksp = g_s16 + (size_t)bh*SSQ*DHD;
    const __nv_bfloat16* vhp = g_vTh + (size_t)bh*DHD*SSQ;
    const __nv_bfloat16* vlp = g_vTl + (size_t)bh*DHD*SSQ;
    const float* maskb = mask + (size_t)b_*SSQ;

    auto issue = [&](int buf, int kb0) {
        const uint32_t so = smb + QTOT + buf*STAGE_SZ;
#pragma unroll
        for (int l = 0; l < 2; l++) {
            const int flat = tid + l*256;
            const int r = flat >> 3, seg = flat & 7;
            const uint32_t swo = SWZ128((uint32_t)(r*128 + seg*16));
            const size_t srcK = (size_t)(kb0 + r)*DHD + seg*8;
            cp16(so +     0 + swo, khp + srcK);
            cp16(so +  8192 + swo, klp + srcK);
            cp16(so + 16384 + swo, ktp + srcK);
            cp16(so + 24576 + swo, ksp + srcK);
            const size_t srcV = (size_t)r*SSQ + kb0 + seg*8;
            cp16(so + 32768 + swo, vhp + srcV);
            cp16(so + 40960 + swo, vlp + srcV);
        }
        if (tid < 16) cp16(so + 49152 + tid*16, maskb + kb0 + tid*4);
    };

    issue(0, 0);  CP_COMMIT();
    issue(1, 64); CP_COMMIT();

    {
        const char* qsrc[4] = {(const char*)qhp, (const char*)qlp,
                               (const char*)qtp, (const char*)qsp};
#pragma unroll
        for (int l = 0; l < 16; l++) {
            const int flat = tid + l*256;
            const int t = flat >> 10;
            const int idx = flat & 1023;
            const int r = idx >> 3, seg = idx & 7;
            uint4 v = *(const uint4*)(qsrc[t] + ((size_t)(qb + r)*DHD + seg*8)*2);
            *(uint4*)(sbuf + t*16384 + SWZ128((uint32_t)(r*128 + seg*16))) = v;
        }
    }

    const int q0 = qb + w*16 + (lane >> 2);
    float rs[2];   // rowscale * log2(e)  (exp2-domain logits)
    rs[0] = g_itn[(size_t)bh*SSQ + q0]     * g_isn[(size_t)bh*SSQ + q0]     * (0.125f * LOG2E);
    rs[1] = g_itn[(size_t)bh*SSQ + q0 + 8] * g_isn[(size_t)bh*SSQ + q0 + 8] * (0.125f * LOG2E);

    float O[8][4];
#pragma unroll
    for (int nf = 0; nf < 8; nf++)
#pragma unroll
        for (int c = 0; c < 4; c++) O[nf][c] = 0.f;
    float m0 = -1e30f, m1 = -1e30f, l0 = 0.f, l1 = 0.f;

    const int arow = w*16 + (lane & 15);
    const int asel = lane >> 4;
    const int brow = (lane & 7) + (lane >> 4)*8;
    const int bsel = (lane >> 3) & 1;

    for (int c = 0; c < 16; c++) {
        if (c < 15) { CP_WAIT(1); } else { CP_WAIT(0); }
        __syncthreads();
        if (c + 2 < 16) { issue((c + 2) % 3, (c + 2)*64); CP_COMMIT(); }

        const uint32_t so = smb + QTOT + (c % 3)*STAGE_SZ;
        const char* sp = sbuf + QTOT + (c % 3)*STAGE_SZ;

        float sb[8][4], st4[8][4], ss4[8][4];
#pragma unroll
        for (int nf = 0; nf < 8; nf++)
#pragma unroll
            for (int cc = 0; cc < 4; cc++) { sb[nf][cc] = 0.f; st4[nf][cc] = 0.f; ss4[nf][cc] = 0.f; }

#pragma unroll
        for (int ks = 0; ks < 4; ks++) {
            uint32_t ah[4], al[4], at_[4], as_[4];
            const uint32_t aoff = SWZ128((uint32_t)(arow*128 + (ks*2 + asel)*16));
            LDSM4(ah,  smb         + aoff);
            LDSM4(al,  smb + 16384 + aoff);
            LDSM4(at_, smb + 32768 + aoff);
            LDSM4(as_, smb + 49152 + aoff);
#pragma unroll
            for (int g = 0; g < 4; g++) {
                const uint32_t boff = SWZ128((uint32_t)((g*16 + brow)*128 + (ks*2 + bsel)*16));
                uint32_t bh4[4], bl4[4], bt4[4], bs4[4];
                LDSM4(bh4, so +     0 + boff);
                LDSM4(bl4, so +  8192 + boff);
                LDSM4(bt4, so + 16384 + boff);
                LDSM4(bs4, so + 24576 + boff);
#pragma unroll
                for (int sub = 0; sub < 2; sub++) {
                    const int nf = 2*g + sub;
                    MMA_BF16(sb[nf],  ah,  bh4[2*sub], bh4[2*sub+1]);
                    MMA_BF16(sb[nf],  ah,  bl4[2*sub], bl4[2*sub+1]);
                    MMA_BF16(sb[nf],  al,  bh4[2*sub], bh4[2*sub+1]);
                    MMA_F16 (st4[nf], at_, bt4[2*sub], bt4[2*sub+1]);
                    MMA_F16 (ss4[nf], as_, bs4[2*sub], bs4[2*sub+1]);
                }
            }
        }

        // ---- combine (exp2 domain) + online softmax ----
        const float* mkp = (const float*)(sp + 49152);
        float mloc0 = -1e30f, mloc1 = -1e30f;
#pragma unroll
        for (int nf = 0; nf < 8; nf++) {
            const float2 mk = *(const float2*)(mkp + nf*8 + (lane & 3)*2);
            const float mk2x = mk.x * LOG2E, mk2y = mk.y * LOG2E;
            float s0 = fmaf(sb[nf][0]*st4[nf][0]*ss4[nf][0], rs[0], mk2x);
            float s1 = fmaf(sb[nf][1]*st4[nf][1]*ss4[nf][1], rs[0], mk2y);
            float s2 = fmaf(sb[nf][2]*st4[nf][2]*ss4[nf][2], rs[1], mk2x);
            float s3 = fmaf(sb[nf][3]*st4[nf][3]*ss4[nf][3], rs[1], mk2y);
            sb[nf][0] = s0; sb[nf][1] = s1; sb[nf][2] = s2; sb[nf][3] = s3;
            mloc0 = fmaxf(mloc0, fmaxf(s0, s1));
            mloc1 = fmaxf(mloc1, fmaxf(s2, s3));
        }
        mloc0 = fmaxf(mloc0, __shfl_xor_sync(0xffffffffu, mloc0, 1));
        mloc0 = fmaxf(mloc0, __shfl_xor_sync(0xffffffffu, mloc0, 2));
        mloc1 = fmaxf(mloc1, __shfl_xor_sync(0xffffffffu, mloc1, 1));
        mloc1 = fmaxf(mloc1, __shfl_xor_sync(0xffffffffu, mloc1, 2));
        const float mn0 = fmaxf(m0, mloc0), mn1 = fmaxf(m1, mloc1);
        const float cr0 = ex2f(m0 - mn0), cr1 = ex2f(m1 - mn1);
        const unsigned same = __all_sync(0xffffffffu, (mn0 == m0) & (mn1 == m1));
        m0 = mn0; m1 = mn1;

        float rsum0 = 0.f, rsum1 = 0.f;
#pragma unroll
        for (int nf = 0; nf < 8; nf++) {
            float p0 = ex2f(sb[nf][0] - mn0);
            float p1 = ex2f(sb[nf][1] - mn0);
            float p2 = ex2f(sb[nf][2] - mn1);
            float p3 = ex2f(sb[nf][3] - mn1);
            sb[nf][0] = p0; sb[nf][1] = p1; sb[nf][2] = p2; sb[nf][3] = p3;
            rsum0 += p0 + p1; rsum1 += p2 + p3;
        }
        if (!same) {
#pragma unroll
            for (int nf = 0; nf < 8; nf++) {
                O[nf][0] *= cr0; O[nf][1] *= cr0; O[nf][2] *= cr1; O[nf][3] *= cr1;
            }
        }
        rsum0 += __shfl_xor_sync(0xffffffffu, rsum0, 1);
        rsum0 += __shfl_xor_sync(0xffffffffu, rsum0, 2);
        rsum1 += __shfl_xor_sync(0xffffffffu, rsum1, 1);
        rsum1 += __shfl_xor_sync(0xffffffffu, rsum1, 2);
        l0 = l0*cr0 + rsum0;
        l1 = l1*cr1 + rsum1;

        // ---- P @ V : trunc-split P in registers ----
#pragma unroll
        for (int ks = 0; ks < 4; ks++) {
            uint32_t ph[4], pl[4];
#pragma unroll
            for (int half = 0; half < 2; half++) {
                const int nf = 2*ks + half;
#pragma unroll
                for (int rr = 0; rr < 2; rr++) {
                    const float p0 = sb[nf][rr*2], p1 = sb[nf][rr*2+1];
                    uint32_t phv;
                    asm("cvt.rz.bf16x2.f32 %0, %1, %2;" : "=r"(phv) : "f"(p1), "f"(p0));
                    const float h0 = __int_as_float(__float_as_int(p0) & 0xffff0000u);
                    const float h1 = __int_as_float(__float_as_int(p1) & 0xffff0000u);
                    uint32_t plv;
                    asm("cvt.rn.bf16x2.f32 %0, %1, %2;" : "=r"(plv) : "f"(p1 - h1), "f"(p0 - h0));
                    ph[half*2 + rr] = phv;
                    pl[half*2 + rr] = plv;
                }
            }
#pragma unroll
            for (int g = 0; g < 4; g++) {
                const uint32_t boff = SWZ128((uint32_t)((g*16 + brow)*128 + (ks*2 + bsel)*16));
                uint32_t vh4[4], vl4[4];
                LDSM4(vh4, so + 32768 + boff);
                LDSM4(vl4, so + 40960 + boff);
#pragma unroll
                for (int sub = 0; sub < 2; sub++) {
                    const int nf = 2*g + sub;
                    MMA_BF16(O[nf], ph, vh4[2*sub], vh4[2*sub+1]);
                    MMA_BF16(O[nf], ph, vl4[2*sub], vl4[2*sub+1]);
                    MMA_BF16(O[nf], pl, vh4[2*sub], vh4[2*sub+1]);
                }
            }
        }
    }

    const float il0 = 1.0f / l0, il1 = 1.0f / l1;
    float* o0 = out + ((size_t)b_*SSQ + q0    )*HD + h*DHD + (lane & 3)*2;
    float* o1 = out + ((size_t)b_*SSQ + q0 + 8)*HD + h*DHD + (lane & 3)*2;
#pragma unroll
    for (int nf = 0; nf < 8; nf++) {
        *(float2*)(o0 + nf*8) = make_float2(O[nf][0]*il0, O[nf][1]*il0);
        *(float2*)(o1 + nf*8) = make_float2(O[nf][2]*il1, O[nf][3]*il1);
    }
}

// ---------------------------------------------------------------------------
extern "C" void kernel_launch(void* const* d_in, const int* in_sizes, int n_in,
                              void* d_out, int out_size)
{
    const float* hs   = (const float*)d_in[0];
    const float* te   = (const float*)d_in[1];
    const float* se   = (const float*)d_in[2];
    const float* mask = (const float*)d_in[3];
    const float* Wq = (const float*)d_in[4];  const float* bq = (const float*)d_in[5];
    const float* Wk = (const float*)d_in[6];  const float* bk = (const float*)d_in[7];
    const float* Wv = (const float*)d_in[8];  const float* bv = (const float*)d_in[9];
    const float* Wt = (const float*)d_in[10]; const float* bt = (const float*)d_in[11];
    const float* Ws = (const float*)d_in[12]; const float* bs = (const float*)d_in[13];
    float* out = (float*)d_out;

    dim3 gx((BB*SSQ*HD)/4/256, 3);
    split_x_kernel<<<gx, 256>>>(hs, te, se);
    dim3 gw((HD*HD)/4/256, 5);
    split_w_kernel<<<gw, 256>>>(Wq, Wk, Wv, Wt, Ws);

    cudaFuncSetAttribute(proj_hmma_kernel, cudaFuncAttributeMaxDynamicSharedMemorySize, PROJ_SMEM);
    dim3 gp(HD/128, (BB*SSQ)/128, 5);   // (6, 32, 5)
    proj_hmma_kernel<<<gp, 256, PROJ_SMEM>>>(bq, bk, bv, bt, bs);

    cudaFuncSetAttribute(attn_hmma_kernel, cudaFuncAttributeMaxDynamicSharedMemorySize, ATTN_SMEM);
    dim3 ga(SSQ/128, BB*NHD);           // (8, 48)
    attn_hmma_kernel<<<ga, 256, ATTN_SMEM>>>(mask, out);
}

// round 12
// speedup vs baseline: 5.4132x; 1.0286x over previous
#include <cuda_runtime.h>
#include <cuda_bf16.h>
#include <cuda_fp16.h>
#include <math.h>
#include <stdint.h>

#define HD   768
#define NHD  12
#define DHD  64
#define BB   4
#define SSQ  1024
#define EPSF 1e-6f
#define LOG2E 1.4426950408889634f

#define SWZ128(x) ((x) ^ (((x) >> 3) & 0x70))

__device__ __forceinline__ uint32_t smem_u32(const void* p) {
    uint32_t a;
    asm("{ .reg .u64 t; cvta.to.shared.u64 t, %1; cvt.u32.u64 %0, t; }" : "=r"(a) : "l"(p));
    return a;
}
__device__ __forceinline__ float ex2f(float x) {
    float r; asm("ex2.approx.f32 %0, %1;" : "=f"(r) : "f"(x)); return r;
}

#define LDSM4(r, addr) \
    asm volatile("ldmatrix.sync.aligned.m8n8.x4.shared.b16 {%0,%1,%2,%3}, [%4];" \
        : "=r"((r)[0]), "=r"((r)[1]), "=r"((r)[2]), "=r"((r)[3]) : "r"(addr))

#define MMA_BF16(d, a, b0, b1) \
    asm volatile("mma.sync.aligned.m16n8k16.row.col.f32.bf16.bf16.f32 " \
        "{%0,%1,%2,%3}, {%4,%5,%6,%7}, {%8,%9}, {%0,%1,%2,%3};" \
        : "+f"((d)[0]), "+f"((d)[1]), "+f"((d)[2]), "+f"((d)[3]) \
        : "r"((a)[0]), "r"((a)[1]), "r"((a)[2]), "r"((a)[3]), "r"(b0), "r"(b1))

#define MMA_F16(d, a, b0, b1) \
    asm volatile("mma.sync.aligned.m16n8k16.row.col.f32.f16.f16.f32 " \
        "{%0,%1,%2,%3}, {%4,%5,%6,%7}, {%8,%9}, {%0,%1,%2,%3};" \
        : "+f"((d)[0]), "+f"((d)[1]), "+f"((d)[2]), "+f"((d)[3]) \
        : "r"((a)[0]), "r"((a)[1]), "r"((a)[2]), "r"((a)[3]), "r"(b0), "r"(b1))

__device__ __forceinline__ void cp16(uint32_t d, const void* s) {
    asm volatile("cp.async.cg.shared.global [%0], [%1], 16;" :: "r"(d), "l"(s) : "memory");
}
#define CP_COMMIT() asm volatile("cp.async.commit_group;" ::: "memory")
#define CP_WAIT(n)  asm volatile("cp.async.wait_group %0;" :: "n"(n) : "memory")

// ---------------------------------------------------------------------------
// Scratch (allocation-free rule: __device__ globals)
// ---------------------------------------------------------------------------
__device__ __nv_bfloat16 g_qh [BB*NHD*SSQ*DHD];   // q hi  [bh][tok][dim]
__device__ __nv_bfloat16 g_ql [BB*NHD*SSQ*DHD];   // q lo
__device__ __nv_bfloat16 g_kh [BB*NHD*SSQ*DHD];
__device__ __nv_bfloat16 g_kl [BB*NHD*SSQ*DHD];
__device__ __half        g_t16[BB*NHD*SSQ*DHD];   // T fp16 [bh][tok][dim]
__device__ __half        g_s16[BB*NHD*SSQ*DHD];
__device__ __nv_bfloat16 g_vTh[BB*NHD*DHD*SSQ];   // V hi  [bh][dim][tok]
__device__ __nv_bfloat16 g_vTl[BB*NHD*DHD*SSQ];
__device__ float g_itn[BB*NHD*SSQ];
__device__ float g_isn[BB*NHD*SSQ];

// bf16 split-precision GEMM inputs
__device__ __nv_bfloat16 g_xh[3*BB*SSQ*HD];
__device__ __nv_bfloat16 g_xl[3*BB*SSQ*HD];
__device__ __nv_bfloat16 g_wh[5*HD*HD];
__device__ __nv_bfloat16 g_wl[5*HD*HD];

// ---------------------------------------------------------------------------
// fp32 -> bf16 hi/lo split kernels
// ---------------------------------------------------------------------------
__global__ __launch_bounds__(256) void split_x_kernel(
    const float* __restrict__ hs, const float* __restrict__ te, const float* __restrict__ se)
{
    const float* src = (blockIdx.y == 0) ? hs : (blockIdx.y == 1) ? te : se;
    const size_t off = (size_t)blockIdx.y * (size_t)(BB*SSQ*HD);
    size_t i = ((size_t)blockIdx.x * blockDim.x + threadIdx.x) * 4;
    if (i >= (size_t)(BB*SSQ*HD)) return;
    float4 x = *(const float4*)(src + i);
    __nv_bfloat16 h0 = __float2bfloat16(x.x), h1 = __float2bfloat16(x.y);
    __nv_bfloat16 h2 = __float2bfloat16(x.z), h3 = __float2bfloat16(x.w);
    __nv_bfloat162 hA; hA.x = h0; hA.y = h1;
    __nv_bfloat162 hB; hB.x = h2; hB.y = h3;
    __nv_bfloat162 lA; lA.x = __float2bfloat16(x.x - __bfloat162float(h0));
                       lA.y = __float2bfloat16(x.y - __bfloat162float(h1));
    __nv_bfloat162 lB; lB.x = __float2bfloat16(x.z - __bfloat162float(h2));
                       lB.y = __float2bfloat16(x.w - __bfloat162float(h3));
    *(__nv_bfloat162*)(g_xh + off + i)     = hA;
    *(__nv_bfloat162*)(g_xh + off + i + 2) = hB;
    *(__nv_bfloat162*)(g_xl + off + i)     = lA;
    *(__nv_bfloat162*)(g_xl + off + i + 2) = lB;
}

__global__ __launch_bounds__(256) void split_w_kernel(
    const float* __restrict__ Wq, const float* __restrict__ Wk, const float* __restrict__ Wv,
    const float* __restrict__ Wt, const float* __restrict__ Ws)
{
    const int z = blockIdx.y;
    const float* src = (z==0)?Wq:(z==1)?Wk:(z==2)?Wv:(z==3)?Wt:Ws;
    const size_t off = (size_t)z * (size_t)(HD*HD);
    size_t i = ((size_t)blockIdx.x * blockDim.x + threadIdx.x) * 4;
    if (i >= (size_t)(HD*HD)) return;
    float4 x = *(const float4*)(src + i);
    __nv_bfloat16 h0 = __float2bfloat16(x.x), h1 = __float2bfloat16(x.y);
    __nv_bfloat16 h2 = __float2bfloat16(x.z), h3 = __float2bfloat16(x.w);
    __nv_bfloat162 hA; hA.x = h0; hA.y = h1;
    __nv_bfloat162 hB; hB.x = h2; hB.y = h3;
    __nv_bfloat162 lA; lA.x = __float2bfloat16(x.x - __bfloat162float(h0));
                       lA.y = __float2bfloat16(x.y - __bfloat162float(h1));
    __nv_bfloat162 lB; lB.x = __float2bfloat16(x.z - __bfloat162float(h2));
                       lB.y = __float2bfloat16(x.w - __bfloat162float(h3));
    *(__nv_bfloat162*)(g_wh + off + i)     = hA;
    *(__nv_bfloat162*)(g_wh + off + i + 2) = hB;
    *(__nv_bfloat162*)(g_wl + off + i)     = lA;
    *(__nv_bfloat162*)(g_wl + off + i + 2) = lB;
}

// ---------------------------------------------------------------------------
// HMMA projection GEMM (split hh+hl+lh), cp.async 3-stage pipeline,
// single __syncthreads per K-chunk. Block 256 thr = 8 warps (4 x 2).
// Tile M=128 tok, N=128 out, K-chunk 64. grid = (6, 32, 5).  (unchanged)
// ---------------------------------------------------------------------------
#define PSTAGE     65536
#define PROJ_SMEM  (3*PSTAGE)

__global__ __launch_bounds__(256) void proj_hmma_kernel(
    const float* __restrict__ bq, const float* __restrict__ bk,
    const float* __restrict__ bv, const float* __restrict__ bt,
    const float* __restrict__ bs)
{
    extern __shared__ char dsm[];
    const uint32_t smb = smem_u32(dsm);

    const int tid  = threadIdx.x;
    const int lane = tid & 31;
    const int wid  = tid >> 5;
    const int wm   = wid & 3;
    const int wn   = wid >> 2;
    const int nt = blockIdx.x;
    const int mt = blockIdx.y;
    const int z  = blockIdx.z;

    const int xsel = (z <= 2) ? 0 : (z == 3) ? 1 : 2;
    const __nv_bfloat16* Xh = g_xh + (size_t)xsel * (BB*SSQ*HD);
    const __nv_bfloat16* Xl = g_xl + (size_t)xsel * (BB*SSQ*HD);
    const __nv_bfloat16* Wh = g_wh + (size_t)z * (HD*HD);
    const __nv_bfloat16* Wl = g_wl + (size_t)z * (HD*HD);
    const float* bias = (z==0)?bq:(z==1)?bk:(z==2)?bv:(z==3)?bt:bs;

    float D[2][8][4];
#pragma unroll
    for (int mf = 0; mf < 2; mf++)
#pragma unroll
        for (int nf = 0; nf < 8; nf++)
#pragma unroll
            for (int c = 0; c < 4; c++) D[mf][nf][c] = 0.f;

    const int a_row = wm*32 + (lane & 15);
    const int a_hi  = (lane >> 4);
    const int b_row = wn*64 + (lane & 7) + (lane >> 4)*8;
    const int b_hi  = (lane >> 3) & 1;

    auto issue = [&](int buf, int kb) {
        const uint32_t so = smb + buf*PSTAGE;
#pragma unroll
        for (int l = 0; l < 4; l++) {
            const int flat = tid + l*256;
            const int r   = flat >> 3;
            const int seg = flat & 7;
            const uint32_t swo = SWZ128((uint32_t)(r*128 + seg*16));
            const size_t ga = (size_t)(mt*128 + r)*HD + kb*64 + seg*8;
            const size_t gb = (size_t)(nt*128 + r)*HD + kb*64 + seg*8;
            cp16(so +     0 + swo, Xh + ga);
            cp16(so + 16384 + swo, Xl + ga);
            cp16(so + 32768 + swo, Wh + gb);
            cp16(so + 49152 + swo, Wl + gb);
        }
    };

    issue(0, 0); CP_COMMIT();
    issue(1, 1); CP_COMMIT();

    for (int kb = 0; kb < 12; kb++) {
        if (kb < 11) { CP_WAIT(1); } else { CP_WAIT(0); }
        __syncthreads();
        if (kb + 2 < 12) { issue((kb + 2) % 3, kb + 2); CP_COMMIT(); }
        const uint32_t so = smb + (kb % 3)*PSTAGE;

#pragma unroll
        for (int ks = 0; ks < 4; ks++) {
            uint32_t ah[2][4], al[2][4];
#pragma unroll
            for (int mf = 0; mf < 2; mf++) {
                const uint32_t byo = SWZ128((uint32_t)((a_row + mf*16)*128 + (ks*2 + a_hi)*16));
                LDSM4(ah[mf], so +     0 + byo);
                LDSM4(al[mf], so + 16384 + byo);
            }
#pragma unroll
            for (int g = 0; g < 4; g++) {
                uint32_t bh4[4], bl4[4];
                const uint32_t byo = SWZ128((uint32_t)((b_row + g*16)*128 + (ks*2 + b_hi)*16));
                LDSM4(bh4, so + 32768 + byo);
                LDSM4(bl4, so + 49152 + byo);
#pragma unroll
                for (int sub = 0; sub < 2; sub++) {
                    const int nf = 2*g + sub;
#pragma unroll
                    for (int mf = 0; mf < 2; mf++) {
                        MMA_BF16(D[mf][nf], ah[mf], bh4[2*sub], bh4[2*sub+1]);
                        MMA_BF16(D[mf][nf], ah[mf], bl4[2*sub], bl4[2*sub+1]);
                        MMA_BF16(D[mf][nf], al[mf], bh4[2*sub], bh4[2*sub+1]);
                    }
                }
            }
        }
    }

    // ---- epilogue ----
    const int b_ = (mt*128) >> 10;
    const int h  = nt*2 + wn;
    const size_t bh = (size_t)b_*NHD + h;

#pragma unroll
    for (int nf = 0; nf < 8; nf++) {
        const int col = nt*128 + wn*64 + nf*8 + (lane & 3)*2;
        const float b0 = bias[col], b1 = bias[col + 1];
#pragma unroll
        for (int mf = 0; mf < 2; mf++) {
            D[mf][nf][0] += b0; D[mf][nf][1] += b1;
            D[mf][nf][2] += b0; D[mf][nf][3] += b1;
        }
    }

    if (z <= 1) {
        __nv_bfloat16* gh = (z == 0) ? g_qh : g_kh;
        __nv_bfloat16* gl = (z == 0) ? g_ql : g_kl;
#pragma unroll
        for (int mf = 0; mf < 2; mf++)
#pragma unroll
            for (int half = 0; half < 2; half++) {
                const int s_ = (mt*128 + wm*32 + mf*16 + half*8 + (lane >> 2)) & 1023;
                const size_t base = (bh*SSQ + s_)*DHD + (lane & 3)*2;
#pragma unroll
                for (int nf = 0; nf < 8; nf++) {
                    const float v0 = D[mf][nf][half*2], v1 = D[mf][nf][half*2+1];
                    __nv_bfloat16 h0 = __float2bfloat16(v0), h1 = __float2bfloat16(v1);
                    __nv_bfloat162 hv; hv.x = h0; hv.y = h1;
                    __nv_bfloat162 lv;
                    lv.x = __float2bfloat16(v0 - __bfloat162float(h0));
                    lv.y = __float2bfloat16(v1 - __bfloat162float(h1));
                    *(uint32_t*)(gh + base + nf*8) = *(uint32_t*)&hv;
                    *(uint32_t*)(gl + base + nf*8) = *(uint32_t*)&lv;
                }
            }
        return;
    }

    if (z >= 3) {
        __half* gt = (z == 3) ? g_t16 : g_s16;
        float* invn = (z == 3) ? g_itn : g_isn;
#pragma unroll
        for (int mf = 0; mf < 2; mf++)
#pragma unroll
            for (int half = 0; half < 2; half++) {
                const int s_ = (mt*128 + wm*32 + mf*16 + half*8 + (lane >> 2)) & 1023;
                const size_t base = (bh*SSQ + s_)*DHD + (lane & 3)*2;
                float ss = 0.f;
#pragma unroll
                for (int nf = 0; nf < 8; nf++) {
                    const float v0 = D[mf][nf][half*2], v1 = D[mf][nf][half*2+1];
                    ss = fmaf(v0, v0, fmaf(v1, v1, ss));
                    __half2 hv = __floats2half2_rn(v0, v1);
                    *(uint32_t*)(gt + base + nf*8) = *(uint32_t*)&hv;
                }
                ss += __shfl_xor_sync(0xffffffffu, ss, 1);
                ss += __shfl_xor_sync(0xffffffffu, ss, 2);
                if ((lane & 3) == 0)
                    invn[bh*SSQ + s_] = 1.0f / (sqrtf(ss) + EPSF);
            }
        return;
    }

    // z == 2: V -> transposed bf16 hi/lo [bh][dim][tok] via smem stage
    float* S = (float*)dsm;
#pragma unroll
    for (int mf = 0; mf < 2; mf++) {
        __syncthreads();
#pragma unroll
        for (int half = 0; half < 2; half++) {
            const int rl = wm*16 + half*8 + (lane >> 2);
            const int c  = wn*64 + (lane & 3)*2;
#pragma unroll
            for (int nf = 0; nf < 8; nf++) {
                S[(c + nf*8    )*66 + rl] = D[mf][nf][half*2];
                S[(c + nf*8 + 1)*66 + rl] = D[mf][nf][half*2+1];
            }
        }
        __syncthreads();
#pragma unroll
        for (int l = 0; l < 8; l++) {
            const int e  = tid + l*256;
            const int d  = e >> 4;
            const int r4 = (e & 15) * 4;
            float4 v = make_float4(S[d*66 + r4], S[d*66 + r4 + 1],
                                   S[d*66 + r4 + 2], S[d*66 + r4 + 3]);
            const int tk = (mt*128 + mf*16 + (r4 >> 4)*32 + (r4 & 15)) & 1023;
            const int hh = nt*2 + (d >> 6);
            const int dl = d & 63;
            const size_t ob = (((size_t)b_*NHD + hh)*DHD + dl)*SSQ + tk;
            __nv_bfloat16 hx = __float2bfloat16(v.x), hy = __float2bfloat16(v.y);
            __nv_bfloat16 hz = __float2bfloat16(v.z), hw = __float2bfloat16(v.w);
            __nv_bfloat162 hA; hA.x = hx; hA.y = hy;
            __nv_bfloat162 hB; hB.x = hz; hB.y = hw;
            __nv_bfloat162 lA;
            lA.x = __float2bfloat16(v.x - __bfloat162float(hx));
            lA.y = __float2bfloat16(v.y - __bfloat162float(hy));
            __nv_bfloat162 lB;
            lB.x = __float2bfloat16(v.z - __bfloat162float(hz));
            lB.y = __float2bfloat16(v.w - __bfloat162float(hw));
            uint2 hu = make_uint2(*(uint32_t*)&hA, *(uint32_t*)&hB);
            uint2 lu = make_uint2(*(uint32_t*)&lA, *(uint32_t*)&lB);
            *(uint2*)(g_vTh + ob) = hu;
            *(uint2*)(g_vTl + ob) = lu;
        }
    }
}

// ---------------------------------------------------------------------------
// HMMA flash attention: 128 threads / 4 warps / 64 queries, 2 blocks per SM.
// qh/ql A-fragments register-resident (loaded once via transient stage);
// qt/qs tiles in smem (16 KB). 2-stage cp.async K/V pipeline.
// smem = 16384 + 2*49408 = 115200 B -> 2 blocks/SM for phase overlap.
// ---------------------------------------------------------------------------
#define AQT       16384                 // qt (8KB) + qs (8KB)
#define STAGE_SZ  49408                 // kh,kl,kt,ks,vh,vl (6x8KB) + mask 256B
#define ATTN_SMEM (AQT + 2*STAGE_SZ)    // 115200

__global__ __launch_bounds__(128, 2) void attn_hmma_kernel(const float* __restrict__ mask,
                                                           float* __restrict__ out)
{
    extern __shared__ char sbuf[];
    const uint32_t smb = smem_u32(sbuf);
    const int tid = threadIdx.x;
    const int lane = tid & 31;
    const int w = tid >> 5;             // 0..3
    const int bh = blockIdx.y;
    const int b_ = bh / NHD;
    const int h  = bh - b_*NHD;
    const int qb = blockIdx.x * 64;

    const __nv_bfloat16* qhp = g_qh  + (size_t)bh*SSQ*DHD;
    const __nv_bfloat16* qlp = g_ql  + (size_t)bh*SSQ*DHD;
    const __half*        qtp = g_t16 + (size_t)bh*SSQ*DHD;
    const __half*        qsp = g_s16 + (size_t)bh*SSQ*DHD;
    const __nv_bfloat16* khp = g_kh  + (size_t)bh*SSQ*DHD;
    const __nv_bfloat16* klp = g_kl  + (size_t)bh*SSQ*DHD;
    const __half*        ktp = g_t16 + (size_t)bh*SSQ*DHD;
    const __half*        ksp = g_s16 + (size_t)bh*SSQ*DHD;
    const __nv_bfloat16* vhp = g_vTh + (size_t)bh*DHD*SSQ;
    const __nv_bfloat16* vlp = g_vTl + (size_t)bh*DHD*SSQ;
    const float* maskb = mask + (size_t)b_*SSQ;

    const int arow = w*16 + (lane & 15);
    const int asel = lane >> 4;
    const int brow = (lane & 7) + (lane >> 4)*8;
    const int bsel = (lane >> 3) & 1;

    // ---- prologue: Q tiles. qt/qs -> permanent smem; qh/ql -> stage0, then
    //      ldmatrix'd into registers (reused for all 16 chunks). ----
#pragma unroll
    for (int l = 0; l < 4; l++) {
        const int flat = tid + l*128;        // 0..511
        const int r = flat >> 3, seg = flat & 7;
        const uint32_t swo = SWZ128((uint32_t)(r*128 + seg*16));
        const size_t src = (size_t)(qb + r)*DHD + seg*8;
        cp16(smb +     0 + swo, qtp + src);                 // qt (permanent)
        cp16(smb +  8192 + swo, qsp + src);                 // qs (permanent)
        cp16(smb + AQT +     0 + swo, qhp + src);           // qh (transient, stage0)
        cp16(smb + AQT +  8192 + swo, qlp + src);           // ql (transient, stage0)
    }
    CP_COMMIT(); CP_WAIT(0);
    __syncthreads();

    uint32_t qhf[4][4], qlf[4][4];
#pragma unroll
    for (int ks = 0; ks < 4; ks++) {
        const uint32_t aoff = SWZ128((uint32_t)(arow*128 + (ks*2 + asel)*16));
        LDSM4(qhf[ks], smb + AQT +    0 + aoff);
        LDSM4(qlf[ks], smb + AQT + 8192 + aoff);
    }
    __syncthreads();   // stage0 free for K/V reuse

    // ---- K/V stage issue ----
    auto issue = [&](int buf, int kb0) {
        const uint32_t so = smb + AQT + buf*STAGE_SZ;
#pragma unroll
        for (int l = 0; l < 4; l++) {
            const int flat = tid + l*128;
            const int r = flat >> 3, seg = flat & 7;
            const uint32_t swo = SWZ128((uint32_t)(r*128 + seg*16));
            const size_t srcK = (size_t)(kb0 + r)*DHD + seg*8;
            cp16(so +     0 + swo, khp + srcK);
            cp16(so +  8192 + swo, klp + srcK);
            cp16(so + 16384 + swo, ktp + srcK);
            cp16(so + 24576 + swo, ksp + srcK);
            const size_t srcV = (size_t)r*SSQ + kb0 + seg*8;
            cp16(so + 32768 + swo, vhp + srcV);
            cp16(so + 40960 + swo, vlp + srcV);
        }
        if (tid < 16) cp16(so + 49152 + tid*16, maskb + kb0 + tid*4);
    };

    issue(0, 0); CP_COMMIT();

    const int q0 = qb + w*16 + (lane >> 2);
    float rs[2];
    rs[0] = g_itn[(size_t)bh*SSQ + q0]     * g_isn[(size_t)bh*SSQ + q0]     * (0.125f * LOG2E);
    rs[1] = g_itn[(size_t)bh*SSQ + q0 + 8] * g_isn[(size_t)bh*SSQ + q0 + 8] * (0.125f * LOG2E);

    float O[8][4];
#pragma unroll
    for (int nf = 0; nf < 8; nf++)
#pragma unroll
        for (int c = 0; c < 4; c++) O[nf][c] = 0.f;
    float m0 = -1e30f, m1 = -1e30f, l0 = 0.f, l1 = 0.f;

    for (int c = 0; c < 16; c++) {
        const int buf = c & 1;
        const uint32_t so = smb + AQT + buf*STAGE_SZ;
        const char* sp = sbuf + AQT + buf*STAGE_SZ;

        if (c + 1 < 16) { issue(buf ^ 1, (c + 1)*64); CP_COMMIT(); CP_WAIT(1); }
        else            { CP_WAIT(0); }
        __syncthreads();

        float sb[8][4], st4[8][4], ss4[8][4];
#pragma unroll
        for (int nf = 0; nf < 8; nf++)
#pragma unroll
            for (int cc = 0; cc < 4; cc++) { sb[nf][cc] = 0.f; st4[nf][cc] = 0.f; ss4[nf][cc] = 0.f; }

#pragma unroll
        for (int ks = 0; ks < 4; ks++) {
            uint32_t at_[4], as_[4];
            const uint32_t aoff = SWZ128((uint32_t)(arow*128 + (ks*2 + asel)*16));
            LDSM4(at_, smb +    0 + aoff);
            LDSM4(as_, smb + 8192 + aoff);
#pragma unroll
            for (int g = 0; g < 4; g++) {
                const uint32_t boff = SWZ128((uint32_t)((g*16 + brow)*128 + (ks*2 + bsel)*16));
                uint32_t bh4[4], bl4[4], bt4[4], bs4[4];
                LDSM4(bh4, so +     0 + boff);
                LDSM4(bl4, so +  8192 + boff);
                LDSM4(bt4, so + 16384 + boff);
                LDSM4(bs4, so + 24576 + boff);
#pragma unroll
                for (int sub = 0; sub < 2; sub++) {
                    const int nf = 2*g + sub;
                    MMA_BF16(sb[nf],  qhf[ks], bh4[2*sub], bh4[2*sub+1]);
                    MMA_BF16(sb[nf],  qhf[ks], bl4[2*sub], bl4[2*sub+1]);
                    MMA_BF16(sb[nf],  qlf[ks], bh4[2*sub], bh4[2*sub+1]);
                    MMA_F16 (st4[nf], at_,     bt4[2*sub], bt4[2*sub+1]);
                    MMA_F16 (ss4[nf], as_,     bs4[2*sub], bs4[2*sub+1]);
                }
            }
        }

        // ---- combine (exp2 domain) + online softmax ----
        const float* mkp = (const float*)(sp + 49152);
        float mloc0 = -1e30f, mloc1 = -1e30f;
#pragma unroll
        for (int nf = 0; nf < 8; nf++) {
            const float2 mk = *(const float2*)(mkp + nf*8 + (lane & 3)*2);
            const float mk2x = mk.x * LOG2E, mk2y = mk.y * LOG2E;
            float s0 = fmaf(sb[nf][0]*st4[nf][0]*ss4[nf][0], rs[0], mk2x);
            float s1 = fmaf(sb[nf][1]*st4[nf][1]*ss4[nf][1], rs[0], mk2y);
            float s2 = fmaf(sb[nf][2]*st4[nf][2]*ss4[nf][2], rs[1], mk2x);
            float s3 = fmaf(sb[nf][3]*st4[nf][3]*ss4[nf][3], rs[1], mk2y);
            sb[nf][0] = s0; sb[nf][1] = s1; sb[nf][2] = s2; sb[nf][3] = s3;
            mloc0 = fmaxf(mloc0, fmaxf(s0, s1));
            mloc1 = fmaxf(mloc1, fmaxf(s2, s3));
        }
        mloc0 = fmaxf(mloc0, __shfl_xor_sync(0xffffffffu, mloc0, 1));
        mloc0 = fmaxf(mloc0, __shfl_xor_sync(0xffffffffu, mloc0, 2));
        mloc1 = fmaxf(mloc1, __shfl_xor_sync(0xffffffffu, mloc1, 1));
        mloc1 = fmaxf(mloc1, __shfl_xor_sync(0xffffffffu, mloc1, 2));
        const float mn0 = fmaxf(m0, mloc0), mn1 = fmaxf(m1, mloc1);
        const float cr0 = ex2f(m0 - mn0), cr1 = ex2f(m1 - mn1);
        const unsigned same = __all_sync(0xffffffffu, (mn0 == m0) & (mn1 == m1));
        m0 = mn0; m1 = mn1;

        float rsum0 = 0.f, rsum1 = 0.f;
#pragma unroll
        for (int nf = 0; nf < 8; nf++) {
            float p0 = ex2f(sb[nf][0] - mn0);
            float p1 = ex2f(sb[nf][1] - mn0);
            float p2 = ex2f(sb[nf][2] - mn1);
            float p3 = ex2f(sb[nf][3] - mn1);
            sb[nf][0] = p0; sb[nf][1] = p1; sb[nf][2] = p2; sb[nf][3] = p3;
            rsum0 += p0 + p1; rsum1 += p2 + p3;
        }
        if (!same) {
#pragma unroll
            for (int nf = 0; nf < 8; nf++) {
                O[nf][0] *= cr0; O[nf][1] *= cr0; O[nf][2] *= cr1; O[nf][3] *= cr1;
            }
        }
        rsum0 += __shfl_xor_sync(0xffffffffu, rsum0, 1);
        rsum0 += __shfl_xor_sync(0xffffffffu, rsum0, 2);
        rsum1 += __shfl_xor_sync(0xffffffffu, rsum1, 1);
        rsum1 += __shfl_xor_sync(0xffffffffu, rsum1, 2);
        l0 = l0*cr0 + rsum0;
        l1 = l1*cr1 + rsum1;

        // ---- P @ V : trunc-split P in registers ----
#pragma unroll
        for (int ks = 0; ks < 4; ks++) {
            uint32_t ph[4], pl[4];
#pragma unroll
            for (int half = 0; half < 2; half++) {
                const int nf = 2*ks + half;
#pragma unroll
                for (int rr = 0; rr < 2; rr++) {
                    const float p0 = sb[nf][rr*2], p1 = sb[nf][rr*2+1];
                    uint32_t phv;
                    asm("cvt.rz.bf16x2.f32 %0, %1, %2;" : "=r"(phv) : "f"(p1), "f"(p0));
                    const float h0 = __int_as_float(__float_as_int(p0) & 0xffff0000u);
                    const float h1 = __int_as_float(__float_as_int(p1) & 0xffff0000u);
                    uint32_t plv;
                    asm("cvt.rn.bf16x2.f32 %0, %1, %2;" : "=r"(plv) : "f"(p1 - h1), "f"(p0 - h0));
                    ph[half*2 + rr] = phv;
                    pl[half*2 + rr] = plv;
                }
            }
#pragma unroll
            for (int g = 0; g < 4; g++) {
                const uint32_t boff = SWZ128((uint32_t)((g*16 + brow)*128 + (ks*2 + bsel)*16));
                uint32_t vh4[4], vl4[4];
                LDSM4(vh4, so + 32768 + boff);
                LDSM4(vl4, so + 40960 + boff);
#pragma unroll
                for (int sub = 0; sub < 2; sub++) {
                    const int nf = 2*g + sub;
                    MMA_BF16(O[nf], ph, vh4[2*sub], vh4[2*sub+1]);
                    MMA_BF16(O[nf], ph, vl4[2*sub], vl4[2*sub+1]);
                    MMA_BF16(O[nf], pl, vh4[2*sub], vh4[2*sub+1]);
                }
            }
        }
        __syncthreads();   // all reads of this stage done before its refill
    }

    const float il0 = 1.0f / l0, il1 = 1.0f / l1;
    float* o0 = out + ((size_t)b_*SSQ + q0    )*HD + h*DHD + (lane & 3)*2;
    float* o1 = out + ((size_t)b_*SSQ + q0 + 8)*HD + h*DHD + (lane & 3)*2;
#pragma unroll
    for (int nf = 0; nf < 8; nf++) {
        *(float2*)(o0 + nf*8) = make_float2(O[nf][0]*il0, O[nf][1]*il0);
        *(float2*)(o1 + nf*8) = make_float2(O[nf][2]*il1, O[nf][3]*il1);
    }
}

// ---------------------------------------------------------------------------
extern "C" void kernel_launch(void* const* d_in, const int* in_sizes, int n_in,
                              void* d_out, int out_size)
{
    const float* hs   = (const float*)d_in[0];
    const float* te   = (const float*)d_in[1];
    const float* se   = (const float*)d_in[2];
    const float* mask = (const float*)d_in[3];
    const float* Wq = (const float*)d_in[4];  const float* bq = (const float*)d_in[5];
    const float* Wk = (const float*)d_in[6];  const float* bk = (const float*)d_in[7];
    const float* Wv = (const float*)d_in[8];  const float* bv = (const float*)d_in[9];
    const float* Wt = (const float*)d_in[10]; const float* bt = (const float*)d_in[11];
    const float* Ws = (const float*)d_in[12]; const float* bs = (const float*)d_in[13];
    float* out = (float*)d_out;

    dim3 gx((BB*SSQ*HD)/4/256, 3);
    split_x_kernel<<<gx, 256>>>(hs, te, se);
    dim3 gw((HD*HD)/4/256, 5);
    split_w_kernel<<<gw, 256>>>(Wq, Wk, Wv, Wt, Ws);

    cudaFuncSetAttribute(proj_hmma_kernel, cudaFuncAttributeMaxDynamicSharedMemorySize, PROJ_SMEM);
    dim3 gp(HD/128, (BB*SSQ)/128, 5);   // (6, 32, 5)
    proj_hmma_kernel<<<gp, 256, PROJ_SMEM>>>(bq, bk, bv, bt, bs);

    cudaFuncSetAttribute(attn_hmma_kernel, cudaFuncAttributeMaxDynamicSharedMemorySize, ATTN_SMEM);
    dim3 ga(SSQ/64, BB*NHD);            // (16, 48)
    attn_hmma_kernel<<<ga, 128, ATTN_SMEM>>>(mask, out);
}

// round 13
// speedup vs baseline: 5.8825x; 1.0867x over previous
#include <cuda_runtime.h>
#include <cuda_bf16.h>
#include <cuda_fp16.h>
#include <math.h>
#include <stdint.h>

#define HD   768
#define NHD  12
#define DHD  64
#define BB   4
#define SSQ  1024
#define EPSF 1e-6f
#define LOG2E 1.4426950408889634f

#define SWZ128(x) ((x) ^ (((x) >> 3) & 0x70))

__device__ __forceinline__ uint32_t smem_u32(const void* p) {
    uint32_t a;
    asm("{ .reg .u64 t; cvta.to.shared.u64 t, %1; cvt.u32.u64 %0, t; }" : "=r"(a) : "l"(p));
    return a;
}
__device__ __forceinline__ float ex2f(float x) {
    float r; asm("ex2.approx.f32 %0, %1;" : "=f"(r) : "f"(x)); return r;
}

#define LDSM4(r, addr) \
    asm volatile("ldmatrix.sync.aligned.m8n8.x4.shared.b16 {%0,%1,%2,%3}, [%4];" \
        : "=r"((r)[0]), "=r"((r)[1]), "=r"((r)[2]), "=r"((r)[3]) : "r"(addr))

#define MMA_BF16(d, a, b0, b1) \
    asm volatile("mma.sync.aligned.m16n8k16.row.col.f32.bf16.bf16.f32 " \
        "{%0,%1,%2,%3}, {%4,%5,%6,%7}, {%8,%9}, {%0,%1,%2,%3};" \
        : "+f"((d)[0]), "+f"((d)[1]), "+f"((d)[2]), "+f"((d)[3]) \
        : "r"((a)[0]), "r"((a)[1]), "r"((a)[2]), "r"((a)[3]), "r"(b0), "r"(b1))

#define MMA_F16(d, a, b0, b1) \
    asm volatile("mma.sync.aligned.m16n8k16.row.col.f32.f16.f16.f32 " \
        "{%0,%1,%2,%3}, {%4,%5,%6,%7}, {%8,%9}, {%0,%1,%2,%3};" \
        : "+f"((d)[0]), "+f"((d)[1]), "+f"((d)[2]), "+f"((d)[3]) \
        : "r"((a)[0]), "r"((a)[1]), "r"((a)[2]), "r"((a)[3]), "r"(b0), "r"(b1))

__device__ __forceinline__ void cp16(uint32_t d, const void* s) {
    asm volatile("cp.async.cg.shared.global [%0], [%1], 16;" :: "r"(d), "l"(s) : "memory");
}
#define CP_COMMIT() asm volatile("cp.async.commit_group;" ::: "memory")
#define CP_WAIT(n)  asm volatile("cp.async.wait_group %0;" :: "n"(n) : "memory")

// ---------------------------------------------------------------------------
// Scratch (allocation-free rule: __device__ globals)
// ---------------------------------------------------------------------------
__device__ __nv_bfloat16 g_qh [BB*NHD*SSQ*DHD];   // q hi  [bh][tok][dim]
__device__ __nv_bfloat16 g_ql [BB*NHD*SSQ*DHD];   // q lo
__device__ __nv_bfloat16 g_kh [BB*NHD*SSQ*DHD];
__device__ __nv_bfloat16 g_kl [BB*NHD*SSQ*DHD];
__device__ __half        g_t16[BB*NHD*SSQ*DHD];   // T fp16 [bh][tok][dim]
__device__ __half        g_s16[BB*NHD*SSQ*DHD];
__device__ __half        g_vT16[BB*NHD*DHD*SSQ];  // V fp16 [bh][dim][tok]
__device__ float g_itn[BB*NHD*SSQ];
__device__ float g_isn[BB*NHD*SSQ];

// bf16 split-precision GEMM inputs
__device__ __nv_bfloat16 g_xh[3*BB*SSQ*HD];
__device__ __nv_bfloat16 g_xl[3*BB*SSQ*HD];
__device__ __nv_bfloat16 g_wh[5*HD*HD];
__device__ __nv_bfloat16 g_wl[5*HD*HD];

// ---------------------------------------------------------------------------
// fp32 -> bf16 hi/lo split kernels
// ---------------------------------------------------------------------------
__global__ __launch_bounds__(256) void split_x_kernel(
    const float* __restrict__ hs, const float* __restrict__ te, const float* __restrict__ se)
{
    const float* src = (blockIdx.y == 0) ? hs : (blockIdx.y == 1) ? te : se;
    const size_t off = (size_t)blockIdx.y * (size_t)(BB*SSQ*HD);
    size_t i = ((size_t)blockIdx.x * blockDim.x + threadIdx.x) * 4;
    if (i >= (size_t)(BB*SSQ*HD)) return;
    float4 x = *(const float4*)(src + i);
    __nv_bfloat16 h0 = __float2bfloat16(x.x), h1 = __float2bfloat16(x.y);
    __nv_bfloat16 h2 = __float2bfloat16(x.z), h3 = __float2bfloat16(x.w);
    __nv_bfloat162 hA; hA.x = h0; hA.y = h1;
    __nv_bfloat162 hB; hB.x = h2; hB.y = h3;
    __nv_bfloat162 lA; lA.x = __float2bfloat16(x.x - __bfloat162float(h0));
                       lA.y = __float2bfloat16(x.y - __bfloat162float(h1));
    __nv_bfloat162 lB; lB.x = __float2bfloat16(x.z - __bfloat162float(h2));
                       lB.y = __float2bfloat16(x.w - __bfloat162float(h3));
    *(__nv_bfloat162*)(g_xh + off + i)     = hA;
    *(__nv_bfloat162*)(g_xh + off + i + 2) = hB;
    *(__nv_bfloat162*)(g_xl + off + i)     = lA;
    *(__nv_bfloat162*)(g_xl + off + i + 2) = lB;
}

__global__ __launch_bounds__(256) void split_w_kernel(
    const float* __restrict__ Wq, const float* __restrict__ Wk, const float* __restrict__ Wv,
    const float* __restrict__ Wt, const float* __restrict__ Ws)
{
    const int z = blockIdx.y;
    const float* src = (z==0)?Wq:(z==1)?Wk:(z==2)?Wv:(z==3)?Wt:Ws;
    const size_t off = (size_t)z * (size_t)(HD*HD);
    size_t i = ((size_t)blockIdx.x * blockDim.x + threadIdx.x) * 4;
    if (i >= (size_t)(HD*HD)) return;
    float4 x = *(const float4*)(src + i);
    __nv_bfloat16 h0 = __float2bfloat16(x.x), h1 = __float2bfloat16(x.y);
    __nv_bfloat16 h2 = __float2bfloat16(x.z), h3 = __float2bfloat16(x.w);
    __nv_bfloat162 hA; hA.x = h0; hA.y = h1;
    __nv_bfloat162 hB; hB.x = h2; hB.y = h3;
    __nv_bfloat162 lA; lA.x = __float2bfloat16(x.x - __bfloat162float(h0));
                       lA.y = __float2bfloat16(x.y - __bfloat162float(h1));
    __nv_bfloat162 lB; lB.x = __float2bfloat16(x.z - __bfloat162float(h2));
                       lB.y = __float2bfloat16(x.w - __bfloat162float(h3));
    *(__nv_bfloat162*)(g_wh + off + i)     = hA;
    *(__nv_bfloat162*)(g_wh + off + i + 2) = hB;
    *(__nv_bfloat162*)(g_wl + off + i)     = lA;
    *(__nv_bfloat162*)(g_wl + off + i + 2) = lB;
}

// ---------------------------------------------------------------------------
// HMMA projection GEMM (split hh+hl+lh), cp.async 3-stage pipeline,
// single __syncthreads per K-chunk. Block 256 thr = 8 warps (4 x 2).
// Tile M=128 tok, N=128 out, K-chunk 64. grid = (6, 32, 5).
// ---------------------------------------------------------------------------
#define PSTAGE     65536
#define PROJ_SMEM  (3*PSTAGE)

__global__ __launch_bounds__(256) void proj_hmma_kernel(
    const float* __restrict__ bq, const float* __restrict__ bk,
    const float* __restrict__ bv, const float* __restrict__ bt,
    const float* __restrict__ bs)
{
    extern __shared__ char dsm[];
    const uint32_t smb = smem_u32(dsm);

    const int tid  = threadIdx.x;
    const int lane = tid & 31;
    const int wid  = tid >> 5;
    const int wm   = wid & 3;
    const int wn   = wid >> 2;
    const int nt = blockIdx.x;
    const int mt = blockIdx.y;
    const int z  = blockIdx.z;

    const int xsel = (z <= 2) ? 0 : (z == 3) ? 1 : 2;
    const __nv_bfloat16* Xh = g_xh + (size_t)xsel * (BB*SSQ*HD);
    const __nv_bfloat16* Xl = g_xl + (size_t)xsel * (BB*SSQ*HD);
    const __nv_bfloat16* Wh = g_wh + (size_t)z * (HD*HD);
    const __nv_bfloat16* Wl = g_wl + (size_t)z * (HD*HD);
    const float* bias = (z==0)?bq:(z==1)?bk:(z==2)?bv:(z==3)?bt:bs;

    float D[2][8][4];
#pragma unroll
    for (int mf = 0; mf < 2; mf++)
#pragma unroll
        for (int nf = 0; nf < 8; nf++)
#pragma unroll
            for (int c = 0; c < 4; c++) D[mf][nf][c] = 0.f;

    const int a_row = wm*32 + (lane & 15);
    const int a_hi  = (lane >> 4);
    const int b_row = wn*64 + (lane & 7) + (lane >> 4)*8;
    const int b_hi  = (lane >> 3) & 1;

    auto issue = [&](int buf, int kb) {
        const uint32_t so = smb + buf*PSTAGE;
#pragma unroll
        for (int l = 0; l < 4; l++) {
            const int flat = tid + l*256;
            const int r   = flat >> 3;
            const int seg = flat & 7;
            const uint32_t swo = SWZ128((uint32_t)(r*128 + seg*16));
            const size_t ga = (size_t)(mt*128 + r)*HD + kb*64 + seg*8;
            const size_t gb = (size_t)(nt*128 + r)*HD + kb*64 + seg*8;
            cp16(so +     0 + swo, Xh + ga);
            cp16(so + 16384 + swo, Xl + ga);
            cp16(so + 32768 + swo, Wh + gb);
            cp16(so + 49152 + swo, Wl + gb);
        }
    };

    issue(0, 0); CP_COMMIT();
    issue(1, 1); CP_COMMIT();

    for (int kb = 0; kb < 12; kb++) {
        if (kb < 11) { CP_WAIT(1); } else { CP_WAIT(0); }
        __syncthreads();
        if (kb + 2 < 12) { issue((kb + 2) % 3, kb + 2); CP_COMMIT(); }
        const uint32_t so = smb + (kb % 3)*PSTAGE;

#pragma unroll
        for (int ks = 0; ks < 4; ks++) {
            uint32_t ah[2][4], al[2][4];
#pragma unroll
            for (int mf = 0; mf < 2; mf++) {
                const uint32_t byo = SWZ128((uint32_t)((a_row + mf*16)*128 + (ks*2 + a_hi)*16));
                LDSM4(ah[mf], so +     0 + byo);
                LDSM4(al[mf], so + 16384 + byo);
            }
#pragma unroll
            for (int g = 0; g < 4; g++) {
                uint32_t bh4[4], bl4[4];
                const uint32_t byo = SWZ128((uint32_t)((b_row + g*16)*128 + (ks*2 + b_hi)*16));
                LDSM4(bh4, so + 32768 + byo);
                LDSM4(bl4, so + 49152 + byo);
#pragma unroll
                for (int sub = 0; sub < 2; sub++) {
                    const int nf = 2*g + sub;
#pragma unroll
                    for (int mf = 0; mf < 2; mf++) {
                        MMA_BF16(D[mf][nf], ah[mf], bh4[2*sub], bh4[2*sub+1]);
                        MMA_BF16(D[mf][nf], ah[mf], bl4[2*sub], bl4[2*sub+1]);
                        MMA_BF16(D[mf][nf], al[mf], bh4[2*sub], bh4[2*sub+1]);
                    }
                }
            }
        }
    }

    // ---- epilogue ----
    const int b_ = (mt*128) >> 10;
    const int h  = nt*2 + wn;
    const size_t bh = (size_t)b_*NHD + h;

#pragma unroll
    for (int nf = 0; nf < 8; nf++) {
        const int col = nt*128 + wn*64 + nf*8 + (lane & 3)*2;
        const float b0 = bias[col], b1 = bias[col + 1];
#pragma unroll
        for (int mf = 0; mf < 2; mf++) {
            D[mf][nf][0] += b0; D[mf][nf][1] += b1;
            D[mf][nf][2] += b0; D[mf][nf][3] += b1;
        }
    }

    if (z <= 1) {
        __nv_bfloat16* gh = (z == 0) ? g_qh : g_kh;
        __nv_bfloat16* gl = (z == 0) ? g_ql : g_kl;
#pragma unroll
        for (int mf = 0; mf < 2; mf++)
#pragma unroll
            for (int half = 0; half < 2; half++) {
                const int s_ = (mt*128 + wm*32 + mf*16 + half*8 + (lane >> 2)) & 1023;
                const size_t base = (bh*SSQ + s_)*DHD + (lane & 3)*2;
#pragma unroll
                for (int nf = 0; nf < 8; nf++) {
                    const float v0 = D[mf][nf][half*2], v1 = D[mf][nf][half*2+1];
                    __nv_bfloat16 h0 = __float2bfloat16(v0), h1 = __float2bfloat16(v1);
                    __nv_bfloat162 hv; hv.x = h0; hv.y = h1;
                    __nv_bfloat162 lv;
                    lv.x = __float2bfloat16(v0 - __bfloat162float(h0));
                    lv.y = __float2bfloat16(v1 - __bfloat162float(h1));
                    *(uint32_t*)(gh + base + nf*8) = *(uint32_t*)&hv;
                    *(uint32_t*)(gl + base + nf*8) = *(uint32_t*)&lv;
                }
            }
        return;
    }

    if (z >= 3) {
        __half* gt = (z == 3) ? g_t16 : g_s16;
        float* invn = (z == 3) ? g_itn : g_isn;
#pragma unroll
        for (int mf = 0; mf < 2; mf++)
#pragma unroll
            for (int half = 0; half < 2; half++) {
                const int s_ = (mt*128 + wm*32 + mf*16 + half*8 + (lane >> 2)) & 1023;
                const size_t base = (bh*SSQ + s_)*DHD + (lane & 3)*2;
                float ss = 0.f;
#pragma unroll
                for (int nf = 0; nf < 8; nf++) {
                    const float v0 = D[mf][nf][half*2], v1 = D[mf][nf][half*2+1];
                    ss = fmaf(v0, v0, fmaf(v1, v1, ss));
                    __half2 hv = __floats2half2_rn(v0, v1);
                    *(uint32_t*)(gt + base + nf*8) = *(uint32_t*)&hv;
                }
                ss += __shfl_xor_sync(0xffffffffu, ss, 1);
                ss += __shfl_xor_sync(0xffffffffu, ss, 2);
                if ((lane & 3) == 0)
                    invn[bh*SSQ + s_] = 1.0f / (sqrtf(ss) + EPSF);
            }
        return;
    }

    // z == 2: V -> transposed fp16 [bh][dim][tok] via smem stage
    float* S = (float*)dsm;
#pragma unroll
    for (int mf = 0; mf < 2; mf++) {
        __syncthreads();
#pragma unroll
        for (int half = 0; half < 2; half++) {
            const int rl = wm*16 + half*8 + (lane >> 2);
            const int c  = wn*64 + (lane & 3)*2;
#pragma unroll
            for (int nf = 0; nf < 8; nf++) {
                S[(c + nf*8    )*66 + rl] = D[mf][nf][half*2];
                S[(c + nf*8 + 1)*66 + rl] = D[mf][nf][half*2+1];
            }
        }
        __syncthreads();
#pragma unroll
        for (int l = 0; l < 8; l++) {
            const int e  = tid + l*256;
            const int d  = e >> 4;
            const int r4 = (e & 15) * 4;
            float4 v = make_float4(S[d*66 + r4], S[d*66 + r4 + 1],
                                   S[d*66 + r4 + 2], S[d*66 + r4 + 3]);
            const int tk = (mt*128 + mf*16 + (r4 >> 4)*32 + (r4 & 15)) & 1023;
            const int hh = nt*2 + (d >> 6);
            const int dl = d & 63;
            const size_t ob = (((size_t)b_*NHD + hh)*DHD + dl)*SSQ + tk;
            __half2 hA = __floats2half2_rn(v.x, v.y);
            __half2 hB = __floats2half2_rn(v.z, v.w);
            uint2 hu = make_uint2(*(uint32_t*)&hA, *(uint32_t*)&hB);
            *(uint2*)(g_vT16 + ob) = hu;
        }
    }
}

// ---------------------------------------------------------------------------
// HMMA flash attention: 128 threads / 4 warps / 64 queries, 2 blocks per SM.
// qh/ql A-fragments register-resident; qt/qs tiles in smem. 2-stage cp.async.
// P@V in single fp16 (P fp16, V fp16) -> 1 MMA per (ks,g,sub).
// smem = 16384 + 2*41216 = 98816 B -> 2 blocks/SM.
// ---------------------------------------------------------------------------
#define AQT       16384                 // qt (8KB) + qs (8KB)
#define STAGE_SZ  41216                 // kh,kl,kt,ks,v16 (5x8KB) + mask 256B
#define ATTN_SMEM (AQT + 2*STAGE_SZ)    // 98816

__global__ __launch_bounds__(128, 2) void attn_hmma_kernel(const float* __restrict__ mask,
                                                           float* __restrict__ out)
{
    extern __shared__ char sbuf[];
    const uint32_t smb = smem_u32(sbuf);
    const int tid = threadIdx.x;
    const int lane = tid & 31;
    const int w = tid >> 5;
    const int bh = blockIdx.y;
    const int b_ = bh / NHD;
    const int h  = bh - b_*NHD;
    const int qb = blockIdx.x * 64;

    const __nv_bfloat16* qhp = g_qh  + (size_t)bh*SSQ*DHD;
    const __nv_bfloat16* qlp = g_ql  + (size_t)bh*SSQ*DHD;
    const __half*        qtp = g_t16 + (size_t)bh*SSQ*DHD;
    const __half*        qsp = g_s16 + (size_t)bh*SSQ*DHD;
    const __nv_bfloat16* khp = g_kh  + (size_t)bh*SSQ*DHD;
    const __nv_bfloat16* klp = g_kl  + (size_t)bh*SSQ*DHD;
    const __half*        ktp = g_t16 + (size_t)bh*SSQ*DHD;
    const __half*        ksp = g_s16 + (size_t)bh*SSQ*DHD;
    const __half*        vp  = g_vT16 + (size_t)bh*DHD*SSQ;
    const float* maskb = mask + (size_t)b_*SSQ;

    const int arow = w*16 + (lane & 15);
    const int asel = lane >> 4;
    const int brow = (lane & 7) + (lane >> 4)*8;
    const int bsel = (lane >> 3) & 1;

    // ---- prologue: qt/qs -> permanent smem; qh/ql staged then registered ----
#pragma unroll
    for (int l = 0; l < 4; l++) {
        const int flat = tid + l*128;
        const int r = flat >> 3, seg = flat & 7;
        const uint32_t swo = SWZ128((uint32_t)(r*128 + seg*16));
        const size_t src = (size_t)(qb + r)*DHD + seg*8;
        cp16(smb +     0 + swo, qtp + src);
        cp16(smb +  8192 + swo, qsp + src);
        cp16(smb + AQT +     0 + swo, qhp + src);
        cp16(smb + AQT +  8192 + swo, qlp + src);
    }
    CP_COMMIT(); CP_WAIT(0);
    __syncthreads();

    uint32_t qhf[4][4], qlf[4][4];
#pragma unroll
    for (int ks = 0; ks < 4; ks++) {
        const uint32_t aoff = SWZ128((uint32_t)(arow*128 + (ks*2 + asel)*16));
        LDSM4(qhf[ks], smb + AQT +    0 + aoff);
        LDSM4(qlf[ks], smb + AQT + 8192 + aoff);
    }
    __syncthreads();

    // ---- K/V stage issue ----
    auto issue = [&](int buf, int kb0) {
        const uint32_t so = smb + AQT + buf*STAGE_SZ;
#pragma unroll
        for (int l = 0; l < 4; l++) {
            const int flat = tid + l*128;
            const int r = flat >> 3, seg = flat & 7;
            const uint32_t swo = SWZ128((uint32_t)(r*128 + seg*16));
            const size_t srcK = (size_t)(kb0 + r)*DHD + seg*8;
            cp16(so +     0 + swo, khp + srcK);
            cp16(so +  8192 + swo, klp + srcK);
            cp16(so + 16384 + swo, ktp + srcK);
            cp16(so + 24576 + swo, ksp + srcK);
            const size_t srcV = (size_t)r*SSQ + kb0 + seg*8;
            cp16(so + 32768 + swo, vp + srcV);
        }
        if (tid < 16) cp16(so + 40960 + tid*16, maskb + kb0 + tid*4);
    };

    issue(0, 0); CP_COMMIT();

    const int q0 = qb + w*16 + (lane >> 2);
    float rs[2];
    rs[0] = g_itn[(size_t)bh*SSQ + q0]     * g_isn[(size_t)bh*SSQ + q0]     * (0.125f * LOG2E);
    rs[1] = g_itn[(size_t)bh*SSQ + q0 + 8] * g_isn[(size_t)bh*SSQ + q0 + 8] * (0.125f * LOG2E);

    float O[8][4];
#pragma unroll
    for (int nf = 0; nf < 8; nf++)
#pragma unroll
        for (int c = 0; c < 4; c++) O[nf][c] = 0.f;
    float m0 = -1e30f, m1 = -1e30f, l0 = 0.f, l1 = 0.f;

    for (int c = 0; c < 16; c++) {
        const int buf = c & 1;
        const uint32_t so = smb + AQT + buf*STAGE_SZ;
        const char* sp = sbuf + AQT + buf*STAGE_SZ;

        if (c + 1 < 16) { issue(buf ^ 1, (c + 1)*64); CP_COMMIT(); CP_WAIT(1); }
        else            { CP_WAIT(0); }
        __syncthreads();

        float sb[8][4], st4[8][4], ss4[8][4];
#pragma unroll
        for (int nf = 0; nf < 8; nf++)
#pragma unroll
            for (int cc = 0; cc < 4; cc++) { sb[nf][cc] = 0.f; st4[nf][cc] = 0.f; ss4[nf][cc] = 0.f; }

#pragma unroll
        for (int ks = 0; ks < 4; ks++) {
            uint32_t at_[4], as_[4];
            const uint32_t aoff = SWZ128((uint32_t)(arow*128 + (ks*2 + asel)*16));
            LDSM4(at_, smb +    0 + aoff);
            LDSM4(as_, smb + 8192 + aoff);
#pragma unroll
            for (int g = 0; g < 4; g++) {
                const uint32_t boff = SWZ128((uint32_t)((g*16 + brow)*128 + (ks*2 + bsel)*16));
                uint32_t bh4[4], bl4[4], bt4[4], bs4[4];
                LDSM4(bh4, so +     0 + boff);
                LDSM4(bl4, so +  8192 + boff);
                LDSM4(bt4, so + 16384 + boff);
                LDSM4(bs4, so + 24576 + boff);
#pragma unroll
                for (int sub = 0; sub < 2; sub++) {
                    const int nf = 2*g + sub;
                    MMA_BF16(sb[nf],  qhf[ks], bh4[2*sub], bh4[2*sub+1]);
                    MMA_BF16(sb[nf],  qhf[ks], bl4[2*sub], bl4[2*sub+1]);
                    MMA_BF16(sb[nf],  qlf[ks], bh4[2*sub], bh4[2*sub+1]);
                    MMA_F16 (st4[nf], at_,     bt4[2*sub], bt4[2*sub+1]);
                    MMA_F16 (ss4[nf], as_,     bs4[2*sub], bs4[2*sub+1]);
                }
            }
        }

        // ---- combine (exp2 domain) + online softmax ----
        const float* mkp = (const float*)(sp + 40960);
        float mloc0 = -1e30f, mloc1 = -1e30f;
#pragma unroll
        for (int nf = 0; nf < 8; nf++) {
            const float2 mk = *(const float2*)(mkp + nf*8 + (lane & 3)*2);
            const float mk2x = mk.x * LOG2E, mk2y = mk.y * LOG2E;
            float s0 = fmaf(sb[nf][0]*st4[nf][0]*ss4[nf][0], rs[0], mk2x);
            float s1 = fmaf(sb[nf][1]*st4[nf][1]*ss4[nf][1], rs[0], mk2y);
            float s2 = fmaf(sb[nf][2]*st4[nf][2]*ss4[nf][2], rs[1], mk2x);
            float s3 = fmaf(sb[nf][3]*st4[nf][3]*ss4[nf][3], rs[1], mk2y);
            sb[nf][0] = s0; sb[nf][1] = s1; sb[nf][2] = s2; sb[nf][3] = s3;
            mloc0 = fmaxf(mloc0, fmaxf(s0, s1));
            mloc1 = fmaxf(mloc1, fmaxf(s2, s3));
        }
        mloc0 = fmaxf(mloc0, __shfl_xor_sync(0xffffffffu, mloc0, 1));
        mloc0 = fmaxf(mloc0, __shfl_xor_sync(0xffffffffu, mloc0, 2));
        mloc1 = fmaxf(mloc1, __shfl_xor_sync(0xffffffffu, mloc1, 1));
        mloc1 = fmaxf(mloc1, __shfl_xor_sync(0xffffffffu, mloc1, 2));
        const float mn0 = fmaxf(m0, mloc0), mn1 = fmaxf(m1, mloc1);
        const float cr0 = ex2f(m0 - mn0), cr1 = ex2f(m1 - mn1);
        const unsigned same = __all_sync(0xffffffffu, (mn0 == m0) & (mn1 == m1));
        m0 = mn0; m1 = mn1;

        float rsum0 = 0.f, rsum1 = 0.f;
#pragma unroll
        for (int nf = 0; nf < 8; nf++) {
            float p0 = ex2f(sb[nf][0] - mn0);
            float p1 = ex2f(sb[nf][1] - mn0);
            float p2 = ex2f(sb[nf][2] - mn1);
            float p3 = ex2f(sb[nf][3] - mn1);
            sb[nf][0] = p0; sb[nf][1] = p1; sb[nf][2] = p2; sb[nf][3] = p3;
            rsum0 += p0 + p1; rsum1 += p2 + p3;
        }
        if (!same) {
#pragma unroll
            for (int nf = 0; nf < 8; nf++) {
                O[nf][0] *= cr0; O[nf][1] *= cr0; O[nf][2] *= cr1; O[nf][3] *= cr1;
            }
        }
        rsum0 += __shfl_xor_sync(0xffffffffu, rsum0, 1);
        rsum0 += __shfl_xor_sync(0xffffffffu, rsum0, 2);
        rsum1 += __shfl_xor_sync(0xffffffffu, rsum1, 1);
        rsum1 += __shfl_xor_sync(0xffffffffu, rsum1, 2);
        l0 = l0*cr0 + rsum0;
        l1 = l1*cr1 + rsum1;

        // ---- P @ V : P -> fp16 A-fragments, single fp16 MMA ----
#pragma unroll
        for (int ks = 0; ks < 4; ks++) {
            uint32_t pf[4];
#pragma unroll
            for (int half = 0; half < 2; half++) {
                const int nf = 2*ks + half;
#pragma unroll
                for (int rr = 0; rr < 2; rr++) {
                    __half2 hv = __floats2half2_rn(sb[nf][rr*2], sb[nf][rr*2+1]);
                    pf[half*2 + rr] = *(uint32_t*)&hv;
                }
            }
#pragma unroll
            for (int g = 0; g < 4; g++) {
                const uint32_t boff = SWZ128((uint32_t)((g*16 + brow)*128 + (ks*2 + bsel)*16));
                uint32_t v4[4];
                LDSM4(v4, so + 32768 + boff);
#pragma unroll
                for (int sub = 0; sub < 2; sub++)
                    MMA_F16(O[2*g + sub], pf, v4[2*sub], v4[2*sub+1]);
            }
        }
        __syncthreads();
    }

    const float il0 = 1.0f / l0, il1 = 1.0f / l1;
    float* o0 = out + ((size_t)b_*SSQ + q0    )*HD + h*DHD + (lane & 3)*2;
    float* o1 = out + ((size_t)b_*SSQ + q0 + 8)*HD + h*DHD + (lane & 3)*2;
#pragma unroll
    for (int nf = 0; nf < 8; nf++) {
        *(float2*)(o0 + nf*8) = make_float2(O[nf][0]*il0, O[nf][1]*il0);
        *(float2*)(o1 + nf*8) = make_float2(O[nf][2]*il1, O[nf][3]*il1);
    }
}

// ---------------------------------------------------------------------------
extern "C" void kernel_launch(void* const* d_in, const int* in_sizes, int n_in,
                              void* d_out, int out_size)
{
    const float* hs   = (const float*)d_in[0];
    const float* te   = (const float*)d_in[1];
    const float* se   = (const float*)d_in[2];
    const float* mask = (const float*)d_in[3];
    const float* Wq = (const float*)d_in[4];  const float* bq = (const float*)d_in[5];
    const float* Wk = (const float*)d_in[6];  const float* bk = (const float*)d_in[7];
    const float* Wv = (const float*)d_in[8];  const float* bv = (const float*)d_in[9];
    const float* Wt = (const float*)d_in[10]; const float* bt = (const float*)d_in[11];
    const float* Ws = (const float*)d_in[12]; const float* bs = (const float*)d_in[13];
    float* out = (float*)d_out;

    dim3 gx((BB*SSQ*HD)/4/256, 3);
    split_x_kernel<<<gx, 256>>>(hs, te, se);
    dim3 gw((HD*HD)/4/256, 5);
    split_w_kernel<<<gw, 256>>>(Wq, Wk, Wv, Wt, Ws);

    cudaFuncSetAttribute(proj_hmma_kernel, cudaFuncAttributeMaxDynamicSharedMemorySize, PROJ_SMEM);
    dim3 gp(HD/128, (BB*SSQ)/128, 5);   // (6, 32, 5)
    proj_hmma_kernel<<<gp, 256, PROJ_SMEM>>>(bq, bk, bv, bt, bs);

    cudaFuncSetAttribute(attn_hmma_kernel, cudaFuncAttributeMaxDynamicSharedMemorySize, ATTN_SMEM);
    dim3 ga(SSQ/64, BB*NHD);            // (16, 48)
    attn_hmma_kernel<<<ga, 128, ATTN_SMEM>>>(mask, out);
}

// round 14
// speedup vs baseline: 6.5116x; 1.1069x over previous
#include <cuda_runtime.h>
#include <cuda_bf16.h>
#include <cuda_fp16.h>
#include <math.h>
#include <stdint.h>

#define HD   768
#define NHD  12
#define DHD  64
#define BB   4
#define SSQ  1024
#define EPSF 1e-6f
#define LOG2E 1.4426950408889634f

#define SWZ128(x) ((x) ^ (((x) >> 3) & 0x70))

__device__ __forceinline__ uint32_t smem_u32(const void* p) {
    uint32_t a;
    asm("{ .reg .u64 t; cvta.to.shared.u64 t, %1; cvt.u32.u64 %0, t; }" : "=r"(a) : "l"(p));
    return a;
}
__device__ __forceinline__ float ex2f(float x) {
    float r; asm("ex2.approx.f32 %0, %1;" : "=f"(r) : "f"(x)); return r;
}

#define LDSM4(r, addr) \
    asm volatile("ldmatrix.sync.aligned.m8n8.x4.shared.b16 {%0,%1,%2,%3}, [%4];" \
        : "=r"((r)[0]), "=r"((r)[1]), "=r"((r)[2]), "=r"((r)[3]) : "r"(addr))

#define MMA_BF16(d, a, b0, b1) \
    asm volatile("mma.sync.aligned.m16n8k16.row.col.f32.bf16.bf16.f32 " \
        "{%0,%1,%2,%3}, {%4,%5,%6,%7}, {%8,%9}, {%0,%1,%2,%3};" \
        : "+f"((d)[0]), "+f"((d)[1]), "+f"((d)[2]), "+f"((d)[3]) \
        : "r"((a)[0]), "r"((a)[1]), "r"((a)[2]), "r"((a)[3]), "r"(b0), "r"(b1))

#define MMA_F16(d, a, b0, b1) \
    asm volatile("mma.sync.aligned.m16n8k16.row.col.f32.f16.f16.f32 " \
        "{%0,%1,%2,%3}, {%4,%5,%6,%7}, {%8,%9}, {%0,%1,%2,%3};" \
        : "+f"((d)[0]), "+f"((d)[1]), "+f"((d)[2]), "+f"((d)[3]) \
        : "r"((a)[0]), "r"((a)[1]), "r"((a)[2]), "r"((a)[3]), "r"(b0), "r"(b1))

__device__ __forceinline__ void cp16(uint32_t d, const void* s) {
    asm volatile("cp.async.cg.shared.global [%0], [%1], 16;" :: "r"(d), "l"(s) : "memory");
}
#define CP_COMMIT() asm volatile("cp.async.commit_group;" ::: "memory")
#define CP_WAIT(n)  asm volatile("cp.async.wait_group %0;" :: "n"(n) : "memory")

// ---------------------------------------------------------------------------
// Scratch (allocation-free rule: __device__ globals)
// ---------------------------------------------------------------------------
__device__ __half g_q16[BB*NHD*SSQ*DHD];   // q fp16 [bh][tok][dim]
__device__ __half g_k16[BB*NHD*SSQ*DHD];   // k fp16 [bh][tok][dim]
__device__ __half g_t16[BB*NHD*SSQ*DHD];   // T fp16 [bh][tok][dim]
__device__ __half g_s16[BB*NHD*SSQ*DHD];
__device__ __half g_vT16[BB*NHD*DHD*SSQ];  // V fp16 [bh][dim][tok]
__device__ float g_itn[BB*NHD*SSQ];
__device__ float g_isn[BB*NHD*SSQ];

// bf16 split-precision GEMM inputs
__device__ __nv_bfloat16 g_xh[3*BB*SSQ*HD];
__device__ __nv_bfloat16 g_xl[3*BB*SSQ*HD];
__device__ __nv_bfloat16 g_wh[5*HD*HD];
__device__ __nv_bfloat16 g_wl[5*HD*HD];

// ---------------------------------------------------------------------------
// fp32 -> bf16 hi/lo split kernels
// ---------------------------------------------------------------------------
__global__ __launch_bounds__(256) void split_x_kernel(
    const float* __restrict__ hs, const float* __restrict__ te, const float* __restrict__ se)
{
    const float* src = (blockIdx.y == 0) ? hs : (blockIdx.y == 1) ? te : se;
    const size_t off = (size_t)blockIdx.y * (size_t)(BB*SSQ*HD);
    size_t i = ((size_t)blockIdx.x * blockDim.x + threadIdx.x) * 4;
    if (i >= (size_t)(BB*SSQ*HD)) return;
    float4 x = *(const float4*)(src + i);
    __nv_bfloat16 h0 = __float2bfloat16(x.x), h1 = __float2bfloat16(x.y);
    __nv_bfloat16 h2 = __float2bfloat16(x.z), h3 = __float2bfloat16(x.w);
    __nv_bfloat162 hA; hA.x = h0; hA.y = h1;
    __nv_bfloat162 hB; hB.x = h2; hB.y = h3;
    __nv_bfloat162 lA; lA.x = __float2bfloat16(x.x - __bfloat162float(h0));
                       lA.y = __float2bfloat16(x.y - __bfloat162float(h1));
    __nv_bfloat162 lB; lB.x = __float2bfloat16(x.z - __bfloat162float(h2));
                       lB.y = __float2bfloat16(x.w - __bfloat162float(h3));
    *(__nv_bfloat162*)(g_xh + off + i)     = hA;
    *(__nv_bfloat162*)(g_xh + off + i + 2) = hB;
    *(__nv_bfloat162*)(g_xl + off + i)     = lA;
    *(__nv_bfloat162*)(g_xl + off + i + 2) = lB;
}

__global__ __launch_bounds__(256) void split_w_kernel(
    const float* __restrict__ Wq, const float* __restrict__ Wk, const float* __restrict__ Wv,
    const float* __restrict__ Wt, const float* __restrict__ Ws)
{
    const int z = blockIdx.y;
    const float* src = (z==0)?Wq:(z==1)?Wk:(z==2)?Wv:(z==3)?Wt:Ws;
    const size_t off = (size_t)z * (size_t)(HD*HD);
    size_t i = ((size_t)blockIdx.x * blockDim.x + threadIdx.x) * 4;
    if (i >= (size_t)(HD*HD)) return;
    float4 x = *(const float4*)(src + i);
    __nv_bfloat16 h0 = __float2bfloat16(x.x), h1 = __float2bfloat16(x.y);
    __nv_bfloat16 h2 = __float2bfloat16(x.z), h3 = __float2bfloat16(x.w);
    __nv_bfloat162 hA; hA.x = h0; hA.y = h1;
    __nv_bfloat162 hB; hB.x = h2; hB.y = h3;
    __nv_bfloat162 lA; lA.x = __float2bfloat16(x.x - __bfloat162float(h0));
                       lA.y = __float2bfloat16(x.y - __bfloat162float(h1));
    __nv_bfloat162 lB; lB.x = __float2bfloat16(x.z - __bfloat162float(h2));
                       lB.y = __float2bfloat16(x.w - __bfloat162float(h3));
    *(__nv_bfloat162*)(g_wh + off + i)     = hA;
    *(__nv_bfloat162*)(g_wh + off + i + 2) = hB;
    *(__nv_bfloat162*)(g_wl + off + i)     = lA;
    *(__nv_bfloat162*)(g_wl + off + i + 2) = lB;
}

// ---------------------------------------------------------------------------
// HMMA projection GEMM (split hh+hl+lh), cp.async 3-stage pipeline,
// single __syncthreads per K-chunk. Block 256 thr = 8 warps (4 x 2).
// Tile M=128 tok, N=128 out, K-chunk 64. grid = (6, 32, 5).
// ---------------------------------------------------------------------------
#define PSTAGE     65536
#define PROJ_SMEM  (3*PSTAGE)

__global__ __launch_bounds__(256) void proj_hmma_kernel(
    const float* __restrict__ bq, const float* __restrict__ bk,
    const float* __restrict__ bv, const float* __restrict__ bt,
    const float* __restrict__ bs)
{
    extern __shared__ char dsm[];
    const uint32_t smb = smem_u32(dsm);

    const int tid  = threadIdx.x;
    const int lane = tid & 31;
    const int wid  = tid >> 5;
    const int wm   = wid & 3;
    const int wn   = wid >> 2;
    const int nt = blockIdx.x;
    const int mt = blockIdx.y;
    const int z  = blockIdx.z;

    const int xsel = (z <= 2) ? 0 : (z == 3) ? 1 : 2;
    const __nv_bfloat16* Xh = g_xh + (size_t)xsel * (BB*SSQ*HD);
    const __nv_bfloat16* Xl = g_xl + (size_t)xsel * (BB*SSQ*HD);
    const __nv_bfloat16* Wh = g_wh + (size_t)z * (HD*HD);
    const __nv_bfloat16* Wl = g_wl + (size_t)z * (HD*HD);
    const float* bias = (z==0)?bq:(z==1)?bk:(z==2)?bv:(z==3)?bt:bs;

    float D[2][8][4];
#pragma unroll
    for (int mf = 0; mf < 2; mf++)
#pragma unroll
        for (int nf = 0; nf < 8; nf++)
#pragma unroll
            for (int c = 0; c < 4; c++) D[mf][nf][c] = 0.f;

    const int a_row = wm*32 + (lane & 15);
    const int a_hi  = (lane >> 4);
    const int b_row = wn*64 + (lane & 7) + (lane >> 4)*8;
    const int b_hi  = (lane >> 3) & 1;

    auto issue = [&](int buf, int kb) {
        const uint32_t so = smb + buf*PSTAGE;
#pragma unroll
        for (int l = 0; l < 4; l++) {
            const int flat = tid + l*256;
            const int r   = flat >> 3;
            const int seg = flat & 7;
            const uint32_t swo = SWZ128((uint32_t)(r*128 + seg*16));
            const size_t ga = (size_t)(mt*128 + r)*HD + kb*64 + seg*8;
            const size_t gb = (size_t)(nt*128 + r)*HD + kb*64 + seg*8;
            cp16(so +     0 + swo, Xh + ga);
            cp16(so + 16384 + swo, Xl + ga);
            cp16(so + 32768 + swo, Wh + gb);
            cp16(so + 49152 + swo, Wl + gb);
        }
    };

    issue(0, 0); CP_COMMIT();
    issue(1, 1); CP_COMMIT();

    for (int kb = 0; kb < 12; kb++) {
        if (kb < 11) { CP_WAIT(1); } else { CP_WAIT(0); }
        __syncthreads();
        if (kb + 2 < 12) { issue((kb + 2) % 3, kb + 2); CP_COMMIT(); }
        const uint32_t so = smb + (kb % 3)*PSTAGE;

#pragma unroll
        for (int ks = 0; ks < 4; ks++) {
            uint32_t ah[2][4], al[2][4];
#pragma unroll
            for (int mf = 0; mf < 2; mf++) {
                const uint32_t byo = SWZ128((uint32_t)((a_row + mf*16)*128 + (ks*2 + a_hi)*16));
                LDSM4(ah[mf], so +     0 + byo);
                LDSM4(al[mf], so + 16384 + byo);
            }
#pragma unroll
            for (int g = 0; g < 4; g++) {
                uint32_t bh4[4], bl4[4];
                const uint32_t byo = SWZ128((uint32_t)((b_row + g*16)*128 + (ks*2 + b_hi)*16));
                LDSM4(bh4, so + 32768 + byo);
                LDSM4(bl4, so + 49152 + byo);
#pragma unroll
                for (int sub = 0; sub < 2; sub++) {
                    const int nf = 2*g + sub;
#pragma unroll
                    for (int mf = 0; mf < 2; mf++) {
                        MMA_BF16(D[mf][nf], ah[mf], bh4[2*sub], bh4[2*sub+1]);
                        MMA_BF16(D[mf][nf], ah[mf], bl4[2*sub], bl4[2*sub+1]);
                        MMA_BF16(D[mf][nf], al[mf], bh4[2*sub], bh4[2*sub+1]);
                    }
                }
            }
        }
    }

    // ---- epilogue ----
    const int b_ = (mt*128) >> 10;
    const int h  = nt*2 + wn;
    const size_t bh = (size_t)b_*NHD + h;

#pragma unroll
    for (int nf = 0; nf < 8; nf++) {
        const int col = nt*128 + wn*64 + nf*8 + (lane & 3)*2;
        const float b0 = bias[col], b1 = bias[col + 1];
#pragma unroll
        for (int mf = 0; mf < 2; mf++) {
            D[mf][nf][0] += b0; D[mf][nf][1] += b1;
            D[mf][nf][2] += b0; D[mf][nf][3] += b1;
        }
    }

    if (z <= 1) {
        // q/k: single fp16 [bh][tok][dim]
        __half* gq = (z == 0) ? g_q16 : g_k16;
#pragma unroll
        for (int mf = 0; mf < 2; mf++)
#pragma unroll
            for (int half = 0; half < 2; half++) {
                const int s_ = (mt*128 + wm*32 + mf*16 + half*8 + (lane >> 2)) & 1023;
                const size_t base = (bh*SSQ + s_)*DHD + (lane & 3)*2;
#pragma unroll
                for (int nf = 0; nf < 8; nf++) {
                    __half2 hv = __floats2half2_rn(D[mf][nf][half*2], D[mf][nf][half*2+1]);
                    *(uint32_t*)(gq + base + nf*8) = *(uint32_t*)&hv;
                }
            }
        return;
    }

    if (z >= 3) {
        __half* gt = (z == 3) ? g_t16 : g_s16;
        float* invn = (z == 3) ? g_itn : g_isn;
#pragma unroll
        for (int mf = 0; mf < 2; mf++)
#pragma unroll
            for (int half = 0; half < 2; half++) {
                const int s_ = (mt*128 + wm*32 + mf*16 + half*8 + (lane >> 2)) & 1023;
                const size_t base = (bh*SSQ + s_)*DHD + (lane & 3)*2;
                float ss = 0.f;
#pragma unroll
                for (int nf = 0; nf < 8; nf++) {
                    const float v0 = D[mf][nf][half*2], v1 = D[mf][nf][half*2+1];
                    ss = fmaf(v0, v0, fmaf(v1, v1, ss));
                    __half2 hv = __floats2half2_rn(v0, v1);
                    *(uint32_t*)(gt + base + nf*8) = *(uint32_t*)&hv;
                }
                ss += __shfl_xor_sync(0xffffffffu, ss, 1);
                ss += __shfl_xor_sync(0xffffffffu, ss, 2);
                if ((lane & 3) == 0)
                    invn[bh*SSQ + s_] = 1.0f / (sqrtf(ss) + EPSF);
            }
        return;
    }

    // z == 2: V -> transposed fp16 [bh][dim][tok] via smem stage
    float* S = (float*)dsm;
#pragma unroll
    for (int mf = 0; mf < 2; mf++) {
        __syncthreads();
#pragma unroll
        for (int half = 0; half < 2; half++) {
            const int rl = wm*16 + half*8 + (lane >> 2);
            const int c  = wn*64 + (lane & 3)*2;
#pragma unroll
            for (int nf = 0; nf < 8; nf++) {
                S[(c + nf*8    )*66 + rl] = D[mf][nf][half*2];
                S[(c + nf*8 + 1)*66 + rl] = D[mf][nf][half*2+1];
            }
        }
        __syncthreads();
#pragma unroll
        for (int l = 0; l < 8; l++) {
            const int e  = tid + l*256;
            const int d  = e >> 4;
            const int r4 = (e & 15) * 4;
            float4 v = make_float4(S[d*66 + r4], S[d*66 + r4 + 1],
                                   S[d*66 + r4 + 2], S[d*66 + r4 + 3]);
            const int tk = (mt*128 + mf*16 + (r4 >> 4)*32 + (r4 & 15)) & 1023;
            const int hh = nt*2 + (d >> 6);
            const int dl = d & 63;
            const size_t ob = (((size_t)b_*NHD + hh)*DHD + dl)*SSQ + tk;
            __half2 hA = __floats2half2_rn(v.x, v.y);
            __half2 hB = __floats2half2_rn(v.z, v.w);
            uint2 hu = make_uint2(*(uint32_t*)&hA, *(uint32_t*)&hB);
            *(uint2*)(g_vT16 + ob) = hu;
        }
    }
}

// ---------------------------------------------------------------------------
// HMMA flash attention: 128 threads / 4 warps / 64 queries, 2 blocks per SM.
// Everything fp16 single: scores = 1 qk + 1 T + 1 S MMA; PV 1 MMA.
// q fragments register-resident; qt/qs tiles in smem. 2-stage cp.async.
// smem = 16384 + 2*33024 = 82432 B -> 2 blocks/SM.
// ---------------------------------------------------------------------------
#define AQT       16384                 // qt (8KB) + qs (8KB)
#define STAGE_SZ  33024                 // k16,t,s,v16 (4x8KB) + mask 256B
#define ATTN_SMEM (AQT + 2*STAGE_SZ)    // 82432

__global__ __launch_bounds__(128, 2) void attn_hmma_kernel(const float* __restrict__ mask,
                                                           float* __restrict__ out)
{
    extern __shared__ char sbuf[];
    const uint32_t smb = smem_u32(sbuf);
    const int tid = threadIdx.x;
    const int lane = tid & 31;
    const int w = tid >> 5;
    const int bh = blockIdx.y;
    const int b_ = bh / NHD;
    const int h  = bh - b_*NHD;
    const int qb = blockIdx.x * 64;

    const __half* q16p = g_q16 + (size_t)bh*SSQ*DHD;
    const __half* k16p = g_k16 + (size_t)bh*SSQ*DHD;
    const __half* qtp  = g_t16 + (size_t)bh*SSQ*DHD;
    const __half* qsp  = g_s16 + (size_t)bh*SSQ*DHD;
    const __half* vp   = g_vT16 + (size_t)bh*DHD*SSQ;
    const float* maskb = mask + (size_t)b_*SSQ;

    const int arow = w*16 + (lane & 15);
    const int asel = lane >> 4;
    const int brow = (lane & 7) + (lane >> 4)*8;
    const int bsel = (lane >> 3) & 1;

    // ---- prologue: qt/qs -> permanent smem; q16 staged then registered ----
#pragma unroll
    for (int l = 0; l < 4; l++) {
        const int flat = tid + l*128;
        const int r = flat >> 3, seg = flat & 7;
        const uint32_t swo = SWZ128((uint32_t)(r*128 + seg*16));
        const size_t src = (size_t)(qb + r)*DHD + seg*8;
        cp16(smb +    0 + swo, qtp + src);
        cp16(smb + 8192 + swo, qsp + src);
        cp16(smb + AQT  + swo, q16p + src);
    }
    CP_COMMIT(); CP_WAIT(0);
    __syncthreads();

    uint32_t qf[4][4];
#pragma unroll
    for (int ks = 0; ks < 4; ks++) {
        const uint32_t aoff = SWZ128((uint32_t)(arow*128 + (ks*2 + asel)*16));
        LDSM4(qf[ks], smb + AQT + aoff);
    }
    __syncthreads();

    // ---- K/V stage issue ----
    auto issue = [&](int buf, int kb0) {
        const uint32_t so = smb + AQT + buf*STAGE_SZ;
#pragma unroll
        for (int l = 0; l < 4; l++) {
            const int flat = tid + l*128;
            const int r = flat >> 3, seg = flat & 7;
            const uint32_t swo = SWZ128((uint32_t)(r*128 + seg*16));
            const size_t srcK = (size_t)(kb0 + r)*DHD + seg*8;
            cp16(so +     0 + swo, k16p + srcK);
            cp16(so +  8192 + swo, qtp + srcK);
            cp16(so + 16384 + swo, qsp + srcK);
            const size_t srcV = (size_t)r*SSQ + kb0 + seg*8;
            cp16(so + 24576 + swo, vp + srcV);
        }
        if (tid < 16) cp16(so + 32768 + tid*16, maskb + kb0 + tid*4);
    };

    issue(0, 0); CP_COMMIT();

    const int q0 = qb + w*16 + (lane >> 2);
    float rs[2];
    rs[0] = g_itn[(size_t)bh*SSQ + q0]     * g_isn[(size_t)bh*SSQ + q0]     * (0.125f * LOG2E);
    rs[1] = g_itn[(size_t)bh*SSQ + q0 + 8] * g_isn[(size_t)bh*SSQ + q0 + 8] * (0.125f * LOG2E);

    float O[8][4];
#pragma unroll
    for (int nf = 0; nf < 8; nf++)
#pragma unroll
        for (int c = 0; c < 4; c++) O[nf][c] = 0.f;
    float m0 = -1e30f, m1 = -1e30f, l0 = 0.f, l1 = 0.f;

    for (int c = 0; c < 16; c++) {
        const int buf = c & 1;
        const uint32_t so = smb + AQT + buf*STAGE_SZ;
        const char* sp = sbuf + AQT + buf*STAGE_SZ;

        if (c + 1 < 16) { issue(buf ^ 1, (c + 1)*64); CP_COMMIT(); CP_WAIT(1); }
        else            { CP_WAIT(0); }
        __syncthreads();

        float sb[8][4], st4[8][4], ss4[8][4];
#pragma unroll
        for (int nf = 0; nf < 8; nf++)
#pragma unroll
            for (int cc = 0; cc < 4; cc++) { sb[nf][cc] = 0.f; st4[nf][cc] = 0.f; ss4[nf][cc] = 0.f; }

#pragma unroll
        for (int ks = 0; ks < 4; ks++) {
            uint32_t at_[4], as_[4];
            const uint32_t aoff = SWZ128((uint32_t)(arow*128 + (ks*2 + asel)*16));
            LDSM4(at_, smb +    0 + aoff);
            LDSM4(as_, smb + 8192 + aoff);
#pragma unroll
            for (int g = 0; g < 4; g++) {
                const uint32_t boff = SWZ128((uint32_t)((g*16 + brow)*128 + (ks*2 + bsel)*16));
                uint32_t k4[4], bt4[4], bs4[4];
                LDSM4(k4,  so +     0 + boff);
                LDSM4(bt4, so +  8192 + boff);
                LDSM4(bs4, so + 16384 + boff);
#pragma unroll
                for (int sub = 0; sub < 2; sub++) {
                    const int nf = 2*g + sub;
                    MMA_F16(sb[nf],  qf[ks], k4[2*sub],  k4[2*sub+1]);
                    MMA_F16(st4[nf], at_,    bt4[2*sub], bt4[2*sub+1]);
                    MMA_F16(ss4[nf], as_,    bs4[2*sub], bs4[2*sub+1]);
                }
            }
        }

        // ---- combine (exp2 domain) + online softmax ----
        const float* mkp = (const float*)(sp + 32768);
        float mloc0 = -1e30f, mloc1 = -1e30f;
#pragma unroll
        for (int nf = 0; nf < 8; nf++) {
            const float2 mk = *(const float2*)(mkp + nf*8 + (lane & 3)*2);
            const float mk2x = mk.x * LOG2E, mk2y = mk.y * LOG2E;
            float s0 = fmaf(sb[nf][0]*st4[nf][0]*ss4[nf][0], rs[0], mk2x);
            float s1 = fmaf(sb[nf][1]*st4[nf][1]*ss4[nf][1], rs[0], mk2y);
            float s2 = fmaf(sb[nf][2]*st4[nf][2]*ss4[nf][2], rs[1], mk2x);
            float s3 = fmaf(sb[nf][3]*st4[nf][3]*ss4[nf][3], rs[1], mk2y);
            sb[nf][0] = s0; sb[nf][1] = s1; sb[nf][2] = s2; sb[nf][3] = s3;
            mloc0 = fmaxf(mloc0, fmaxf(s0, s1));
            mloc1 = fmaxf(mloc1, fmaxf(s2, s3));
        }
        mloc0 = fmaxf(mloc0, __shfl_xor_sync(0xffffffffu, mloc0, 1));
        mloc0 = fmaxf(mloc0, __shfl_xor_sync(0xffffffffu, mloc0, 2));
        mloc1 = fmaxf(mloc1, __shfl_xor_sync(0xffffffffu, mloc1, 1));
        mloc1 = fmaxf(mloc1, __shfl_xor_sync(0xffffffffu, mloc1, 2));
        const float mn0 = fmaxf(m0, mloc0), mn1 = fmaxf(m1, mloc1);
        const float cr0 = ex2f(m0 - mn0), cr1 = ex2f(m1 - mn1);
        const unsigned same = __all_sync(0xffffffffu, (mn0 == m0) & (mn1 == m1));
        m0 = mn0; m1 = mn1;

        float rsum0 = 0.f, rsum1 = 0.f;
#pragma unroll
        for (int nf = 0; nf < 8; nf++) {
            float p0 = ex2f(sb[nf][0] - mn0);
            float p1 = ex2f(sb[nf][1] - mn0);
            float p2 = ex2f(sb[nf][2] - mn1);
            float p3 = ex2f(sb[nf][3] - mn1);
            sb[nf][0] = p0; sb[nf][1] = p1; sb[nf][2] = p2; sb[nf][3] = p3;
            rsum0 += p0 + p1; rsum1 += p2 + p3;
        }
        if (!same) {
#pragma unroll
            for (int nf = 0; nf < 8; nf++) {
                O[nf][0] *= cr0; O[nf][1] *= cr0; O[nf][2] *= cr1; O[nf][3] *= cr1;
            }
        }
        rsum0 += __shfl_xor_sync(0xffffffffu, rsum0, 1);
        rsum0 += __shfl_xor_sync(0xffffffffu, rsum0, 2);
        rsum1 += __shfl_xor_sync(0xffffffffu, rsum1, 1);
        rsum1 += __shfl_xor_sync(0xffffffffu, rsum1, 2);
        l0 = l0*cr0 + rsum0;
        l1 = l1*cr1 + rsum1;

        // ---- P @ V : P -> fp16 A-fragments, single fp16 MMA ----
#pragma unroll
        for (int ks = 0; ks < 4; ks++) {
            uint32_t pf[4];
#pragma unroll
            for (int half = 0; half < 2; half++) {
                const int nf = 2*ks + half;
#pragma unroll
                for (int rr = 0; rr < 2; rr++) {
                    __half2 hv = __floats2half2_rn(sb[nf][rr*2], sb[nf][rr*2+1]);
                    pf[half*2 + rr] = *(uint32_t*)&hv;
                }
            }
#pragma unroll
            for (int g = 0; g < 4; g++) {
                const uint32_t boff = SWZ128((uint32_t)((g*16 + brow)*128 + (ks*2 + bsel)*16));
                uint32_t v4[4];
                LDSM4(v4, so + 24576 + boff);
#pragma unroll
                for (int sub = 0; sub < 2; sub++)
                    MMA_F16(O[2*g + sub], pf, v4[2*sub], v4[2*sub+1]);
            }
        }
        __syncthreads();
    }

    const float il0 = 1.0f / l0, il1 = 1.0f / l1;
    float* o0 = out + ((size_t)b_*SSQ + q0    )*HD + h*DHD + (lane & 3)*2;
    float* o1 = out + ((size_t)b_*SSQ + q0 + 8)*HD + h*DHD + (lane & 3)*2;
#pragma unroll
    for (int nf = 0; nf < 8; nf++) {
        *(float2*)(o0 + nf*8) = make_float2(O[nf][0]*il0, O[nf][1]*il0);
        *(float2*)(o1 + nf*8) = make_float2(O[nf][2]*il1, O[nf][3]*il1);
    }
}

// ---------------------------------------------------------------------------
extern "C" void kernel_launch(void* const* d_in, const int* in_sizes, int n_in,
                              void* d_out, int out_size)
{
    const float* hs   = (const float*)d_in[0];
    const float* te   = (const float*)d_in[1];
    const float* se   = (const float*)d_in[2];
    const float* mask = (const float*)d_in[3];
    const float* Wq = (const float*)d_in[4];  const float* bq = (const float*)d_in[5];
    const float* Wk = (const float*)d_in[6];  const float* bk = (const float*)d_in[7];
    const float* Wv = (const float*)d_in[8];  const float* bv = (const float*)d_in[9];
    const float* Wt = (const float*)d_in[10]; const float* bt = (const float*)d_in[11];
    const float* Ws = (const float*)d_in[12]; const float* bs = (const float*)d_in[13];
    float* out = (float*)d_out;

    dim3 gx((BB*SSQ*HD)/4/256, 3);
    split_x_kernel<<<gx, 256>>>(hs, te, se);
    dim3 gw((HD*HD)/4/256, 5);
    split_w_kernel<<<gw, 256>>>(Wq, Wk, Wv, Wt, Ws);

    cudaFuncSetAttribute(proj_hmma_kernel, cudaFuncAttributeMaxDynamicSharedMemorySize, PROJ_SMEM);
    dim3 gp(HD/128, (BB*SSQ)/128, 5);   // (6, 32, 5)
    proj_hmma_kernel<<<gp, 256, PROJ_SMEM>>>(bq, bk, bv, bt, bs);

    cudaFuncSetAttribute(attn_hmma_kernel, cudaFuncAttributeMaxDynamicSharedMemorySize, ATTN_SMEM);
    dim3 ga(SSQ/64, BB*NHD);            // (16, 48)
    attn_hmma_kernel<<<ga, 128, ATTN_SMEM>>>(mask, out);
}

// round 15
// speedup vs baseline: 6.5388x; 1.0042x over previous
#include <cuda_runtime.h>
#include <cuda_bf16.h>
#include <cuda_fp16.h>
#include <math.h>
#include <stdint.h>

#define HD   768
#define NHD  12
#define DHD  64
#define BB   4
#define SSQ  1024
#define EPSF 1e-6f
#define LOG2E 1.4426950408889634f

#define SWZ128(x) ((x) ^ (((x) >> 3) & 0x70))

__device__ __forceinline__ uint32_t smem_u32(const void* p) {
    uint32_t a;
    asm("{ .reg .u64 t; cvta.to.shared.u64 t, %1; cvt.u32.u64 %0, t; }" : "=r"(a) : "l"(p));
    return a;
}
__device__ __forceinline__ float ex2f(float x) {
    float r; asm("ex2.approx.f32 %0, %1;" : "=f"(r) : "f"(x)); return r;
}

#define LDSM4(r, addr) \
    asm volatile("ldmatrix.sync.aligned.m8n8.x4.shared.b16 {%0,%1,%2,%3}, [%4];" \
        : "=r"((r)[0]), "=r"((r)[1]), "=r"((r)[2]), "=r"((r)[3]) : "r"(addr))

#define MMA_BF16(d, a, b0, b1) \
    asm volatile("mma.sync.aligned.m16n8k16.row.col.f32.bf16.bf16.f32 " \
        "{%0,%1,%2,%3}, {%4,%5,%6,%7}, {%8,%9}, {%0,%1,%2,%3};" \
        : "+f"((d)[0]), "+f"((d)[1]), "+f"((d)[2]), "+f"((d)[3]) \
        : "r"((a)[0]), "r"((a)[1]), "r"((a)[2]), "r"((a)[3]), "r"(b0), "r"(b1))

#define MMA_F16(d, a, b0, b1) \
    asm volatile("mma.sync.aligned.m16n8k16.row.col.f32.f16.f16.f32 " \
        "{%0,%1,%2,%3}, {%4,%5,%6,%7}, {%8,%9}, {%0,%1,%2,%3};" \
        : "+f"((d)[0]), "+f"((d)[1]), "+f"((d)[2]), "+f"((d)[3]) \
        : "r"((a)[0]), "r"((a)[1]), "r"((a)[2]), "r"((a)[3]), "r"(b0), "r"(b1))

__device__ __forceinline__ void cp16(uint32_t d, const void* s) {
    asm volatile("cp.async.cg.shared.global [%0], [%1], 16;" :: "r"(d), "l"(s) : "memory");
}
#define CP_COMMIT() asm volatile("cp.async.commit_group;" ::: "memory")
#define CP_WAIT(n)  asm volatile("cp.async.wait_group %0;" :: "n"(n) : "memory")

// ---------------------------------------------------------------------------
// Scratch (allocation-free rule: __device__ globals)
// ---------------------------------------------------------------------------
__device__ __half g_q16[BB*NHD*SSQ*DHD];   // q fp16 [bh][tok][dim]
__device__ __half g_k16[BB*NHD*SSQ*DHD];
__device__ __half g_t16[BB*NHD*SSQ*DHD];
__device__ __half g_s16[BB*NHD*SSQ*DHD];
__device__ __half g_vT16[BB*NHD*DHD*SSQ];  // V fp16 [bh][dim][tok]
__device__ float g_itn[BB*NHD*SSQ];
__device__ float g_isn[BB*NHD*SSQ];

// bf16 split-precision GEMM inputs
__device__ __nv_bfloat16 g_xh[3*BB*SSQ*HD];
__device__ __nv_bfloat16 g_xl[3*BB*SSQ*HD];
__device__ __nv_bfloat16 g_wh[5*HD*HD];
__device__ __nv_bfloat16 g_wl[5*HD*HD];

// ---------------------------------------------------------------------------
// fp32 -> bf16 hi/lo split kernels
// ---------------------------------------------------------------------------
__global__ __launch_bounds__(256) void split_x_kernel(
    const float* __restrict__ hs, const float* __restrict__ te, const float* __restrict__ se)
{
    const float* src = (blockIdx.y == 0) ? hs : (blockIdx.y == 1) ? te : se;
    const size_t off = (size_t)blockIdx.y * (size_t)(BB*SSQ*HD);
    size_t i = ((size_t)blockIdx.x * blockDim.x + threadIdx.x) * 4;
    if (i >= (size_t)(BB*SSQ*HD)) return;
    float4 x = *(const float4*)(src + i);
    __nv_bfloat16 h0 = __float2bfloat16(x.x), h1 = __float2bfloat16(x.y);
    __nv_bfloat16 h2 = __float2bfloat16(x.z), h3 = __float2bfloat16(x.w);
    __nv_bfloat162 hA; hA.x = h0; hA.y = h1;
    __nv_bfloat162 hB; hB.x = h2; hB.y = h3;
    __nv_bfloat162 lA; lA.x = __float2bfloat16(x.x - __bfloat162float(h0));
                       lA.y = __float2bfloat16(x.y - __bfloat162float(h1));
    __nv_bfloat162 lB; lB.x = __float2bfloat16(x.z - __bfloat162float(h2));
                       lB.y = __float2bfloat16(x.w - __bfloat162float(h3));
    *(__nv_bfloat162*)(g_xh + off + i)     = hA;
    *(__nv_bfloat162*)(g_xh + off + i + 2) = hB;
    *(__nv_bfloat162*)(g_xl + off + i)     = lA;
    *(__nv_bfloat162*)(g_xl + off + i + 2) = lB;
}

__global__ __launch_bounds__(256) void split_w_kernel(
    const float* __restrict__ Wq, const float* __restrict__ Wk, const float* __restrict__ Wv,
    const float* __restrict__ Wt, const float* __restrict__ Ws)
{
    const int z = blockIdx.y;
    const float* src = (z==0)?Wq:(z==1)?Wk:(z==2)?Wv:(z==3)?Wt:Ws;
    const size_t off = (size_t)z * (size_t)(HD*HD);
    size_t i = ((size_t)blockIdx.x * blockDim.x + threadIdx.x) * 4;
    if (i >= (size_t)(HD*HD)) return;
    float4 x = *(const float4*)(src + i);
    __nv_bfloat16 h0 = __float2bfloat16(x.x), h1 = __float2bfloat16(x.y);
    __nv_bfloat16 h2 = __float2bfloat16(x.z), h3 = __float2bfloat16(x.w);
    __nv_bfloat162 hA; hA.x = h0; hA.y = h1;
    __nv_bfloat162 hB; hB.x = h2; hB.y = h3;
    __nv_bfloat162 lA; lA.x = __float2bfloat16(x.x - __bfloat162float(h0));
                       lA.y = __float2bfloat16(x.y - __bfloat162float(h1));
    __nv_bfloat162 lB; lB.x = __float2bfloat16(x.z - __bfloat162float(h2));
                       lB.y = __float2bfloat16(x.w - __bfloat162float(h3));
    *(__nv_bfloat162*)(g_wh + off + i)     = hA;
    *(__nv_bfloat162*)(g_wh + off + i + 2) = hB;
    *(__nv_bfloat162*)(g_wl + off + i)     = lA;
    *(__nv_bfloat162*)(g_wl + off + i + 2) = lB;
}

// ---------------------------------------------------------------------------
// HMMA projection GEMM (split hh+hl+lh), cp.async 3-stage pipeline,
// single __syncthreads per K-chunk. Block 256 thr = 8 warps (4 x 2).
// Tile M=128 tok, N=128 out, K-chunk 64. grid = (6, 32, 5).  (unchanged)
// ---------------------------------------------------------------------------
#define PSTAGE     65536
#define PROJ_SMEM  (3*PSTAGE)

__global__ __launch_bounds__(256) void proj_hmma_kernel(
    const float* __restrict__ bq, const float* __restrict__ bk,
    const float* __restrict__ bv, const float* __restrict__ bt,
    const float* __restrict__ bs)
{
    extern __shared__ char dsm[];
    const uint32_t smb = smem_u32(dsm);

    const int tid  = threadIdx.x;
    const int lane = tid & 31;
    const int wid  = tid >> 5;
    const int wm   = wid & 3;
    const int wn   = wid >> 2;
    const int nt = blockIdx.x;
    const int mt = blockIdx.y;
    const int z  = blockIdx.z;

    const int xsel = (z <= 2) ? 0 : (z == 3) ? 1 : 2;
    const __nv_bfloat16* Xh = g_xh + (size_t)xsel * (BB*SSQ*HD);
    const __nv_bfloat16* Xl = g_xl + (size_t)xsel * (BB*SSQ*HD);
    const __nv_bfloat16* Wh = g_wh + (size_t)z * (HD*HD);
    const __nv_bfloat16* Wl = g_wl + (size_t)z * (HD*HD);
    const float* bias = (z==0)?bq:(z==1)?bk:(z==2)?bv:(z==3)?bt:bs;

    float D[2][8][4];
#pragma unroll
    for (int mf = 0; mf < 2; mf++)
#pragma unroll
        for (int nf = 0; nf < 8; nf++)
#pragma unroll
            for (int c = 0; c < 4; c++) D[mf][nf][c] = 0.f;

    const int a_row = wm*32 + (lane & 15);
    const int a_hi  = (lane >> 4);
    const int b_row = wn*64 + (lane & 7) + (lane >> 4)*8;
    const int b_hi  = (lane >> 3) & 1;

    auto issue = [&](int buf, int kb) {
        const uint32_t so = smb + buf*PSTAGE;
#pragma unroll
        for (int l = 0; l < 4; l++) {
            const int flat = tid + l*256;
            const int r   = flat >> 3;
            const int seg = flat & 7;
            const uint32_t swo = SWZ128((uint32_t)(r*128 + seg*16));
            const size_t ga = (size_t)(mt*128 + r)*HD + kb*64 + seg*8;
            const size_t gb = (size_t)(nt*128 + r)*HD + kb*64 + seg*8;
            cp16(so +     0 + swo, Xh + ga);
            cp16(so + 16384 + swo, Xl + ga);
            cp16(so + 32768 + swo, Wh + gb);
            cp16(so + 49152 + swo, Wl + gb);
        }
    };

    issue(0, 0); CP_COMMIT();
    issue(1, 1); CP_COMMIT();

    for (int kb = 0; kb < 12; kb++) {
        if (kb < 11) { CP_WAIT(1); } else { CP_WAIT(0); }
        __syncthreads();
        if (kb + 2 < 12) { issue((kb + 2) % 3, kb + 2); CP_COMMIT(); }
        const uint32_t so = smb + (kb % 3)*PSTAGE;

#pragma unroll
        for (int ks = 0; ks < 4; ks++) {
            uint32_t ah[2][4], al[2][4];
#pragma unroll
            for (int mf = 0; mf < 2; mf++) {
                const uint32_t byo = SWZ128((uint32_t)((a_row + mf*16)*128 + (ks*2 + a_hi)*16));
                LDSM4(ah[mf], so +     0 + byo);
                LDSM4(al[mf], so + 16384 + byo);
            }
#pragma unroll
            for (int g = 0; g < 4; g++) {
                uint32_t bh4[4], bl4[4];
                const uint32_t byo = SWZ128((uint32_t)((b_row + g*16)*128 + (ks*2 + b_hi)*16));
                LDSM4(bh4, so + 32768 + byo);
                LDSM4(bl4, so + 49152 + byo);
#pragma unroll
                for (int sub = 0; sub < 2; sub++) {
                    const int nf = 2*g + sub;
#pragma unroll
                    for (int mf = 0; mf < 2; mf++) {
                        MMA_BF16(D[mf][nf], ah[mf], bh4[2*sub], bh4[2*sub+1]);
                        MMA_BF16(D[mf][nf], ah[mf], bl4[2*sub], bl4[2*sub+1]);
                        MMA_BF16(D[mf][nf], al[mf], bh4[2*sub], bh4[2*sub+1]);
                    }
                }
            }
        }
    }

    // ---- epilogue ----
    const int b_ = (mt*128) >> 10;
    const int h  = nt*2 + wn;
    const size_t bh = (size_t)b_*NHD + h;

#pragma unroll
    for (int nf = 0; nf < 8; nf++) {
        const int col = nt*128 + wn*64 + nf*8 + (lane & 3)*2;
        const float b0 = bias[col], b1 = bias[col + 1];
#pragma unroll
        for (int mf = 0; mf < 2; mf++) {
            D[mf][nf][0] += b0; D[mf][nf][1] += b1;
            D[mf][nf][2] += b0; D[mf][nf][3] += b1;
        }
    }

    if (z <= 1) {
        __half* gq = (z == 0) ? g_q16 : g_k16;
#pragma unroll
        for (int mf = 0; mf < 2; mf++)
#pragma unroll
            for (int half = 0; half < 2; half++) {
                const int s_ = (mt*128 + wm*32 + mf*16 + half*8 + (lane >> 2)) & 1023;
                const size_t base = (bh*SSQ + s_)*DHD + (lane & 3)*2;
#pragma unroll
                for (int nf = 0; nf < 8; nf++) {
                    __half2 hv = __floats2half2_rn(D[mf][nf][half*2], D[mf][nf][half*2+1]);
                    *(uint32_t*)(gq + base + nf*8) = *(uint32_t*)&hv;
                }
            }
        return;
    }

    if (z >= 3) {
        __half* gt = (z == 3) ? g_t16 : g_s16;
        float* invn = (z == 3) ? g_itn : g_isn;
#pragma unroll
        for (int mf = 0; mf < 2; mf++)
#pragma unroll
            for (int half = 0; half < 2; half++) {
                const int s_ = (mt*128 + wm*32 + mf*16 + half*8 + (lane >> 2)) & 1023;
                const size_t base = (bh*SSQ + s_)*DHD + (lane & 3)*2;
                float ss = 0.f;
#pragma unroll
                for (int nf = 0; nf < 8; nf++) {
                    const float v0 = D[mf][nf][half*2], v1 = D[mf][nf][half*2+1];
                    ss = fmaf(v0, v0, fmaf(v1, v1, ss));
                    __half2 hv = __floats2half2_rn(v0, v1);
                    *(uint32_t*)(gt + base + nf*8) = *(uint32_t*)&hv;
                }
                ss += __shfl_xor_sync(0xffffffffu, ss, 1);
                ss += __shfl_xor_sync(0xffffffffu, ss, 2);
                if ((lane & 3) == 0)
                    invn[bh*SSQ + s_] = 1.0f / (sqrtf(ss) + EPSF);
            }
        return;
    }

    // z == 2: V -> transposed fp16 [bh][dim][tok] via smem stage
    float* S = (float*)dsm;
#pragma unroll
    for (int mf = 0; mf < 2; mf++) {
        __syncthreads();
#pragma unroll
        for (int half = 0; half < 2; half++) {
            const int rl = wm*16 + half*8 + (lane >> 2);
            const int c  = wn*64 + (lane & 3)*2;
#pragma unroll
            for (int nf = 0; nf < 8; nf++) {
                S[(c + nf*8    )*66 + rl] = D[mf][nf][half*2];
                S[(c + nf*8 + 1)*66 + rl] = D[mf][nf][half*2+1];
            }
        }
        __syncthreads();
#pragma unroll
        for (int l = 0; l < 8; l++) {
            const int e  = tid + l*256;
            const int d  = e >> 4;
            const int r4 = (e & 15) * 4;
            float4 v = make_float4(S[d*66 + r4], S[d*66 + r4 + 1],
                                   S[d*66 + r4 + 2], S[d*66 + r4 + 3]);
            const int tk = (mt*128 + mf*16 + (r4 >> 4)*32 + (r4 & 15)) & 1023;
            const int hh = nt*2 + (d >> 6);
            const int dl = d & 63;
            const size_t ob = (((size_t)b_*NHD + hh)*DHD + dl)*SSQ + tk;
            __half2 hA = __floats2half2_rn(v.x, v.y);
            __half2 hB = __floats2half2_rn(v.z, v.w);
            uint2 hu = make_uint2(*(uint32_t*)&hA, *(uint32_t*)&hB);
            *(uint2*)(g_vT16 + ob) = hu;
        }
    }
}

// ---------------------------------------------------------------------------
// HMMA flash attention: 128 threads / 4 warps / 64 queries, 2 blocks per SM.
// Sub-chunk pipelining: 64-key chunk split into two 32-key units;
// order = scores(u0), scores(u1), softmax(u0) [hidden under u1 MMA drain],
// PV(u0), softmax(u1) [hidden under PV(u0) drain], PV(u1).
// smem = 16384 + 2*33024 = 82432 B -> 2 blocks/SM.
// ---------------------------------------------------------------------------
#define AQT       16384                 // qt (8KB) + qs (8KB)
#define STAGE_SZ  33024                 // k16,t,s,v16 (4x8KB) + mask 256B
#define ATTN_SMEM (AQT + 2*STAGE_SZ)    // 82432

__global__ __launch_bounds__(128, 2) void attn_hmma_kernel(const float* __restrict__ mask,
                                                           float* __restrict__ out)
{
    extern __shared__ char sbuf[];
    const uint32_t smb = smem_u32(sbuf);
    const int tid = threadIdx.x;
    const int lane = tid & 31;
    const int w = tid >> 5;
    const int bh = blockIdx.y;
    const int b_ = bh / NHD;
    const int h  = bh - b_*NHD;
    const int qb = blockIdx.x * 64;

    const __half* q16p = g_q16 + (size_t)bh*SSQ*DHD;
    const __half* k16p = g_k16 + (size_t)bh*SSQ*DHD;
    const __half* qtp  = g_t16 + (size_t)bh*SSQ*DHD;
    const __half* qsp  = g_s16 + (size_t)bh*SSQ*DHD;
    const __half* vp   = g_vT16 + (size_t)bh*DHD*SSQ;
    const float* maskb = mask + (size_t)b_*SSQ;

    const int arow = w*16 + (lane & 15);
    const int asel = lane >> 4;
    const int brow = (lane & 7) + (lane >> 4)*8;
    const int bsel = (lane >> 3) & 1;

    // ---- prologue: qt/qs -> permanent smem; q16 staged then registered ----
#pragma unroll
    for (int l = 0; l < 4; l++) {
        const int flat = tid + l*128;
        const int r = flat >> 3, seg = flat & 7;
        const uint32_t swo = SWZ128((uint32_t)(r*128 + seg*16));
        const size_t src = (size_t)(qb + r)*DHD + seg*8;
        cp16(smb +    0 + swo, qtp + src);
        cp16(smb + 8192 + swo, qsp + src);
        cp16(smb + AQT  + swo, q16p + src);
    }
    CP_COMMIT(); CP_WAIT(0);
    __syncthreads();

    uint32_t qf[4][4];
#pragma unroll
    for (int ks = 0; ks < 4; ks++) {
        const uint32_t aoff = SWZ128((uint32_t)(arow*128 + (ks*2 + asel)*16));
        LDSM4(qf[ks], smb + AQT + aoff);
    }
    __syncthreads();

    // ---- K/V stage issue ----
    auto issue = [&](int buf, int kb0) {
        const uint32_t so = smb + AQT + buf*STAGE_SZ;
#pragma unroll
        for (int l = 0; l < 4; l++) {
            const int flat = tid + l*128;
            const int r = flat >> 3, seg = flat & 7;
            const uint32_t swo = SWZ128((uint32_t)(r*128 + seg*16));
            const size_t srcK = (size_t)(kb0 + r)*DHD + seg*8;
            cp16(so +     0 + swo, k16p + srcK);
            cp16(so +  8192 + swo, qtp + srcK);
            cp16(so + 16384 + swo, qsp + srcK);
            const size_t srcV = (size_t)r*SSQ + kb0 + seg*8;
            cp16(so + 24576 + swo, vp + srcV);
        }
        if (tid < 16) cp16(so + 32768 + tid*16, maskb + kb0 + tid*4);
    };

    issue(0, 0); CP_COMMIT();

    const int q0 = qb + w*16 + (lane >> 2);
    float rs[2];
    rs[0] = g_itn[(size_t)bh*SSQ + q0]     * g_isn[(size_t)bh*SSQ + q0]     * (0.125f * LOG2E);
    rs[1] = g_itn[(size_t)bh*SSQ + q0 + 8] * g_isn[(size_t)bh*SSQ + q0 + 8] * (0.125f * LOG2E);

    float O[8][4];
#pragma unroll
    for (int nf = 0; nf < 8; nf++)
#pragma unroll
        for (int c = 0; c < 4; c++) O[nf][c] = 0.f;
    float m0 = -1e30f, m1 = -1e30f, l0 = 0.f, l1 = 0.f;

    for (int c = 0; c < 16; c++) {
        const int buf = c & 1;
        const uint32_t so = smb + AQT + buf*STAGE_SZ;
        const char* sp = sbuf + AQT + buf*STAGE_SZ;

        if (c + 1 < 16) { issue(buf ^ 1, (c + 1)*64); CP_COMMIT(); CP_WAIT(1); }
        else            { CP_WAIT(0); }
        __syncthreads();

        // ---- raw scores for BOTH 32-key units (tensor-dense region) ----
        float sb[2][4][4], st4[2][4][4], ss4[2][4][4];
#pragma unroll
        for (int u = 0; u < 2; u++)
#pragma unroll
            for (int nf = 0; nf < 4; nf++)
#pragma unroll
                for (int cc = 0; cc < 4; cc++) {
                    sb[u][nf][cc] = 0.f; st4[u][nf][cc] = 0.f; ss4[u][nf][cc] = 0.f;
                }

#pragma unroll
        for (int u = 0; u < 2; u++) {
#pragma unroll
            for (int ks = 0; ks < 4; ks++) {
                uint32_t at_[4], as_[4];
                const uint32_t aoff = SWZ128((uint32_t)(arow*128 + (ks*2 + asel)*16));
                LDSM4(at_, smb +    0 + aoff);
                LDSM4(as_, smb + 8192 + aoff);
#pragma unroll
                for (int g2 = 0; g2 < 2; g2++) {
                    const int grow = u*32 + g2*16 + brow;
                    const uint32_t boff = SWZ128((uint32_t)(grow*128 + (ks*2 + bsel)*16));
                    uint32_t k4[4], bt4[4], bs4[4];
                    LDSM4(k4,  so +     0 + boff);
                    LDSM4(bt4, so +  8192 + boff);
                    LDSM4(bs4, so + 16384 + boff);
#pragma unroll
                    for (int sub = 0; sub < 2; sub++) {
                        const int nf = 2*g2 + sub;
                        MMA_F16(sb[u][nf],  qf[ks], k4[2*sub],  k4[2*sub+1]);
                        MMA_F16(st4[u][nf], at_,    bt4[2*sub], bt4[2*sub+1]);
                        MMA_F16(ss4[u][nf], as_,    bs4[2*sub], bs4[2*sub+1]);
                    }
                }
            }
        }

        // ---- per-unit: softmax (scalar, overlaps draining MMAs) then PV ----
        const float* mkp = (const float*)(sp + 32768);
#pragma unroll
        for (int u = 0; u < 2; u++) {
            float mloc0 = -1e30f, mloc1 = -1e30f;
#pragma unroll
            for (int nf = 0; nf < 4; nf++) {
                const float2 mk = *(const float2*)(mkp + u*32 + nf*8 + (lane & 3)*2);
                const float mk2x = mk.x * LOG2E, mk2y = mk.y * LOG2E;
                float s0 = fmaf(sb[u][nf][0]*st4[u][nf][0]*ss4[u][nf][0], rs[0], mk2x);
                float s1 = fmaf(sb[u][nf][1]*st4[u][nf][1]*ss4[u][nf][1], rs[0], mk2y);
                float s2 = fmaf(sb[u][nf][2]*st4[u][nf][2]*ss4[u][nf][2], rs[1], mk2x);
                float s3 = fmaf(sb[u][nf][3]*st4[u][nf][3]*ss4[u][nf][3], rs[1], mk2y);
                sb[u][nf][0] = s0; sb[u][nf][1] = s1; sb[u][nf][2] = s2; sb[u][nf][3] = s3;
                mloc0 = fmaxf(mloc0, fmaxf(s0, s1));
                mloc1 = fmaxf(mloc1, fmaxf(s2, s3));
            }
            mloc0 = fmaxf(mloc0, __shfl_xor_sync(0xffffffffu, mloc0, 1));
            mloc0 = fmaxf(mloc0, __shfl_xor_sync(0xffffffffu, mloc0, 2));
            mloc1 = fmaxf(mloc1, __shfl_xor_sync(0xffffffffu, mloc1, 1));
            mloc1 = fmaxf(mloc1, __shfl_xor_sync(0xffffffffu, mloc1, 2));
            const float mn0 = fmaxf(m0, mloc0), mn1 = fmaxf(m1, mloc1);
            const float cr0 = ex2f(m0 - mn0), cr1 = ex2f(m1 - mn1);
            const unsigned same = __all_sync(0xffffffffu, (mn0 == m0) & (mn1 == m1));
            m0 = mn0; m1 = mn1;

            float rsum0 = 0.f, rsum1 = 0.f;
#pragma unroll
            for (int nf = 0; nf < 4; nf++) {
                float p0 = ex2f(sb[u][nf][0] - mn0);
                float p1 = ex2f(sb[u][nf][1] - mn0);
                float p2 = ex2f(sb[u][nf][2] - mn1);
                float p3 = ex2f(sb[u][nf][3] - mn1);
                sb[u][nf][0] = p0; sb[u][nf][1] = p1; sb[u][nf][2] = p2; sb[u][nf][3] = p3;
                rsum0 += p0 + p1; rsum1 += p2 + p3;
            }
            if (!same) {
#pragma unroll
                for (int nf = 0; nf < 8; nf++) {
                    O[nf][0] *= cr0; O[nf][1] *= cr0; O[nf][2] *= cr1; O[nf][3] *= cr1;
                }
            }
            rsum0 += __shfl_xor_sync(0xffffffffu, rsum0, 1);
            rsum0 += __shfl_xor_sync(0xffffffffu, rsum0, 2);
            rsum1 += __shfl_xor_sync(0xffffffffu, rsum1, 1);
            rsum1 += __shfl_xor_sync(0xffffffffu, rsum1, 2);
            l0 = l0*cr0 + rsum0;
            l1 = l1*cr1 + rsum1;

            // ---- PV for this unit: 2 key-groups of 16 ----
#pragma unroll
            for (int j = 0; j < 2; j++) {
                uint32_t pf[4];
#pragma unroll
                for (int half = 0; half < 2; half++) {
                    const int nf = 2*j + half;
#pragma unroll
                    for (int rr = 0; rr < 2; rr++) {
                        __half2 hv = __floats2half2_rn(sb[u][nf][rr*2], sb[u][nf][rr*2+1]);
                        pf[half*2 + rr] = *(uint32_t*)&hv;
                    }
                }
                const int kg = u*2 + j;   // global 16-key group
#pragma unroll
                for (int g = 0; g < 4; g++) {
                    const uint32_t boff = SWZ128((uint32_t)((g*16 + brow)*128 + (kg*2 + bsel)*16));
                    uint32_t v4[4];
                    LDSM4(v4, so + 24576 + boff);
#pragma unroll
                    for (int sub = 0; sub < 2; sub++)
                        MMA_F16(O[2*g + sub], pf, v4[2*sub], v4[2*sub+1]);
                }
            }
        }
        __syncthreads();
    }

    const float il0 = 1.0f / l0, il1 = 1.0f / l1;
    float* o0 = out + ((size_t)b_*SSQ + q0    )*HD + h*DHD + (lane & 3)*2;
    float* o1 = out + ((size_t)b_*SSQ + q0 + 8)*HD + h*DHD + (lane & 3)*2;
#pragma unroll
    for (int nf = 0; nf < 8; nf++) {
        *(float2*)(o0 + nf*8) = make_float2(O[nf][0]*il0, O[nf][1]*il0);
        *(float2*)(o1 + nf*8) = make_float2(O[nf][2]*il1, O[nf][3]*il1);
    }
}

// ---------------------------------------------------------------------------
extern "C" void kernel_launch(void* const* d_in, const int* in_sizes, int n_in,
                              void* d_out, int out_size)
{
    const float* hs   = (const float*)d_in[0];
    const float* te   = (const float*)d_in[1];
    const float* se   = (const float*)d_in[2];
    const float* mask = (const float*)d_in[3];
    const float* Wq = (const float*)d_in[4];  const float* bq = (const float*)d_in[5];
    const float* Wk = (const float*)d_in[6];  const float* bk = (const float*)d_in[7];
    const float* Wv = (const float*)d_in[8];  const float* bv = (const float*)d_in[9];
    const float* Wt = (const float*)d_in[10]; const float* bt = (const float*)d_in[11];
    const float* Ws = (const float*)d_in[12]; const float* bs = (const float*)d_in[13];
    float* out = (float*)d_out;

    dim3 gx((BB*SSQ*HD)/4/256, 3);
    split_x_kernel<<<gx, 256>>>(hs, te, se);
    dim3 gw((HD*HD)/4/256, 5);
    split_w_kernel<<<gw, 256>>>(Wq, Wk, Wv, Wt, Ws);

    cudaFuncSetAttribute(proj_hmma_kernel, cudaFuncAttributeMaxDynamicSharedMemorySize, PROJ_SMEM);
    dim3 gp(HD/128, (BB*SSQ)/128, 5);   // (6, 32, 5)
    proj_hmma_kernel<<<gp, 256, PROJ_SMEM>>>(bq, bk, bv, bt, bs);

    cudaFuncSetAttribute(attn_hmma_kernel, cudaFuncAttributeMaxDynamicSharedMemorySize, ATTN_SMEM);
    dim3 ga(SSQ/64, BB*NHD);            // (16, 48)
    attn_hmma_kernel<<<ga, 128, ATTN_SMEM>>>(mask, out);
}